// round 3
// baseline (speedup 1.0000x reference)
#include <cuda_runtime.h>
#include <math.h>

#define B_   4
#define C_   256
#define CQK_ 128
#define N_   4096

// ---------------- scratch (device globals; no allocations allowed) ----------
__device__ float g_Q[B_ * CQK_ * N_];             //  8 MB  [b][d][n]
__device__ float g_K[B_ * CQK_ * N_];             //  8 MB  [b][d][n]
__device__ float g_V[B_ * C_ * N_];               // 16 MB  [b][c][n]
__device__ float g_S[(size_t)B_ * N_ * N_];       // 256 MB [b][i][j]
__device__ float g_L[B_ * N_];                    // l_i = m_i + log(sum_j exp(s_ij - m_i))

// ---------------- kernel 1: QKV projections (1x1 conv == GEMM) --------------
// out[b][o][n] = sum_c W[o][c] * x[b][c][n] + bias[o]
// grid: (N/64, 8, B). by 0..1 -> Q rows, 2..3 -> K rows, 4..7 -> V rows.
__global__ __launch_bounds__(256) void proj_kernel(
    const float* __restrict__ x,
    const float* __restrict__ wq, const float* __restrict__ bq,
    const float* __restrict__ wk, const float* __restrict__ bk,
    const float* __restrict__ wv, const float* __restrict__ bv)
{
    __shared__ float As[16][68];   // [kk][row]   (weight, transposed on store)
    __shared__ float Bs[16][68];   // [kk][n]     (x)

    const int by = blockIdx.y;
    const int b  = blockIdx.z;
    const float* W; const float* bias; float* out; int row0;
    if (by < 2)      { W = wq; bias = bq; out = g_Q + (size_t)b * CQK_ * N_; row0 = by * 64; }
    else if (by < 4) { W = wk; bias = bk; out = g_K + (size_t)b * CQK_ * N_; row0 = (by - 2) * 64; }
    else             { W = wv; bias = bv; out = g_V + (size_t)b * C_   * N_; row0 = (by - 4) * 64; }

    const int tid = threadIdx.y * 16 + threadIdx.x;
    const int n0  = blockIdx.x * 64;
    const float* xb = x + (size_t)b * C_ * N_;

    float acc[4][4] = {};

    for (int kt = 0; kt < C_; kt += 16) {
        // weight tile: 64 rows x 16 k, transpose into As[kk][row]
        {
            int r  = tid >> 2;
            int k4 = (tid & 3) * 4;
            float4 w4 = *reinterpret_cast<const float4*>(&W[(size_t)(row0 + r) * C_ + kt + k4]);
            As[k4 + 0][r] = w4.x; As[k4 + 1][r] = w4.y;
            As[k4 + 2][r] = w4.z; As[k4 + 3][r] = w4.w;
        }
        // x tile: 16 k x 64 n, coalesced
        {
            int kk = tid >> 4;
            int j4 = (tid & 15) * 4;
            float4 x4 = *reinterpret_cast<const float4*>(&xb[(size_t)(kt + kk) * N_ + n0 + j4]);
            *reinterpret_cast<float4*>(&Bs[kk][j4]) = x4;
        }
        __syncthreads();
        #pragma unroll
        for (int kk = 0; kk < 16; kk++) {
            float4 a4 = *reinterpret_cast<const float4*>(&As[kk][threadIdx.y * 4]);
            float4 b4 = *reinterpret_cast<const float4*>(&Bs[kk][threadIdx.x * 4]);
            float a[4] = {a4.x, a4.y, a4.z, a4.w};
            float c[4] = {b4.x, b4.y, b4.z, b4.w};
            #pragma unroll
            for (int u = 0; u < 4; u++)
                #pragma unroll
                for (int v = 0; v < 4; v++)
                    acc[u][v] += a[u] * c[v];
        }
        __syncthreads();
    }

    #pragma unroll
    for (int u = 0; u < 4; u++) {
        int row = row0 + threadIdx.y * 4 + u;
        float bi = bias[row];
        #pragma unroll
        for (int v = 0; v < 4; v++)
            out[(size_t)row * N_ + n0 + threadIdx.x * 4 + v] = acc[u][v] + bi;
    }
}

// ---------------- kernel 2: scores S = Q^T K  (per batch 4096x4096, K=128) --
__global__ __launch_bounds__(256) void scores_kernel()
{
    __shared__ float As[16][68];   // [kk][i]
    __shared__ float Bs[16][68];   // [kk][j]

    const int j0 = blockIdx.x * 64;
    const int i0 = blockIdx.y * 64;
    const int b  = blockIdx.z;
    const float* Qb = g_Q + (size_t)b * CQK_ * N_;
    const float* Kb = g_K + (size_t)b * CQK_ * N_;
    float* Sb = g_S + (size_t)b * N_ * N_;

    const int tid = threadIdx.y * 16 + threadIdx.x;
    float acc[4][4] = {};

    for (int kt = 0; kt < CQK_; kt += 16) {
        int kk = tid >> 4;
        int j4 = (tid & 15) * 4;
        *reinterpret_cast<float4*>(&As[kk][j4]) =
            *reinterpret_cast<const float4*>(&Qb[(size_t)(kt + kk) * N_ + i0 + j4]);
        *reinterpret_cast<float4*>(&Bs[kk][j4]) =
            *reinterpret_cast<const float4*>(&Kb[(size_t)(kt + kk) * N_ + j0 + j4]);
        __syncthreads();
        #pragma unroll
        for (int k2 = 0; k2 < 16; k2++) {
            float4 a4 = *reinterpret_cast<const float4*>(&As[k2][threadIdx.y * 4]);
            float4 b4 = *reinterpret_cast<const float4*>(&Bs[k2][threadIdx.x * 4]);
            float a[4] = {a4.x, a4.y, a4.z, a4.w};
            float c[4] = {b4.x, b4.y, b4.z, b4.w};
            #pragma unroll
            for (int u = 0; u < 4; u++)
                #pragma unroll
                for (int v = 0; v < 4; v++)
                    acc[u][v] += a[u] * c[v];
        }
        __syncthreads();
    }

    #pragma unroll
    for (int u = 0; u < 4; u++) {
        size_t base = (size_t)(i0 + threadIdx.y * 4 + u) * N_ + j0 + threadIdx.x * 4;
        #pragma unroll
        for (int v = 0; v < 4; v++)
            Sb[base + v] = acc[u][v];
    }
}

// ---------------- kernel 3: per-row logsumexp -------------------------------
// l[row] = max_j S[row][j] + log(sum_j exp(S[row][j] - max))
__global__ __launch_bounds__(128) void rowstats_kernel()
{
    const int row = blockIdx.x;                  // 0 .. B*N-1
    const float* Sr = g_S + (size_t)row * N_;
    const int t = threadIdx.x;

    float v[32];
    float m = -3.0e38f;
    #pragma unroll
    for (int i = 0; i < 32; i++) {
        v[i] = Sr[t + i * 128];
        m = fmaxf(m, v[i]);
    }
    #pragma unroll
    for (int o = 16; o > 0; o >>= 1)
        m = fmaxf(m, __shfl_xor_sync(0xffffffffu, m, o));

    __shared__ float redm[4];
    if ((t & 31) == 0) redm[t >> 5] = m;
    __syncthreads();
    float M = fmaxf(fmaxf(redm[0], redm[1]), fmaxf(redm[2], redm[3]));

    float s = 0.f;
    #pragma unroll
    for (int i = 0; i < 32; i++)
        s += __expf(v[i] - M);
    #pragma unroll
    for (int o = 16; o > 0; o >>= 1)
        s += __shfl_xor_sync(0xffffffffu, s, o);

    __shared__ float reds[4];
    if ((t & 31) == 0) reds[t >> 5] = s;
    __syncthreads();
    if (t == 0)
        g_L[row] = M + __logf(reds[0] + reds[1] + reds[2] + reds[3]);
}

// ---------------- kernel 4: AV GEMM + epilogue ------------------------------
// out[b][c][j] = gamma * ( sum_i V[b][c][i] * exp(S[b][i][j] - l[b][i]) ) + x[b][c][j]
__global__ __launch_bounds__(256) void av_kernel(
    const float* __restrict__ x, const float* __restrict__ gamma,
    float* __restrict__ out)
{
    __shared__ float As[16][68];   // [kk(i)][c]
    __shared__ float Bs[16][68];   // [kk(i)][j]   (P tile, exp applied)

    const int j0 = blockIdx.x * 64;
    const int c0 = blockIdx.y * 64;
    const int b  = blockIdx.z;
    const float* Vb = g_V + (size_t)b * C_ * N_;
    const float* Sb = g_S + (size_t)b * N_ * N_;
    const float* Lb = g_L + b * N_;

    const int tid = threadIdx.y * 16 + threadIdx.x;
    float acc[4][4] = {};

    for (int kt = 0; kt < N_; kt += 16) {
        // V tile: 64 c-rows x 16 i, transpose into As[kk][c]
        {
            int cc = tid >> 2;
            int k4 = (tid & 3) * 4;
            float4 v4 = *reinterpret_cast<const float4*>(&Vb[(size_t)(c0 + cc) * N_ + kt + k4]);
            As[k4 + 0][cc] = v4.x; As[k4 + 1][cc] = v4.y;
            As[k4 + 2][cc] = v4.z; As[k4 + 3][cc] = v4.w;
        }
        // P tile: exp(S - l), coalesced in j
        {
            int kk = tid >> 4;
            int j4 = (tid & 15) * 4;
            float l = Lb[kt + kk];
            float4 s4 = *reinterpret_cast<const float4*>(&Sb[(size_t)(kt + kk) * N_ + j0 + j4]);
            float4 p4;
            p4.x = __expf(s4.x - l);
            p4.y = __expf(s4.y - l);
            p4.z = __expf(s4.z - l);
            p4.w = __expf(s4.w - l);
            *reinterpret_cast<float4*>(&Bs[kk][j4]) = p4;
        }
        __syncthreads();
        #pragma unroll
        for (int kk = 0; kk < 16; kk++) {
            float4 a4 = *reinterpret_cast<const float4*>(&As[kk][threadIdx.y * 4]);
            float4 b4 = *reinterpret_cast<const float4*>(&Bs[kk][threadIdx.x * 4]);
            float a[4] = {a4.x, a4.y, a4.z, a4.w};
            float c[4] = {b4.x, b4.y, b4.z, b4.w};
            #pragma unroll
            for (int u = 0; u < 4; u++)
                #pragma unroll
                for (int v = 0; v < 4; v++)
                    acc[u][v] += a[u] * c[v];
        }
        __syncthreads();
    }

    const float g = gamma[0];
    #pragma unroll
    for (int u = 0; u < 4; u++) {
        int c = c0 + threadIdx.y * 4 + u;
        size_t base = (size_t)b * C_ * N_ + (size_t)c * N_ + j0 + threadIdx.x * 4;
        #pragma unroll
        for (int v = 0; v < 4; v++)
            out[base + v] = g * acc[u][v] + x[base + v];
    }
}

// ---------------- launch ----------------------------------------------------
extern "C" void kernel_launch(void* const* d_in, const int* in_sizes, int n_in,
                              void* d_out, int out_size)
{
    const float* x     = (const float*)d_in[0];
    const float* wq    = (const float*)d_in[1];
    const float* bq    = (const float*)d_in[2];
    const float* wk    = (const float*)d_in[3];
    const float* bk    = (const float*)d_in[4];
    const float* wv    = (const float*)d_in[5];
    const float* bv    = (const float*)d_in[6];
    const float* gamma = (const float*)d_in[7];
    float* out = (float*)d_out;

    dim3 blk(16, 16);
    proj_kernel  <<<dim3(N_ / 64, 8, B_),  blk>>>(x, wq, bq, wk, bk, wv, bv);
    scores_kernel<<<dim3(N_ / 64, N_ / 64, B_), blk>>>();
    rowstats_kernel<<<dim3(B_ * N_), 128>>>();
    av_kernel    <<<dim3(N_ / 64, C_ / 64, B_), blk>>>(x, gamma, out);
}

// round 6
// speedup vs baseline: 1.1216x; 1.1216x over previous
#include <cuda_runtime.h>
#include <cuda_bf16.h>
#include <math.h>
#include <stdint.h>

#define B_   4
#define C_   256
#define CQK_ 128
#define N_   4096

// ---------------- scratch (device globals; no allocations allowed) ----------
__device__ float g_Q[B_ * CQK_ * N_];             //  8 MB  [b][d][n]
__device__ float g_K[B_ * CQK_ * N_];             //  8 MB  [b][d][n]
__device__ float g_V[B_ * C_ * N_];               // 16 MB  [b][c][n]
__device__ float g_S[(size_t)B_ * N_ * N_];       // 256 MB [b][i][j]
__device__ float g_L[B_ * N_];                    // logsumexp per (b,i)

// bf16 split operands
__device__ __nv_bfloat16 g_qhi[B_ * N_ * CQK_];   // [b][n][d] (transposed)
__device__ __nv_bfloat16 g_qlo[B_ * N_ * CQK_];
__device__ __nv_bfloat16 g_khi[B_ * N_ * CQK_];
__device__ __nv_bfloat16 g_klo[B_ * N_ * CQK_];
__device__ __nv_bfloat16 g_vhi[B_ * C_ * N_];     // [b][c][n]
__device__ __nv_bfloat16 g_vlo[B_ * C_ * N_];
__device__ __nv_bfloat16 g_phi[(size_t)B_ * N_ * N_];  // 128 MB [b][j][i] (P^T)
__device__ __nv_bfloat16 g_plo[(size_t)B_ * N_ * N_];  // 128 MB

// ---------------- mma.sync helper (baseline PTX, no 'a' features) -----------
__device__ __forceinline__ void mma16816(float* c, const uint32_t* a, const uint32_t* b) {
    asm volatile(
        "mma.sync.aligned.m16n8k16.row.col.f32.bf16.bf16.f32 "
        "{%0,%1,%2,%3}, {%4,%5,%6,%7}, {%8,%9}, {%0,%1,%2,%3};"
        : "+f"(c[0]), "+f"(c[1]), "+f"(c[2]), "+f"(c[3])
        : "r"(a[0]), "r"(a[1]), "r"(a[2]), "r"(a[3]), "r"(b[0]), "r"(b[1]));
}

// SMEM tile: 128 rows x 64 bf16 cols, row stride 72 (conflict-free frag loads)
#define SROW 72

// stage 128x64 bf16 tile (global row-major, stride rs) into smem [r][SROW]
__device__ __forceinline__ void stage_tile(__nv_bfloat16* s, const __nv_bfloat16* g,
                                           int rs, int tid) {
    int r0 = tid >> 3;           // 0..31
    int c8 = (tid & 7) * 8;      // 0..56
    #pragma unroll
    for (int p = 0; p < 4; p++) {
        int r = p * 32 + r0;
        uint4 v = *reinterpret_cast<const uint4*>(g + (size_t)r * rs + c8);
        *reinterpret_cast<uint4*>(s + r * SROW + c8) = v;
    }
}

// ---------------- kernel 1: QKV projections (SIMT) --------------------------
__global__ __launch_bounds__(256) void proj_kernel(
    const float* __restrict__ x,
    const float* __restrict__ wq, const float* __restrict__ bq,
    const float* __restrict__ wk, const float* __restrict__ bk,
    const float* __restrict__ wv, const float* __restrict__ bv)
{
    __shared__ float As[16][68];
    __shared__ float Bs[16][68];

    const int by = blockIdx.y;
    const int b  = blockIdx.z;
    const float* W; const float* bias; float* out; int row0;
    if (by < 2)      { W = wq; bias = bq; out = g_Q + (size_t)b * CQK_ * N_; row0 = by * 64; }
    else if (by < 4) { W = wk; bias = bk; out = g_K + (size_t)b * CQK_ * N_; row0 = (by - 2) * 64; }
    else             { W = wv; bias = bv; out = g_V + (size_t)b * C_   * N_; row0 = (by - 4) * 64; }

    const int tid = threadIdx.y * 16 + threadIdx.x;
    const int n0  = blockIdx.x * 64;
    const float* xb = x + (size_t)b * C_ * N_;

    float acc[4][4] = {};

    for (int kt = 0; kt < C_; kt += 16) {
        {
            int r  = tid >> 2;
            int k4 = (tid & 3) * 4;
            float4 w4 = *reinterpret_cast<const float4*>(&W[(size_t)(row0 + r) * C_ + kt + k4]);
            As[k4 + 0][r] = w4.x; As[k4 + 1][r] = w4.y;
            As[k4 + 2][r] = w4.z; As[k4 + 3][r] = w4.w;
        }
        {
            int kk = tid >> 4;
            int j4 = (tid & 15) * 4;
            float4 x4 = *reinterpret_cast<const float4*>(&xb[(size_t)(kt + kk) * N_ + n0 + j4]);
            *reinterpret_cast<float4*>(&Bs[kk][j4]) = x4;
        }
        __syncthreads();
        #pragma unroll
        for (int kk = 0; kk < 16; kk++) {
            float4 a4 = *reinterpret_cast<const float4*>(&As[kk][threadIdx.y * 4]);
            float4 b4 = *reinterpret_cast<const float4*>(&Bs[kk][threadIdx.x * 4]);
            float a[4] = {a4.x, a4.y, a4.z, a4.w};
            float c[4] = {b4.x, b4.y, b4.z, b4.w};
            #pragma unroll
            for (int u = 0; u < 4; u++)
                #pragma unroll
                for (int v = 0; v < 4; v++)
                    acc[u][v] += a[u] * c[v];
        }
        __syncthreads();
    }

    #pragma unroll
    for (int u = 0; u < 4; u++) {
        int row = row0 + threadIdx.y * 4 + u;
        float bi = bias[row];
        #pragma unroll
        for (int v = 0; v < 4; v++)
            out[(size_t)row * N_ + n0 + threadIdx.x * 4 + v] = acc[u][v] + bi;
    }
}

// ---------------- kernel 2a: Q/K transpose + bf16 hi/lo split ---------------
__global__ __launch_bounds__(256) void qk_convert()
{
    __shared__ float t[32][33];
    const int z = blockIdx.z;            // 0..3 Q, 4..7 K
    const int b = z & 3;
    const bool isK = z >= 4;
    const float* src = (isK ? g_K : g_Q) + (size_t)b * CQK_ * N_;
    __nv_bfloat16* dhi = (isK ? g_khi : g_qhi) + (size_t)b * N_ * CQK_;
    __nv_bfloat16* dlo = (isK ? g_klo : g_qlo) + (size_t)b * N_ * CQK_;

    const int n0 = blockIdx.x * 32;
    const int d0 = blockIdx.y * 32;
    const int tx = threadIdx.x, ty = threadIdx.y;

    #pragma unroll
    for (int k = 0; k < 4; k++) {
        int dd = ty + k * 8;
        t[dd][tx] = src[(size_t)(d0 + dd) * N_ + n0 + tx];
    }
    __syncthreads();
    #pragma unroll
    for (int k = 0; k < 4; k++) {
        int nn = ty + k * 8;
        float f = t[tx][nn];
        __nv_bfloat16 hi = __float2bfloat16(f);
        float r = f - __bfloat162float(hi);
        size_t o = (size_t)(n0 + nn) * CQK_ + d0 + tx;
        dhi[o] = hi;
        dlo[o] = __float2bfloat16(r);
    }
}

// ---------------- kernel 2b: V bf16 hi/lo split ------------------------------
__global__ __launch_bounds__(256) void v_convert()
{
    size_t i = ((size_t)blockIdx.x * 256 + threadIdx.x) * 4;
    float4 f = *reinterpret_cast<const float4*>(&g_V[i]);
    __nv_bfloat16 h0 = __float2bfloat16(f.x), h1 = __float2bfloat16(f.y);
    __nv_bfloat16 h2 = __float2bfloat16(f.z), h3 = __float2bfloat16(f.w);
    __nv_bfloat162 hA, hB, lA, lB;
    hA.x = h0; hA.y = h1; hB.x = h2; hB.y = h3;
    lA.x = __float2bfloat16(f.x - __bfloat162float(h0));
    lA.y = __float2bfloat16(f.y - __bfloat162float(h1));
    lB.x = __float2bfloat16(f.z - __bfloat162float(h2));
    lB.y = __float2bfloat16(f.w - __bfloat162float(h3));
    *reinterpret_cast<__nv_bfloat162*>(&g_vhi[i])     = hA;
    *reinterpret_cast<__nv_bfloat162*>(&g_vhi[i + 2]) = hB;
    *reinterpret_cast<__nv_bfloat162*>(&g_vlo[i])     = lA;
    *reinterpret_cast<__nv_bfloat162*>(&g_vlo[i + 2]) = lB;
}

// ---------------- kernel 3: scores S = Q K^T (HMMA, 3-term split) -----------
// CTA tile 128(i) x 128(j); 8 warps (2 in M x 4 in N), warp tile 64x32.
__global__ __launch_bounds__(256, 2) void scores_mma()
{
    __shared__ __nv_bfloat16 As[128 * SROW];
    __shared__ __nv_bfloat16 Bs[128 * SROW];

    const int tid = threadIdx.x;
    const int lane = tid & 31, wid = tid >> 5;
    const int wm = wid & 1, wn = wid >> 1;
    const int m_base = wm * 64, n_base = wn * 32;
    const int g = lane >> 2, q2 = (lane & 3) * 2;

    const int j0 = blockIdx.x * 128, i0 = blockIdx.y * 128, b = blockIdx.z;

    const __nv_bfloat16* qhi_b = g_qhi + ((size_t)b * N_ + i0) * CQK_;
    const __nv_bfloat16* qlo_b = g_qlo + ((size_t)b * N_ + i0) * CQK_;
    const __nv_bfloat16* khi_b = g_khi + ((size_t)b * N_ + j0) * CQK_;
    const __nv_bfloat16* klo_b = g_klo + ((size_t)b * N_ + j0) * CQK_;
    const __nv_bfloat16* aSrc[3] = {qhi_b, qhi_b, qlo_b};
    const __nv_bfloat16* bSrc[3] = {khi_b, klo_b, khi_b};

    float acc[16][4] = {};

    for (int ch = 0; ch < 6; ch++) {
        const int ph = ch >> 1, koff = (ch & 1) * 64;
        stage_tile(As, aSrc[ph] + koff, CQK_, tid);
        stage_tile(Bs, bSrc[ph] + koff, CQK_, tid);
        __syncthreads();

        #pragma unroll
        for (int ks = 0; ks < 4; ks++) {
            const int k0 = ks * 16;
            uint32_t a[4][4];
            #pragma unroll
            for (int mi = 0; mi < 4; mi++) {
                const int r = m_base + mi * 16 + g;
                a[mi][0] = *reinterpret_cast<const uint32_t*>(&As[r * SROW + k0 + q2]);
                a[mi][1] = *reinterpret_cast<const uint32_t*>(&As[(r + 8) * SROW + k0 + q2]);
                a[mi][2] = *reinterpret_cast<const uint32_t*>(&As[r * SROW + k0 + 8 + q2]);
                a[mi][3] = *reinterpret_cast<const uint32_t*>(&As[(r + 8) * SROW + k0 + 8 + q2]);
            }
            uint32_t bf[4][2];
            #pragma unroll
            for (int ni = 0; ni < 4; ni++) {
                const int n = n_base + ni * 8 + g;
                bf[ni][0] = *reinterpret_cast<const uint32_t*>(&Bs[n * SROW + k0 + q2]);
                bf[ni][1] = *reinterpret_cast<const uint32_t*>(&Bs[n * SROW + k0 + 8 + q2]);
            }
            #pragma unroll
            for (int mi = 0; mi < 4; mi++)
                #pragma unroll
                for (int ni = 0; ni < 4; ni++)
                    mma16816(acc[mi * 4 + ni], a[mi], bf[ni]);
        }
        __syncthreads();
    }

    float* Sb = g_S + (size_t)b * N_ * N_;
    #pragma unroll
    for (int mi = 0; mi < 4; mi++) {
        #pragma unroll
        for (int ni = 0; ni < 4; ni++) {
            const float* c = acc[mi * 4 + ni];
            const int r = i0 + m_base + mi * 16 + g;
            const int col = j0 + n_base + ni * 8 + q2;
            *reinterpret_cast<float2*>(&Sb[(size_t)r * N_ + col])       = make_float2(c[0], c[1]);
            *reinterpret_cast<float2*>(&Sb[(size_t)(r + 8) * N_ + col]) = make_float2(c[2], c[3]);
        }
    }
}

// ---------------- kernel 4: per-row logsumexp -------------------------------
__global__ __launch_bounds__(128) void rowstats_kernel()
{
    const int row = blockIdx.x;
    const float* Sr = g_S + (size_t)row * N_;
    const int t = threadIdx.x;

    float v[32];
    float m = -3.0e38f;
    #pragma unroll
    for (int i = 0; i < 32; i++) {
        v[i] = Sr[t + i * 128];
        m = fmaxf(m, v[i]);
    }
    #pragma unroll
    for (int o = 16; o > 0; o >>= 1)
        m = fmaxf(m, __shfl_xor_sync(0xffffffffu, m, o));

    __shared__ float redm[4];
    if ((t & 31) == 0) redm[t >> 5] = m;
    __syncthreads();
    float M = fmaxf(fmaxf(redm[0], redm[1]), fmaxf(redm[2], redm[3]));

    float s = 0.f;
    #pragma unroll
    for (int i = 0; i < 32; i++)
        s += __expf(v[i] - M);
    #pragma unroll
    for (int o = 16; o > 0; o >>= 1)
        s += __shfl_xor_sync(0xffffffffu, s, o);

    __shared__ float reds[4];
    if ((t & 31) == 0) reds[t >> 5] = s;
    __syncthreads();
    if (t == 0)
        g_L[row] = M + __logf(reds[0] + reds[1] + reds[2] + reds[3]);
}

// ---------------- kernel 5: P = exp(S - l), transposed bf16 hi/lo -----------
__global__ __launch_bounds__(256) void pexp_kernel()
{
    __shared__ float t[64][65];
    const int j0 = blockIdx.x * 64, i0 = blockIdx.y * 64, b = blockIdx.z;
    const float* Sb = g_S + (size_t)b * N_ * N_;
    const float* Lb = g_L + (size_t)b * N_;
    const int tid = threadIdx.x;

    #pragma unroll
    for (int r = 0; r < 16; r++) {
        int idx = r * 256 + tid;
        int ii = idx >> 6, jj = idx & 63;
        float l = Lb[i0 + ii];
        t[ii][jj] = __expf(Sb[(size_t)(i0 + ii) * N_ + j0 + jj] - l);
    }
    __syncthreads();

    const int j = tid >> 2, ic = tid & 3;
    __align__(16) __nv_bfloat16 hi[16];
    __align__(16) __nv_bfloat16 lo[16];
    #pragma unroll
    for (int q = 0; q < 16; q++) {
        float p = t[ic * 16 + q][j];
        __nv_bfloat16 h = __float2bfloat16(p);
        hi[q] = h;
        lo[q] = __float2bfloat16(p - __bfloat162float(h));
    }
    size_t obase = ((size_t)b * N_ + j0 + j) * N_ + i0 + ic * 16;
    *reinterpret_cast<uint4*>(g_phi + obase)     = *reinterpret_cast<uint4*>(hi);
    *reinterpret_cast<uint4*>(g_phi + obase + 8) = *reinterpret_cast<uint4*>(hi + 8);
    *reinterpret_cast<uint4*>(g_plo + obase)     = *reinterpret_cast<uint4*>(lo);
    *reinterpret_cast<uint4*>(g_plo + obase + 8) = *reinterpret_cast<uint4*>(lo + 8);
}

// ---------------- kernel 6: AV GEMM (HMMA, 3-term split) + epilogue ----------
// out[c][j] = gamma * sum_i V[c][i] * P[i][j] + x[c][j]
// CTA tile 128(c) x 128(j); K = i = 4096, 3 phases x 64 chunks of 64.
__global__ __launch_bounds__(256, 2) void av_mma(
    const float* __restrict__ x, const float* __restrict__ gamma,
    float* __restrict__ out)
{
    __shared__ __nv_bfloat16 As[128 * SROW];
    __shared__ __nv_bfloat16 Bs[128 * SROW];

    const int tid = threadIdx.x;
    const int lane = tid & 31, wid = tid >> 5;
    const int wm = wid & 1, wn = wid >> 1;
    const int m_base = wm * 64, n_base = wn * 32;
    const int g = lane >> 2, q2 = (lane & 3) * 2;

    const int j0 = blockIdx.x * 128, c0 = blockIdx.y * 128, b = blockIdx.z;

    const __nv_bfloat16* vhi_b = g_vhi + ((size_t)b * C_ + c0) * N_;
    const __nv_bfloat16* vlo_b = g_vlo + ((size_t)b * C_ + c0) * N_;
    const __nv_bfloat16* phi_b = g_phi + ((size_t)b * N_ + j0) * N_;
    const __nv_bfloat16* plo_b = g_plo + ((size_t)b * N_ + j0) * N_;
    const __nv_bfloat16* aSrc[3] = {vhi_b, vhi_b, vlo_b};
    const __nv_bfloat16* bSrc[3] = {phi_b, plo_b, phi_b};

    float acc[16][4] = {};

    for (int ch = 0; ch < 192; ch++) {
        const int ph = ch >> 6, koff = (ch & 63) * 64;
        stage_tile(As, aSrc[ph] + koff, N_, tid);
        stage_tile(Bs, bSrc[ph] + koff, N_, tid);
        __syncthreads();

        #pragma unroll
        for (int ks = 0; ks < 4; ks++) {
            const int k0 = ks * 16;
            uint32_t a[4][4];
            #pragma unroll
            for (int mi = 0; mi < 4; mi++) {
                const int r = m_base + mi * 16 + g;
                a[mi][0] = *reinterpret_cast<const uint32_t*>(&As[r * SROW + k0 + q2]);
                a[mi][1] = *reinterpret_cast<const uint32_t*>(&As[(r + 8) * SROW + k0 + q2]);
                a[mi][2] = *reinterpret_cast<const uint32_t*>(&As[r * SROW + k0 + 8 + q2]);
                a[mi][3] = *reinterpret_cast<const uint32_t*>(&As[(r + 8) * SROW + k0 + 8 + q2]);
            }
            uint32_t bf[4][2];
            #pragma unroll
            for (int ni = 0; ni < 4; ni++) {
                const int n = n_base + ni * 8 + g;
                bf[ni][0] = *reinterpret_cast<const uint32_t*>(&Bs[n * SROW + k0 + q2]);
                bf[ni][1] = *reinterpret_cast<const uint32_t*>(&Bs[n * SROW + k0 + 8 + q2]);
            }
            #pragma unroll
            for (int mi = 0; mi < 4; mi++)
                #pragma unroll
                for (int ni = 0; ni < 4; ni++)
                    mma16816(acc[mi * 4 + ni], a[mi], bf[ni]);
        }
        __syncthreads();
    }

    const float gm = gamma[0];
    #pragma unroll
    for (int mi = 0; mi < 4; mi++) {
        #pragma unroll
        for (int ni = 0; ni < 4; ni++) {
            const float* c = acc[mi * 4 + ni];
            const int cc = c0 + m_base + mi * 16 + g;
            const int col = j0 + n_base + ni * 8 + q2;
            size_t o0 = ((size_t)b * C_ + cc) * N_ + col;
            size_t o1 = ((size_t)b * C_ + cc + 8) * N_ + col;
            float2 x0 = *reinterpret_cast<const float2*>(&x[o0]);
            float2 x1 = *reinterpret_cast<const float2*>(&x[o1]);
            *reinterpret_cast<float2*>(&out[o0]) =
                make_float2(gm * c[0] + x0.x, gm * c[1] + x0.y);
            *reinterpret_cast<float2*>(&out[o1]) =
                make_float2(gm * c[2] + x1.x, gm * c[3] + x1.y);
        }
    }
}

// ---------------- launch ----------------------------------------------------
extern "C" void kernel_launch(void* const* d_in, const int* in_sizes, int n_in,
                              void* d_out, int out_size)
{
    const float* x     = (const float*)d_in[0];
    const float* wq    = (const float*)d_in[1];
    const float* bq    = (const float*)d_in[2];
    const float* wk    = (const float*)d_in[3];
    const float* bk    = (const float*)d_in[4];
    const float* wv    = (const float*)d_in[5];
    const float* bv    = (const float*)d_in[6];
    const float* gamma = (const float*)d_in[7];
    float* out = (float*)d_out;

    dim3 blk(16, 16);
    proj_kernel   <<<dim3(N_ / 64, 8, B_), blk>>>(x, wq, bq, wk, bk, wv, bv);
    qk_convert    <<<dim3(N_ / 32, CQK_ / 32, B_ * 2), dim3(32, 8)>>>();
    v_convert     <<<dim3((B_ * C_ * N_) / 1024), 256>>>();
    scores_mma    <<<dim3(N_ / 128, N_ / 128, B_), 256>>>();
    rowstats_kernel<<<dim3(B_ * N_), 128>>>();
    pexp_kernel   <<<dim3(N_ / 64, N_ / 64, B_), 256>>>();
    av_mma        <<<dim3(N_ / 128, C_ / 128, B_), 256>>>(x, gamma, out);
}

// round 8
// speedup vs baseline: 2.3803x; 2.1223x over previous
#include <cuda_runtime.h>
#include <cuda_bf16.h>
#include <math.h>
#include <stdint.h>

#define B_   4
#define C_   256
#define CQK_ 128
#define N_   4096

// ---------------- scratch (device globals; no allocations allowed) ----------
__device__ float g_Q[B_ * CQK_ * N_];
__device__ float g_K[B_ * CQK_ * N_];
__device__ float g_V[B_ * C_ * N_];
__device__ float g_S[(size_t)B_ * N_ * N_];
__device__ float g_L[B_ * N_];

__device__ __nv_bfloat16 g_qhi[B_ * N_ * CQK_];   // [b][n][d]
__device__ __nv_bfloat16 g_qlo[B_ * N_ * CQK_];
__device__ __nv_bfloat16 g_khi[B_ * N_ * CQK_];
__device__ __nv_bfloat16 g_klo[B_ * N_ * CQK_];
__device__ __nv_bfloat16 g_vhi[B_ * C_ * N_];     // [b][c][n]
__device__ __nv_bfloat16 g_vlo[B_ * C_ * N_];
__device__ __nv_bfloat16 g_phi[(size_t)B_ * N_ * N_];  // [b][j][i] (P^T)
__device__ __nv_bfloat16 g_plo[(size_t)B_ * N_ * N_];

// ---------------- PTX helpers (baseline features only) ----------------------
__device__ __forceinline__ uint32_t smem_u32(const void* p) {
    uint32_t a;
    asm("{ .reg .u64 t; cvta.to.shared.u64 t, %1; cvt.u32.u64 %0, t; }" : "=r"(a) : "l"(p));
    return a;
}
__device__ __forceinline__ void mma16816(float* c, const uint32_t* a, const uint32_t* b) {
    asm volatile(
        "mma.sync.aligned.m16n8k16.row.col.f32.bf16.bf16.f32 "
        "{%0,%1,%2,%3}, {%4,%5,%6,%7}, {%8,%9}, {%0,%1,%2,%3};"
        : "+f"(c[0]), "+f"(c[1]), "+f"(c[2]), "+f"(c[3])
        : "r"(a[0]), "r"(a[1]), "r"(a[2]), "r"(a[3]), "r"(b[0]), "r"(b[1]));
}
__device__ __forceinline__ void ldm_x4(uint32_t* r, uint32_t addr) {
    asm volatile("ldmatrix.sync.aligned.m8n8.x4.shared.b16 {%0,%1,%2,%3}, [%4];"
                 : "=r"(r[0]), "=r"(r[1]), "=r"(r[2]), "=r"(r[3]) : "r"(addr));
}
__device__ __forceinline__ void cp16(uint32_t saddr, const void* g) {
    asm volatile("cp.async.cg.shared.global [%0], [%1], 16;" :: "r"(saddr), "l"(g));
}
#define CP_COMMIT() asm volatile("cp.async.commit_group;" ::: "memory")
#define CP_WAIT0()  asm volatile("cp.async.wait_group 0;" ::: "memory")
#define CP_WAIT1()  asm volatile("cp.async.wait_group 1;" ::: "memory")

// ---------------- combined-tile staging --------------------------------------
// tile: 128 rows x 128 bytes; each row = [hi: 32 bf16 | lo: 32 bf16], XOR-swizzled.
__device__ __forceinline__ void stage2(uint32_t sbase, const __nv_bfloat16* hi,
                                       const __nv_bfloat16* lo, size_t rs, int kt, int tid) {
    #pragma unroll
    for (int p = 0; p < 4; p++) {
        int idx = p * 256 + tid;
        int row = idx >> 3, c8 = idx & 7;
        const __nv_bfloat16* src = (c8 < 4) ? (hi + (size_t)row * rs + kt + c8 * 8)
                                            : (lo + (size_t)row * rs + kt + (c8 - 4) * 8);
        uint32_t sa = sbase + row * 128 + ((c8 ^ (row & 7)) << 4);
        cp16(sa, src);
    }
}

// ---------------- one K=32 chunk of 3-term split MMA -------------------------
// acc += Ahi*Bhi + Alo*Bhi + Ahi*Blo  (warp tile 64x32, 8 warps = CTA 128x128)
__device__ __forceinline__ void mma_chunk(float acc[16][4], uint32_t Abase, uint32_t Bbase,
                                          int m_base, int n_base, int lane) {
    const int L7 = lane & 7;
    const int rowA = L7 + (lane & 8);          // + m_base + mi*16
    const int rowB = L7 + ((lane >> 1) & 8);   // + n_base + nip*16
    #pragma unroll
    for (int ks = 0; ks < 2; ks++) {
        const int cAh = 2 * ks + (lane >> 4);
        const int cBh = 2 * ks + ((lane >> 3) & 1);
        const uint32_t swAh = (uint32_t)((cAh ^ L7) << 4);
        const uint32_t swAl = (uint32_t)(((cAh + 4) ^ L7) << 4);
        const uint32_t swBh = (uint32_t)((cBh ^ L7) << 4);
        const uint32_t swBl = (uint32_t)(((cBh + 4) ^ L7) << 4);

        uint32_t bh[2][4], bl[2][4];
        #pragma unroll
        for (int nip = 0; nip < 2; nip++) {
            uint32_t rb = Bbase + (uint32_t)(n_base + nip * 16 + rowB) * 128;
            ldm_x4(bh[nip], rb + swBh);
            ldm_x4(bl[nip], rb + swBl);
        }
        #pragma unroll
        for (int mi = 0; mi < 4; mi++) {
            uint32_t ra = Abase + (uint32_t)(m_base + mi * 16 + rowA) * 128;
            uint32_t ah[4], al[4];
            ldm_x4(ah, ra + swAh);
            ldm_x4(al, ra + swAl);
            #pragma unroll
            for (int nip = 0; nip < 2; nip++) {
                #pragma unroll
                for (int h = 0; h < 2; h++) {
                    float* c = acc[mi * 4 + nip * 2 + h];
                    uint32_t bfh[2] = {bh[nip][2 * h], bh[nip][2 * h + 1]};
                    uint32_t bfl[2] = {bl[nip][2 * h], bl[nip][2 * h + 1]};
                    mma16816(c, ah, bfh);
                    mma16816(c, al, bfh);
                    mma16816(c, ah, bfl);
                }
            }
        }
    }
}

// double-buffered pipeline over NCH chunks of K=32
template <int NCH>
__device__ __forceinline__ void gemm_pipe(float acc[16][4], uint32_t base,
    const __nv_bfloat16* ahi, const __nv_bfloat16* alo, size_t ars,
    const __nv_bfloat16* bhi, const __nv_bfloat16* blo, size_t brs,
    int m_base, int n_base, int tid, int lane)
{
    stage2(base, ahi, alo, ars, 0, tid);
    stage2(base + 16384, bhi, blo, brs, 0, tid);
    CP_COMMIT();
    for (int ch = 0; ch < NCH; ch++) {
        if (ch + 1 < NCH) {
            uint32_t o = (uint32_t)(((ch + 1) & 1) * 32768);
            stage2(base + o, ahi, alo, ars, (ch + 1) * 32, tid);
            stage2(base + o + 16384, bhi, blo, brs, (ch + 1) * 32, tid);
            CP_COMMIT();
            CP_WAIT1();
        } else {
            CP_WAIT0();
        }
        __syncthreads();
        uint32_t o = (uint32_t)((ch & 1) * 32768);
        mma_chunk(acc, base + o, base + o + 16384, m_base, n_base, lane);
        __syncthreads();
    }
}

// ---------------- kernel 1: QKV projections (SIMT) ---------------------------
__global__ __launch_bounds__(256) void proj_kernel(
    const float* __restrict__ x,
    const float* __restrict__ wq, const float* __restrict__ bq,
    const float* __restrict__ wk, const float* __restrict__ bk,
    const float* __restrict__ wv, const float* __restrict__ bv)
{
    __shared__ float As[16][68];
    __shared__ float Bs[16][68];

    const int by = blockIdx.y;
    const int b  = blockIdx.z;
    const float* W; const float* bias; float* out; int row0;
    if (by < 2)      { W = wq; bias = bq; out = g_Q + (size_t)b * CQK_ * N_; row0 = by * 64; }
    else if (by < 4) { W = wk; bias = bk; out = g_K + (size_t)b * CQK_ * N_; row0 = (by - 2) * 64; }
    else             { W = wv; bias = bv; out = g_V + (size_t)b * C_   * N_; row0 = (by - 4) * 64; }

    const int tid = threadIdx.y * 16 + threadIdx.x;
    const int n0  = blockIdx.x * 64;
    const float* xb = x + (size_t)b * C_ * N_;

    float acc[4][4] = {};

    for (int kt = 0; kt < C_; kt += 16) {
        {
            int r  = tid >> 2;
            int k4 = (tid & 3) * 4;
            float4 w4 = *reinterpret_cast<const float4*>(&W[(size_t)(row0 + r) * C_ + kt + k4]);
            As[k4 + 0][r] = w4.x; As[k4 + 1][r] = w4.y;
            As[k4 + 2][r] = w4.z; As[k4 + 3][r] = w4.w;
        }
        {
            int kk = tid >> 4;
            int j4 = (tid & 15) * 4;
            float4 x4 = *reinterpret_cast<const float4*>(&xb[(size_t)(kt + kk) * N_ + n0 + j4]);
            *reinterpret_cast<float4*>(&Bs[kk][j4]) = x4;
        }
        __syncthreads();
        #pragma unroll
        for (int kk = 0; kk < 16; kk++) {
            float4 a4 = *reinterpret_cast<const float4*>(&As[kk][threadIdx.y * 4]);
            float4 b4 = *reinterpret_cast<const float4*>(&Bs[kk][threadIdx.x * 4]);
            float a[4] = {a4.x, a4.y, a4.z, a4.w};
            float c[4] = {b4.x, b4.y, b4.z, b4.w};
            #pragma unroll
            for (int u = 0; u < 4; u++)
                #pragma unroll
                for (int v = 0; v < 4; v++)
                    acc[u][v] += a[u] * c[v];
        }
        __syncthreads();
    }

    #pragma unroll
    for (int u = 0; u < 4; u++) {
        int row = row0 + threadIdx.y * 4 + u;
        float bi = bias[row];
        #pragma unroll
        for (int v = 0; v < 4; v++)
            out[(size_t)row * N_ + n0 + threadIdx.x * 4 + v] = acc[u][v] + bi;
    }
}

// ---------------- kernel 2a: Q/K transpose + bf16 hi/lo split ----------------
__global__ __launch_bounds__(256) void qk_convert()
{
    __shared__ float t[32][33];
    const int z = blockIdx.z;
    const int b = z & 3;
    const bool isK = z >= 4;
    const float* src = (isK ? g_K : g_Q) + (size_t)b * CQK_ * N_;
    __nv_bfloat16* dhi = (isK ? g_khi : g_qhi) + (size_t)b * N_ * CQK_;
    __nv_bfloat16* dlo = (isK ? g_klo : g_qlo) + (size_t)b * N_ * CQK_;

    const int n0 = blockIdx.x * 32;
    const int d0 = blockIdx.y * 32;
    const int tx = threadIdx.x, ty = threadIdx.y;

    #pragma unroll
    for (int k = 0; k < 4; k++) {
        int dd = ty + k * 8;
        t[dd][tx] = src[(size_t)(d0 + dd) * N_ + n0 + tx];
    }
    __syncthreads();
    #pragma unroll
    for (int k = 0; k < 4; k++) {
        int nn = ty + k * 8;
        float f = t[tx][nn];
        __nv_bfloat16 hi = __float2bfloat16(f);
        float r = f - __bfloat162float(hi);
        size_t o = (size_t)(n0 + nn) * CQK_ + d0 + tx;
        dhi[o] = hi;
        dlo[o] = __float2bfloat16(r);
    }
}

// ---------------- kernel 2b: V bf16 hi/lo split ------------------------------
__global__ __launch_bounds__(256) void v_convert()
{
    size_t i = ((size_t)blockIdx.x * 256 + threadIdx.x) * 4;
    float4 f = *reinterpret_cast<const float4*>(&g_V[i]);
    __nv_bfloat16 h0 = __float2bfloat16(f.x), h1 = __float2bfloat16(f.y);
    __nv_bfloat16 h2 = __float2bfloat16(f.z), h3 = __float2bfloat16(f.w);
    __nv_bfloat162 hA, hB, lA, lB;
    hA.x = h0; hA.y = h1; hB.x = h2; hB.y = h3;
    lA.x = __float2bfloat16(f.x - __bfloat162float(h0));
    lA.y = __float2bfloat16(f.y - __bfloat162float(h1));
    lB.x = __float2bfloat16(f.z - __bfloat162float(h2));
    lB.y = __float2bfloat16(f.w - __bfloat162float(h3));
    *reinterpret_cast<__nv_bfloat162*>(&g_vhi[i])     = hA;
    *reinterpret_cast<__nv_bfloat162*>(&g_vhi[i + 2]) = hB;
    *reinterpret_cast<__nv_bfloat162*>(&g_vlo[i])     = lA;
    *reinterpret_cast<__nv_bfloat162*>(&g_vlo[i + 2]) = lB;
}

// ---------------- kernel 3: scores S = Q K^T --------------------------------
__global__ __launch_bounds__(256, 2) void scores_mma()
{
    extern __shared__ char dyn[];
    const uint32_t base = smem_u32(dyn);

    const int tid = threadIdx.x;
    const int lane = tid & 31, wid = tid >> 5;
    const int m_base = (wid & 1) * 64, n_base = (wid >> 1) * 32;
    const int g = lane >> 2, q2 = (lane & 3) * 2;

    const int j0 = blockIdx.x * 128, i0 = blockIdx.y * 128, b = blockIdx.z;

    float acc[16][4] = {};
    gemm_pipe<4>(acc, base,
                 g_qhi + ((size_t)b * N_ + i0) * CQK_,
                 g_qlo + ((size_t)b * N_ + i0) * CQK_, CQK_,
                 g_khi + ((size_t)b * N_ + j0) * CQK_,
                 g_klo + ((size_t)b * N_ + j0) * CQK_, CQK_,
                 m_base, n_base, tid, lane);

    float* Sb = g_S + (size_t)b * N_ * N_;
    #pragma unroll
    for (int mi = 0; mi < 4; mi++) {
        #pragma unroll
        for (int ni = 0; ni < 4; ni++) {
            const float* c = acc[mi * 4 + ni];
            const int r = i0 + m_base + mi * 16 + g;
            const int col = j0 + n_base + ni * 8 + q2;
            *reinterpret_cast<float2*>(&Sb[(size_t)r * N_ + col])       = make_float2(c[0], c[1]);
            *reinterpret_cast<float2*>(&Sb[(size_t)(r + 8) * N_ + col]) = make_float2(c[2], c[3]);
        }
    }
}

// ---------------- kernel 4: per-row logsumexp --------------------------------
__global__ __launch_bounds__(128) void rowstats_kernel()
{
    const int row = blockIdx.x;
    const float* Sr = g_S + (size_t)row * N_;
    const int t = threadIdx.x;

    float v[32];
    float m = -3.0e38f;
    #pragma unroll
    for (int i = 0; i < 32; i++) {
        v[i] = Sr[t + i * 128];
        m = fmaxf(m, v[i]);
    }
    #pragma unroll
    for (int o = 16; o > 0; o >>= 1)
        m = fmaxf(m, __shfl_xor_sync(0xffffffffu, m, o));

    __shared__ float redm[4];
    if ((t & 31) == 0) redm[t >> 5] = m;
    __syncthreads();
    float M = fmaxf(fmaxf(redm[0], redm[1]), fmaxf(redm[2], redm[3]));

    float s = 0.f;
    #pragma unroll
    for (int i = 0; i < 32; i++)
        s += __expf(v[i] - M);
    #pragma unroll
    for (int o = 16; o > 0; o >>= 1)
        s += __shfl_xor_sync(0xffffffffu, s, o);

    __shared__ float reds[4];
    if ((t & 31) == 0) reds[t >> 5] = s;
    __syncthreads();
    if (t == 0)
        g_L[row] = M + __logf(reds[0] + reds[1] + reds[2] + reds[3]);
}

// ---------------- kernel 5: P = exp(S - l), transposed bf16 hi/lo ------------
__global__ __launch_bounds__(256) void pexp_kernel()
{
    __shared__ float t[64][65];
    const int j0 = blockIdx.x * 64, i0 = blockIdx.y * 64, b = blockIdx.z;
    const float* Sb = g_S + (size_t)b * N_ * N_;
    const float* Lb = g_L + (size_t)b * N_;
    const int tid = threadIdx.x;

    #pragma unroll
    for (int r = 0; r < 16; r++) {
        int idx = r * 256 + tid;
        int ii = idx >> 6, jj = idx & 63;
        float l = Lb[i0 + ii];
        t[ii][jj] = __expf(Sb[(size_t)(i0 + ii) * N_ + j0 + jj] - l);
    }
    __syncthreads();

    const int j = tid >> 2, ic = tid & 3;
    __align__(16) __nv_bfloat16 hi[16];
    __align__(16) __nv_bfloat16 lo[16];
    #pragma unroll
    for (int q = 0; q < 16; q++) {
        float p = t[ic * 16 + q][j];
        __nv_bfloat16 h = __float2bfloat16(p);
        hi[q] = h;
        lo[q] = __float2bfloat16(p - __bfloat162float(h));
    }
    size_t obase = ((size_t)b * N_ + j0 + j) * N_ + i0 + ic * 16;
    *reinterpret_cast<uint4*>(g_phi + obase)     = *reinterpret_cast<uint4*>(hi);
    *reinterpret_cast<uint4*>(g_phi + obase + 8) = *reinterpret_cast<uint4*>(hi + 8);
    *reinterpret_cast<uint4*>(g_plo + obase)     = *reinterpret_cast<uint4*>(lo);
    *reinterpret_cast<uint4*>(g_plo + obase + 8) = *reinterpret_cast<uint4*>(lo + 8);
}

// ---------------- kernel 6: AV GEMM + epilogue -------------------------------
__global__ __launch_bounds__(256, 2) void av_mma(
    const float* __restrict__ x, const float* __restrict__ gamma,
    float* __restrict__ out)
{
    extern __shared__ char dyn[];
    const uint32_t base = smem_u32(dyn);

    const int tid = threadIdx.x;
    const int lane = tid & 31, wid = tid >> 5;
    const int m_base = (wid & 1) * 64, n_base = (wid >> 1) * 32;
    const int g = lane >> 2, q2 = (lane & 3) * 2;

    const int j0 = blockIdx.x * 128, c0 = blockIdx.y * 128, b = blockIdx.z;

    float acc[16][4] = {};
    gemm_pipe<128>(acc, base,
                   g_vhi + ((size_t)b * C_ + c0) * N_,
                   g_vlo + ((size_t)b * C_ + c0) * N_, N_,
                   g_phi + ((size_t)b * N_ + j0) * N_,
                   g_plo + ((size_t)b * N_ + j0) * N_, N_,
                   m_base, n_base, tid, lane);

    const float gm = gamma[0];
    #pragma unroll
    for (int mi = 0; mi < 4; mi++) {
        #pragma unroll
        for (int ni = 0; ni < 4; ni++) {
            const float* c = acc[mi * 4 + ni];
            const int cc = c0 + m_base + mi * 16 + g;
            const int col = j0 + n_base + ni * 8 + q2;
            size_t o0 = ((size_t)b * C_ + cc) * N_ + col;
            size_t o1 = ((size_t)b * C_ + cc + 8) * N_ + col;
            float2 x0 = *reinterpret_cast<const float2*>(&x[o0]);
            float2 x1 = *reinterpret_cast<const float2*>(&x[o1]);
            *reinterpret_cast<float2*>(&out[o0]) =
                make_float2(gm * c[0] + x0.x, gm * c[1] + x0.y);
            *reinterpret_cast<float2*>(&out[o1]) =
                make_float2(gm * c[2] + x1.x, gm * c[3] + x1.y);
        }
    }
}

// ---------------- launch -----------------------------------------------------
extern "C" void kernel_launch(void* const* d_in, const int* in_sizes, int n_in,
                              void* d_out, int out_size)
{
    const float* x     = (const float*)d_in[0];
    const float* wq    = (const float*)d_in[1];
    const float* bq    = (const float*)d_in[2];
    const float* wk    = (const float*)d_in[3];
    const float* bk    = (const float*)d_in[4];
    const float* wv    = (const float*)d_in[5];
    const float* bv    = (const float*)d_in[6];
    const float* gamma = (const float*)d_in[7];
    float* out = (float*)d_out;

    const int DYN = 65536;   // 2 stages x (A 16KB + B 16KB)
    cudaFuncSetAttribute(scores_mma, cudaFuncAttributeMaxDynamicSharedMemorySize, DYN);
    cudaFuncSetAttribute(av_mma,     cudaFuncAttributeMaxDynamicSharedMemorySize, DYN);

    dim3 blk(16, 16);
    proj_kernel   <<<dim3(N_ / 64, 8, B_), blk>>>(x, wq, bq, wk, bk, wv, bv);
    qk_convert    <<<dim3(N_ / 32, CQK_ / 32, B_ * 2), dim3(32, 8)>>>();
    v_convert     <<<dim3((B_ * C_ * N_) / 1024), 256>>>();
    scores_mma    <<<dim3(N_ / 128, N_ / 128, B_), 256, DYN>>>();
    rowstats_kernel<<<dim3(B_ * N_), 128>>>();
    pexp_kernel   <<<dim3(N_ / 64, N_ / 64, B_), 256>>>();
    av_mma        <<<dim3(N_ / 128, C_ / 128, B_), 256, DYN>>>(x, gamma, out);
}

// round 9
// speedup vs baseline: 2.7035x; 1.1358x over previous
#include <cuda_runtime.h>
#include <cuda_bf16.h>
#include <math.h>
#include <stdint.h>

#define B_   4
#define C_   256
#define CQK_ 128
#define N_   4096

// ---------------- scratch (device globals; no allocations allowed) ----------
__device__ float g_S[(size_t)B_ * N_ * N_];       // 256 MB [b][i][j]
__device__ float g_L[B_ * N_];

__device__ __nv_bfloat16 g_xThi[B_ * N_ * C_];    // [b][n][c]  8 MB
__device__ __nv_bfloat16 g_xTlo[B_ * N_ * C_];
__device__ __nv_bfloat16 g_wqhi[CQK_ * C_], g_wqlo[CQK_ * C_];
__device__ __nv_bfloat16 g_wkhi[CQK_ * C_], g_wklo[CQK_ * C_];
__device__ __nv_bfloat16 g_wvhi[C_ * C_],   g_wvlo[C_ * C_];

__device__ __nv_bfloat16 g_qhi[B_ * N_ * CQK_];   // [b][n][d]
__device__ __nv_bfloat16 g_qlo[B_ * N_ * CQK_];
__device__ __nv_bfloat16 g_khi[B_ * N_ * CQK_];
__device__ __nv_bfloat16 g_klo[B_ * N_ * CQK_];
__device__ __nv_bfloat16 g_vhi[B_ * C_ * N_];     // [b][c][n]
__device__ __nv_bfloat16 g_vlo[B_ * C_ * N_];
__device__ __nv_bfloat16 g_phi[(size_t)B_ * N_ * N_];  // [b][j][i] (P^T)
__device__ __nv_bfloat16 g_plo[(size_t)B_ * N_ * N_];

// ---------------- PTX helpers (baseline features only) ----------------------
__device__ __forceinline__ uint32_t smem_u32(const void* p) {
    uint32_t a;
    asm("{ .reg .u64 t; cvta.to.shared.u64 t, %1; cvt.u32.u64 %0, t; }" : "=r"(a) : "l"(p));
    return a;
}
__device__ __forceinline__ void mma16816(float* c, const uint32_t* a, const uint32_t* b) {
    asm volatile(
        "mma.sync.aligned.m16n8k16.row.col.f32.bf16.bf16.f32 "
        "{%0,%1,%2,%3}, {%4,%5,%6,%7}, {%8,%9}, {%0,%1,%2,%3};"
        : "+f"(c[0]), "+f"(c[1]), "+f"(c[2]), "+f"(c[3])
        : "r"(a[0]), "r"(a[1]), "r"(a[2]), "r"(a[3]), "r"(b[0]), "r"(b[1]));
}
__device__ __forceinline__ void ldm_x4(uint32_t* r, uint32_t addr) {
    asm volatile("ldmatrix.sync.aligned.m8n8.x4.shared.b16 {%0,%1,%2,%3}, [%4];"
                 : "=r"(r[0]), "=r"(r[1]), "=r"(r[2]), "=r"(r[3]) : "r"(addr));
}
__device__ __forceinline__ void cp16(uint32_t saddr, const void* g) {
    asm volatile("cp.async.cg.shared.global [%0], [%1], 16;" :: "r"(saddr), "l"(g));
}
#define CP_COMMIT() asm volatile("cp.async.commit_group;" ::: "memory")
#define CP_WAIT0()  asm volatile("cp.async.wait_group 0;" ::: "memory")
#define CP_WAIT1()  asm volatile("cp.async.wait_group 1;" ::: "memory")

__device__ __forceinline__ void split_bf16(float v, __nv_bfloat16& h, __nv_bfloat16& l) {
    h = __float2bfloat16(v);
    l = __float2bfloat16(v - __bfloat162float(h));
}

// ---------------- combined-tile staging --------------------------------------
// tile: 128 rows x 128 bytes; row = [hi: 32 bf16 | lo: 32 bf16], XOR-swizzled.
__device__ __forceinline__ void stage2(uint32_t sbase, const __nv_bfloat16* hi,
                                       const __nv_bfloat16* lo, size_t rs, int kt, int tid) {
    #pragma unroll
    for (int p = 0; p < 4; p++) {
        int idx = p * 256 + tid;
        int row = idx >> 3, c8 = idx & 7;
        const __nv_bfloat16* src = (c8 < 4) ? (hi + (size_t)row * rs + kt + c8 * 8)
                                            : (lo + (size_t)row * rs + kt + (c8 - 4) * 8);
        uint32_t sa = sbase + row * 128 + ((c8 ^ (row & 7)) << 4);
        cp16(sa, src);
    }
}

// ---------------- one K=32 chunk of 3-term split MMA -------------------------
__device__ __forceinline__ void mma_chunk(float acc[16][4], uint32_t Abase, uint32_t Bbase,
                                          int m_base, int n_base, int lane) {
    const int L7 = lane & 7;
    const int rowA = L7 + (lane & 8);
    const int rowB = L7 + ((lane >> 1) & 8);
    #pragma unroll
    for (int ks = 0; ks < 2; ks++) {
        const int cAh = 2 * ks + (lane >> 4);
        const int cBh = 2 * ks + ((lane >> 3) & 1);
        const uint32_t swAh = (uint32_t)((cAh ^ L7) << 4);
        const uint32_t swAl = (uint32_t)(((cAh + 4) ^ L7) << 4);
        const uint32_t swBh = (uint32_t)((cBh ^ L7) << 4);
        const uint32_t swBl = (uint32_t)(((cBh + 4) ^ L7) << 4);

        uint32_t bh[2][4], bl[2][4];
        #pragma unroll
        for (int nip = 0; nip < 2; nip++) {
            uint32_t rb = Bbase + (uint32_t)(n_base + nip * 16 + rowB) * 128;
            ldm_x4(bh[nip], rb + swBh);
            ldm_x4(bl[nip], rb + swBl);
        }
        #pragma unroll
        for (int mi = 0; mi < 4; mi++) {
            uint32_t ra = Abase + (uint32_t)(m_base + mi * 16 + rowA) * 128;
            uint32_t ah[4], al[4];
            ldm_x4(ah, ra + swAh);
            ldm_x4(al, ra + swAl);
            #pragma unroll
            for (int nip = 0; nip < 2; nip++) {
                #pragma unroll
                for (int h = 0; h < 2; h++) {
                    float* c = acc[mi * 4 + nip * 2 + h];
                    uint32_t bfh[2] = {bh[nip][2 * h], bh[nip][2 * h + 1]};
                    uint32_t bfl[2] = {bl[nip][2 * h], bl[nip][2 * h + 1]};
                    mma16816(c, ah, bfh);
                    mma16816(c, al, bfh);
                    mma16816(c, ah, bfl);
                }
            }
        }
    }
}

// 3-stage pipeline over NCH chunks of K=32; one __syncthreads per chunk
template <int NCH>
__device__ __forceinline__ void gemm_pipe(float acc[16][4], uint32_t base,
    const __nv_bfloat16* ahi, const __nv_bfloat16* alo, size_t ars,
    const __nv_bfloat16* bhi, const __nv_bfloat16* blo, size_t brs,
    int m_base, int n_base, int tid, int lane)
{
    stage2(base, ahi, alo, ars, 0, tid);
    stage2(base + 16384, bhi, blo, brs, 0, tid);
    CP_COMMIT();
    stage2(base + 32768, ahi, alo, ars, 32, tid);
    stage2(base + 32768 + 16384, bhi, blo, brs, 32, tid);
    CP_COMMIT();
    for (int ch = 0; ch < NCH; ch++) {
        if (ch == NCH - 1) { CP_WAIT0(); } else { CP_WAIT1(); }
        __syncthreads();
        if (ch + 2 < NCH) {
            uint32_t o = (uint32_t)(((ch + 2) % 3) * 32768);
            stage2(base + o, ahi, alo, ars, (ch + 2) * 32, tid);
            stage2(base + o + 16384, bhi, blo, brs, (ch + 2) * 32, tid);
            CP_COMMIT();
        }
        uint32_t o = (uint32_t)((ch % 3) * 32768);
        mma_chunk(acc, base + o, base + o + 16384, m_base, n_base, lane);
    }
}

// ---------------- kernel 1a: x transpose + bf16 hi/lo split ------------------
// x[b][c][n] fp32 -> xT[b][n][c] bf16 hi/lo
__global__ __launch_bounds__(256) void xsplit(const float* __restrict__ x)
{
    __shared__ float t[32][33];
    const int b  = blockIdx.z;
    const int n0 = blockIdx.x * 32;
    const int c0 = blockIdx.y * 32;
    const float* src = x + (size_t)b * C_ * N_;
    const int tx = threadIdx.x, ty = threadIdx.y;

    #pragma unroll
    for (int k = 0; k < 4; k++) {
        int cc = ty + k * 8;
        t[cc][tx] = src[(size_t)(c0 + cc) * N_ + n0 + tx];
    }
    __syncthreads();
    #pragma unroll
    for (int k = 0; k < 4; k++) {
        int nn = ty + k * 8;
        float f = t[tx][nn];
        __nv_bfloat16 h, l;
        split_bf16(f, h, l);
        size_t o = ((size_t)b * N_ + n0 + nn) * C_ + c0 + tx;
        g_xThi[o] = h;
        g_xTlo[o] = l;
    }
}

// ---------------- kernel 1b: weight splits -----------------------------------
__global__ __launch_bounds__(256) void wsplit(const float* __restrict__ wq,
                                              const float* __restrict__ wk,
                                              const float* __restrict__ wv)
{
    int i = blockIdx.x * 256 + threadIdx.x;
    float f; __nv_bfloat16* dh; __nv_bfloat16* dl; int o;
    if (i < 32768)       { f = wq[i];          dh = g_wqhi; dl = g_wqlo; o = i; }
    else if (i < 65536)  { f = wk[i - 32768];  dh = g_wkhi; dl = g_wklo; o = i - 32768; }
    else                 { f = wv[i - 65536];  dh = g_wvhi; dl = g_wvlo; o = i - 65536; }
    __nv_bfloat16 h, l;
    split_bf16(f, h, l);
    dh[o] = h; dl[o] = l;
}

// ---------------- kernel 2a: Q/K projection GEMM -----------------------------
// Q^T[n][d] = xT[n][c] . W[d][c]^T + b[d]; out written as bf16 hi/lo directly
__global__ __launch_bounds__(256, 2) void proj_qk_mma(
    const float* __restrict__ bq, const float* __restrict__ bk)
{
    extern __shared__ char dyn[];
    const uint32_t base = smem_u32(dyn);

    const int tid = threadIdx.x;
    const int lane = tid & 31, wid = tid >> 5;
    const int m_base = (wid & 1) * 64, n_base = (wid >> 1) * 32;
    const int g = lane >> 2, q2 = (lane & 3) * 2;

    const int i0 = blockIdx.x * 128;
    const int zy = blockIdx.y;
    const int b = zy & 3;
    const bool isK = zy >= 4;
    const __nv_bfloat16* whi = isK ? g_wkhi : g_wqhi;
    const __nv_bfloat16* wlo = isK ? g_wklo : g_wqlo;
    const float* bias = isK ? bk : bq;
    __nv_bfloat16* dhi = (isK ? g_khi : g_qhi) + ((size_t)b * N_ + i0) * CQK_;
    __nv_bfloat16* dlo = (isK ? g_klo : g_qlo) + ((size_t)b * N_ + i0) * CQK_;

    float acc[16][4] = {};
    gemm_pipe<8>(acc, base,
                 g_xThi + ((size_t)b * N_ + i0) * C_,
                 g_xTlo + ((size_t)b * N_ + i0) * C_, C_,
                 whi, wlo, C_, m_base, n_base, tid, lane);

    #pragma unroll
    for (int mi = 0; mi < 4; mi++) {
        #pragma unroll
        for (int ni = 0; ni < 4; ni++) {
            const float* c = acc[mi * 4 + ni];
            const int r = m_base + mi * 16 + g;
            const int col = n_base + ni * 8 + q2;
            float2 bb = *reinterpret_cast<const float2*>(&bias[col]);
            __nv_bfloat16 h0, l0, h1, l1;
            split_bf16(c[0] + bb.x, h0, l0);
            split_bf16(c[1] + bb.y, h1, l1);
            __nv_bfloat162 hp; hp.x = h0; hp.y = h1;
            __nv_bfloat162 lp; lp.x = l0; lp.y = l1;
            *reinterpret_cast<__nv_bfloat162*>(&dhi[(size_t)r * CQK_ + col]) = hp;
            *reinterpret_cast<__nv_bfloat162*>(&dlo[(size_t)r * CQK_ + col]) = lp;
            split_bf16(c[2] + bb.x, h0, l0);
            split_bf16(c[3] + bb.y, h1, l1);
            hp.x = h0; hp.y = h1; lp.x = l0; lp.y = l1;
            *reinterpret_cast<__nv_bfloat162*>(&dhi[(size_t)(r + 8) * CQK_ + col]) = hp;
            *reinterpret_cast<__nv_bfloat162*>(&dlo[(size_t)(r + 8) * CQK_ + col]) = lp;
        }
    }
}

// ---------------- kernel 2b: V projection GEMM -------------------------------
// V[c][n] = Wv[c][c'] . xT[n][c']^T + bv[c]; bf16 hi/lo out
__global__ __launch_bounds__(256, 2) void proj_v_mma(const float* __restrict__ bv)
{
    extern __shared__ char dyn[];
    const uint32_t base = smem_u32(dyn);

    const int tid = threadIdx.x;
    const int lane = tid & 31, wid = tid >> 5;
    const int m_base = (wid & 1) * 64, n_base = (wid >> 1) * 32;
    const int g = lane >> 2, q2 = (lane & 3) * 2;

    const int j0 = blockIdx.x * 128;
    const int c0 = blockIdx.y * 128;
    const int b  = blockIdx.z;

    float acc[16][4] = {};
    gemm_pipe<8>(acc, base,
                 g_wvhi + (size_t)c0 * C_, g_wvlo + (size_t)c0 * C_, C_,
                 g_xThi + ((size_t)b * N_ + j0) * C_,
                 g_xTlo + ((size_t)b * N_ + j0) * C_, C_,
                 m_base, n_base, tid, lane);

    #pragma unroll
    for (int mi = 0; mi < 4; mi++) {
        const int cc = c0 + m_base + mi * 16 + g;
        const float bv0 = bv[cc], bv1 = bv[cc + 8];
        #pragma unroll
        for (int ni = 0; ni < 4; ni++) {
            const float* c = acc[mi * 4 + ni];
            const int col = j0 + n_base + ni * 8 + q2;
            __nv_bfloat16 h0, l0, h1, l1;
            split_bf16(c[0] + bv0, h0, l0);
            split_bf16(c[1] + bv0, h1, l1);
            __nv_bfloat162 hp; hp.x = h0; hp.y = h1;
            __nv_bfloat162 lp; lp.x = l0; lp.y = l1;
            size_t o0 = ((size_t)b * C_ + cc) * N_ + col;
            *reinterpret_cast<__nv_bfloat162*>(&g_vhi[o0]) = hp;
            *reinterpret_cast<__nv_bfloat162*>(&g_vlo[o0]) = lp;
            split_bf16(c[2] + bv1, h0, l0);
            split_bf16(c[3] + bv1, h1, l1);
            hp.x = h0; hp.y = h1; lp.x = l0; lp.y = l1;
            size_t o1 = ((size_t)b * C_ + cc + 8) * N_ + col;
            *reinterpret_cast<__nv_bfloat162*>(&g_vhi[o1]) = hp;
            *reinterpret_cast<__nv_bfloat162*>(&g_vlo[o1]) = lp;
        }
    }
}

// ---------------- kernel 3: scores S = Q K^T ---------------------------------
__global__ __launch_bounds__(256, 2) void scores_mma()
{
    extern __shared__ char dyn[];
    const uint32_t base = smem_u32(dyn);

    const int tid = threadIdx.x;
    const int lane = tid & 31, wid = tid >> 5;
    const int m_base = (wid & 1) * 64, n_base = (wid >> 1) * 32;
    const int g = lane >> 2, q2 = (lane & 3) * 2;

    const int j0 = blockIdx.x * 128, i0 = blockIdx.y * 128, b = blockIdx.z;

    float acc[16][4] = {};
    gemm_pipe<4>(acc, base,
                 g_qhi + ((size_t)b * N_ + i0) * CQK_,
                 g_qlo + ((size_t)b * N_ + i0) * CQK_, CQK_,
                 g_khi + ((size_t)b * N_ + j0) * CQK_,
                 g_klo + ((size_t)b * N_ + j0) * CQK_, CQK_,
                 m_base, n_base, tid, lane);

    float* Sb = g_S + (size_t)b * N_ * N_;
    #pragma unroll
    for (int mi = 0; mi < 4; mi++) {
        #pragma unroll
        for (int ni = 0; ni < 4; ni++) {
            const float* c = acc[mi * 4 + ni];
            const int r = i0 + m_base + mi * 16 + g;
            const int col = j0 + n_base + ni * 8 + q2;
            *reinterpret_cast<float2*>(&Sb[(size_t)r * N_ + col])       = make_float2(c[0], c[1]);
            *reinterpret_cast<float2*>(&Sb[(size_t)(r + 8) * N_ + col]) = make_float2(c[2], c[3]);
        }
    }
}

// ---------------- kernel 4: per-row logsumexp --------------------------------
__global__ __launch_bounds__(128) void rowstats_kernel()
{
    const int row = blockIdx.x;
    const float* Sr = g_S + (size_t)row * N_;
    const int t = threadIdx.x;

    float v[32];
    float m = -3.0e38f;
    #pragma unroll
    for (int i = 0; i < 32; i++) {
        v[i] = Sr[t + i * 128];
        m = fmaxf(m, v[i]);
    }
    #pragma unroll
    for (int o = 16; o > 0; o >>= 1)
        m = fmaxf(m, __shfl_xor_sync(0xffffffffu, m, o));

    __shared__ float redm[4];
    if ((t & 31) == 0) redm[t >> 5] = m;
    __syncthreads();
    float M = fmaxf(fmaxf(redm[0], redm[1]), fmaxf(redm[2], redm[3]));

    float s = 0.f;
    #pragma unroll
    for (int i = 0; i < 32; i++)
        s += __expf(v[i] - M);
    #pragma unroll
    for (int o = 16; o > 0; o >>= 1)
        s += __shfl_xor_sync(0xffffffffu, s, o);

    __shared__ float reds[4];
    if ((t & 31) == 0) reds[t >> 5] = s;
    __syncthreads();
    if (t == 0)
        g_L[row] = M + __logf(reds[0] + reds[1] + reds[2] + reds[3]);
}

// ---------------- kernel 5: P = exp(S - l), transposed bf16 hi/lo ------------
__global__ __launch_bounds__(256) void pexp_kernel()
{
    __shared__ float t[64][65];
    const int j0 = blockIdx.x * 64, i0 = blockIdx.y * 64, b = blockIdx.z;
    const float* Sb = g_S + (size_t)b * N_ * N_;
    const float* Lb = g_L + (size_t)b * N_;
    const int tid = threadIdx.x;

    #pragma unroll
    for (int r = 0; r < 16; r++) {
        int idx = r * 256 + tid;
        int ii = idx >> 6, jj = idx & 63;
        float l = Lb[i0 + ii];
        t[ii][jj] = __expf(Sb[(size_t)(i0 + ii) * N_ + j0 + jj] - l);
    }
    __syncthreads();

    const int j = tid >> 2, ic = tid & 3;
    __align__(16) __nv_bfloat16 hi[16];
    __align__(16) __nv_bfloat16 lo[16];
    #pragma unroll
    for (int q = 0; q < 16; q++) {
        float p = t[ic * 16 + q][j];
        __nv_bfloat16 h, l;
        split_bf16(p, h, l);
        hi[q] = h; lo[q] = l;
    }
    size_t obase = ((size_t)b * N_ + j0 + j) * N_ + i0 + ic * 16;
    *reinterpret_cast<uint4*>(g_phi + obase)     = *reinterpret_cast<uint4*>(hi);
    *reinterpret_cast<uint4*>(g_phi + obase + 8) = *reinterpret_cast<uint4*>(hi + 8);
    *reinterpret_cast<uint4*>(g_plo + obase)     = *reinterpret_cast<uint4*>(lo);
    *reinterpret_cast<uint4*>(g_plo + obase + 8) = *reinterpret_cast<uint4*>(lo + 8);
}

// ---------------- kernel 6: AV GEMM + epilogue -------------------------------
__global__ __launch_bounds__(256, 2) void av_mma(
    const float* __restrict__ x, const float* __restrict__ gamma,
    float* __restrict__ out)
{
    extern __shared__ char dyn[];
    const uint32_t base = smem_u32(dyn);

    const int tid = threadIdx.x;
    const int lane = tid & 31, wid = tid >> 5;
    const int m_base = (wid & 1) * 64, n_base = (wid >> 1) * 32;
    const int g = lane >> 2, q2 = (lane & 3) * 2;

    const int j0 = blockIdx.x * 128, c0 = blockIdx.y * 128, b = blockIdx.z;

    float acc[16][4] = {};
    gemm_pipe<128>(acc, base,
                   g_vhi + ((size_t)b * C_ + c0) * N_,
                   g_vlo + ((size_t)b * C_ + c0) * N_, N_,
                   g_phi + ((size_t)b * N_ + j0) * N_,
                   g_plo + ((size_t)b * N_ + j0) * N_, N_,
                   m_base, n_base, tid, lane);

    const float gm = gamma[0];
    #pragma unroll
    for (int mi = 0; mi < 4; mi++) {
        #pragma unroll
        for (int ni = 0; ni < 4; ni++) {
            const float* c = acc[mi * 4 + ni];
            const int cc = c0 + m_base + mi * 16 + g;
            const int col = j0 + n_base + ni * 8 + q2;
            size_t o0 = ((size_t)b * C_ + cc) * N_ + col;
            size_t o1 = ((size_t)b * C_ + cc + 8) * N_ + col;
            float2 x0 = *reinterpret_cast<const float2*>(&x[o0]);
            float2 x1 = *reinterpret_cast<const float2*>(&x[o1]);
            *reinterpret_cast<float2*>(&out[o0]) =
                make_float2(gm * c[0] + x0.x, gm * c[1] + x0.y);
            *reinterpret_cast<float2*>(&out[o1]) =
                make_float2(gm * c[2] + x1.x, gm * c[3] + x1.y);
        }
    }
}

// ---------------- launch -----------------------------------------------------
extern "C" void kernel_launch(void* const* d_in, const int* in_sizes, int n_in,
                              void* d_out, int out_size)
{
    const float* x     = (const float*)d_in[0];
    const float* wq    = (const float*)d_in[1];
    const float* bq    = (const float*)d_in[2];
    const float* wk    = (const float*)d_in[3];
    const float* bk    = (const float*)d_in[4];
    const float* wv    = (const float*)d_in[5];
    const float* bv    = (const float*)d_in[6];
    const float* gamma = (const float*)d_in[7];
    float* out = (float*)d_out;

    const int DYN = 98304;   // 3 stages x (A 16KB + B 16KB)
    cudaFuncSetAttribute(proj_qk_mma, cudaFuncAttributeMaxDynamicSharedMemorySize, DYN);
    cudaFuncSetAttribute(proj_v_mma,  cudaFuncAttributeMaxDynamicSharedMemorySize, DYN);
    cudaFuncSetAttribute(scores_mma,  cudaFuncAttributeMaxDynamicSharedMemorySize, DYN);
    cudaFuncSetAttribute(av_mma,      cudaFuncAttributeMaxDynamicSharedMemorySize, DYN);

    xsplit        <<<dim3(N_ / 32, C_ / 32, B_), dim3(32, 8)>>>(x);
    wsplit        <<<dim3(512), 256>>>(wq, wk, wv);
    proj_qk_mma   <<<dim3(N_ / 128, B_ * 2), 256, DYN>>>(bq, bk);
    proj_v_mma    <<<dim3(N_ / 128, C_ / 128, B_), 256, DYN>>>(bv);
    scores_mma    <<<dim3(N_ / 128, N_ / 128, B_), 256, DYN>>>();
    rowstats_kernel<<<dim3(B_ * N_), 128>>>();
    pexp_kernel   <<<dim3(N_ / 64, N_ / 64, B_), 256>>>();
    av_mma        <<<dim3(N_ / 128, C_ / 128, B_), 256, DYN>>>(x, gamma, out);
}

// round 10
// speedup vs baseline: 3.4858x; 1.2894x over previous
#include <cuda_runtime.h>
#include <cuda_bf16.h>
#include <math.h>
#include <stdint.h>

#define B_   4
#define C_   256
#define CQK_ 128
#define N_   4096

// ---------------- scratch (device globals; no allocations allowed) ----------
__device__ float g_S[(size_t)B_ * N_ * N_];       // 256 MB [b][i][j]
__device__ float g_L[B_ * N_];
__device__ float g_pm[B_ * 32 * N_];              // per-tile row max   [b][jblk][i]
__device__ float g_ps[B_ * 32 * N_];              // per-tile row sumexp

__device__ __nv_bfloat16 g_xThi[B_ * N_ * C_];    // [b][n][c]
__device__ __nv_bfloat16 g_xTlo[B_ * N_ * C_];
__device__ __nv_bfloat16 g_wqhi[CQK_ * C_], g_wqlo[CQK_ * C_];
__device__ __nv_bfloat16 g_wkhi[CQK_ * C_], g_wklo[CQK_ * C_];
__device__ __nv_bfloat16 g_wvhi[C_ * C_],   g_wvlo[C_ * C_];

__device__ __nv_bfloat16 g_qhi[B_ * N_ * CQK_];   // [b][n][d]
__device__ __nv_bfloat16 g_qlo[B_ * N_ * CQK_];
__device__ __nv_bfloat16 g_khi[B_ * N_ * CQK_];
__device__ __nv_bfloat16 g_klo[B_ * N_ * CQK_];
__device__ __nv_bfloat16 g_vhi[B_ * C_ * N_];     // [b][c][n]
__device__ __nv_bfloat16 g_vlo[B_ * C_ * N_];
__device__ __nv_bfloat16 g_phi[(size_t)B_ * N_ * N_];  // [b][j][i] (P^T, hi only)

// ---------------- PTX helpers (baseline features only) ----------------------
__device__ __forceinline__ uint32_t smem_u32(const void* p) {
    uint32_t a;
    asm("{ .reg .u64 t; cvta.to.shared.u64 t, %1; cvt.u32.u64 %0, t; }" : "=r"(a) : "l"(p));
    return a;
}
__device__ __forceinline__ void mma16816(float* c, const uint32_t* a, const uint32_t* b) {
    asm volatile(
        "mma.sync.aligned.m16n8k16.row.col.f32.bf16.bf16.f32 "
        "{%0,%1,%2,%3}, {%4,%5,%6,%7}, {%8,%9}, {%0,%1,%2,%3};"
        : "+f"(c[0]), "+f"(c[1]), "+f"(c[2]), "+f"(c[3])
        : "r"(a[0]), "r"(a[1]), "r"(a[2]), "r"(a[3]), "r"(b[0]), "r"(b[1]));
}
__device__ __forceinline__ void ldm_x4(uint32_t* r, uint32_t addr) {
    asm volatile("ldmatrix.sync.aligned.m8n8.x4.shared.b16 {%0,%1,%2,%3}, [%4];"
                 : "=r"(r[0]), "=r"(r[1]), "=r"(r[2]), "=r"(r[3]) : "r"(addr));
}
__device__ __forceinline__ void cp16(uint32_t saddr, const void* g) {
    asm volatile("cp.async.cg.shared.global [%0], [%1], 16;" :: "r"(saddr), "l"(g));
}
#define CP_COMMIT() asm volatile("cp.async.commit_group;" ::: "memory")
#define CP_WAIT0()  asm volatile("cp.async.wait_group 0;" ::: "memory")
#define CP_WAIT1()  asm volatile("cp.async.wait_group 1;" ::: "memory")

__device__ __forceinline__ void split_bf16(float v, __nv_bfloat16& h, __nv_bfloat16& l) {
    h = __float2bfloat16(v);
    l = __float2bfloat16(v - __bfloat162float(h));
}

// ---------------- staging ----------------------------------------------------
// 128 rows x 128B; row = [hi: 32 bf16 | lo: 32 bf16], XOR-swizzled.
__device__ __forceinline__ void stage2(uint32_t sbase, const __nv_bfloat16* hi,
                                       const __nv_bfloat16* lo, size_t rs, int kt, int tid) {
    #pragma unroll
    for (int p = 0; p < 4; p++) {
        int idx = p * 256 + tid;
        int row = idx >> 3, c8 = idx & 7;
        const __nv_bfloat16* src = (c8 < 4) ? (hi + (size_t)row * rs + kt + c8 * 8)
                                            : (lo + (size_t)row * rs + kt + (c8 - 4) * 8);
        uint32_t sa = sbase + row * 128 + ((c8 ^ (row & 7)) << 4);
        cp16(sa, src);
    }
}
// 128 rows x 64B (hi only, K=32), row-pair swizzle; conflict-free for ldmatrix.
__device__ __forceinline__ void stage1h(uint32_t sbase, const __nv_bfloat16* src,
                                        size_t rs, int kt, int tid) {
    #pragma unroll
    for (int p = 0; p < 2; p++) {
        int idx = p * 256 + tid;
        int row = idx >> 2, c4 = idx & 3;
        uint32_t sa = sbase + row * 64 + ((c4 ^ ((row >> 1) & 3)) << 4);
        cp16(sa, src + (size_t)row * rs + kt + c4 * 8);
    }
}

// ---------------- 3-term K=32 chunk (both operands hi/lo) --------------------
__device__ __forceinline__ void mma_chunk(float acc[16][4], uint32_t Abase, uint32_t Bbase,
                                          int m_base, int n_base, int lane) {
    const int L7 = lane & 7;
    const int rowA = L7 + (lane & 8);
    const int rowB = L7 + ((lane >> 1) & 8);
    #pragma unroll
    for (int ks = 0; ks < 2; ks++) {
        const int cAh = 2 * ks + (lane >> 4);
        const int cBh = 2 * ks + ((lane >> 3) & 1);
        const uint32_t swAh = (uint32_t)((cAh ^ L7) << 4);
        const uint32_t swAl = (uint32_t)(((cAh + 4) ^ L7) << 4);
        const uint32_t swBh = (uint32_t)((cBh ^ L7) << 4);
        const uint32_t swBl = (uint32_t)(((cBh + 4) ^ L7) << 4);

        uint32_t bh[2][4], bl[2][4];
        #pragma unroll
        for (int nip = 0; nip < 2; nip++) {
            uint32_t rb = Bbase + (uint32_t)(n_base + nip * 16 + rowB) * 128;
            ldm_x4(bh[nip], rb + swBh);
            ldm_x4(bl[nip], rb + swBl);
        }
        #pragma unroll
        for (int mi = 0; mi < 4; mi++) {
            uint32_t ra = Abase + (uint32_t)(m_base + mi * 16 + rowA) * 128;
            uint32_t ah[4], al[4];
            ldm_x4(ah, ra + swAh);
            ldm_x4(al, ra + swAl);
            #pragma unroll
            for (int nip = 0; nip < 2; nip++) {
                #pragma unroll
                for (int h = 0; h < 2; h++) {
                    float* c = acc[mi * 4 + nip * 2 + h];
                    uint32_t bfh[2] = {bh[nip][2 * h], bh[nip][2 * h + 1]};
                    uint32_t bfl[2] = {bl[nip][2 * h], bl[nip][2 * h + 1]};
                    mma16816(c, ah, bfh);
                    mma16816(c, al, bfh);
                    mma16816(c, ah, bfl);
                }
            }
        }
    }
}

// ---------------- 2-term K=32 chunk (A hi/lo 128B rows, B hi 64B rows) -------
__device__ __forceinline__ void mma_chunk_av(float acc[16][4], uint32_t Abase, uint32_t Bbase,
                                             int m_base, int n_base, int lane) {
    const int L7 = lane & 7;
    const int rowA = L7 + (lane & 8);
    const int rowB = L7 + ((lane >> 1) & 8);
    #pragma unroll
    for (int ks = 0; ks < 2; ks++) {
        const int cAh = 2 * ks + (lane >> 4);
        const int cB  = 2 * ks + ((lane >> 3) & 1);
        const uint32_t swAh = (uint32_t)((cAh ^ L7) << 4);
        const uint32_t swAl = (uint32_t)(((cAh + 4) ^ L7) << 4);

        uint32_t bh[2][4];
        #pragma unroll
        for (int nip = 0; nip < 2; nip++) {
            int row = n_base + nip * 16 + rowB;
            uint32_t rb = Bbase + (uint32_t)row * 64 + (uint32_t)(((cB ^ ((row >> 1) & 3))) << 4);
            ldm_x4(bh[nip], rb);
        }
        #pragma unroll
        for (int mi = 0; mi < 4; mi++) {
            uint32_t ra = Abase + (uint32_t)(m_base + mi * 16 + rowA) * 128;
            uint32_t ah[4], al[4];
            ldm_x4(ah, ra + swAh);
            ldm_x4(al, ra + swAl);
            #pragma unroll
            for (int nip = 0; nip < 2; nip++) {
                #pragma unroll
                for (int h = 0; h < 2; h++) {
                    float* c = acc[mi * 4 + nip * 2 + h];
                    uint32_t bf[2] = {bh[nip][2 * h], bh[nip][2 * h + 1]};
                    mma16816(c, ah, bf);
                    mma16816(c, al, bf);
                }
            }
        }
    }
}

// 3-stage pipeline, both operands hi/lo (32KB/stage)
template <int NCH>
__device__ __forceinline__ void gemm_pipe(float acc[16][4], uint32_t base,
    const __nv_bfloat16* ahi, const __nv_bfloat16* alo, size_t ars,
    const __nv_bfloat16* bhi, const __nv_bfloat16* blo, size_t brs,
    int m_base, int n_base, int tid, int lane)
{
    stage2(base, ahi, alo, ars, 0, tid);
    stage2(base + 16384, bhi, blo, brs, 0, tid);
    CP_COMMIT();
    stage2(base + 32768, ahi, alo, ars, 32, tid);
    stage2(base + 32768 + 16384, bhi, blo, brs, 32, tid);
    CP_COMMIT();
    for (int ch = 0; ch < NCH; ch++) {
        if (ch == NCH - 1) { CP_WAIT0(); } else { CP_WAIT1(); }
        __syncthreads();
        if (ch + 2 < NCH) {
            uint32_t o = (uint32_t)(((ch + 2) % 3) * 32768);
            stage2(base + o, ahi, alo, ars, (ch + 2) * 32, tid);
            stage2(base + o + 16384, bhi, blo, brs, (ch + 2) * 32, tid);
            CP_COMMIT();
        }
        uint32_t o = (uint32_t)((ch % 3) * 32768);
        mma_chunk(acc, base + o, base + o + 16384, m_base, n_base, lane);
    }
}

// ---------------- kernel 1a: x transpose + bf16 hi/lo split ------------------
__global__ __launch_bounds__(256) void xsplit(const float* __restrict__ x)
{
    __shared__ float t[32][33];
    const int b  = blockIdx.z;
    const int n0 = blockIdx.x * 32;
    const int c0 = blockIdx.y * 32;
    const float* src = x + (size_t)b * C_ * N_;
    const int tx = threadIdx.x, ty = threadIdx.y;

    #pragma unroll
    for (int k = 0; k < 4; k++) {
        int cc = ty + k * 8;
        t[cc][tx] = src[(size_t)(c0 + cc) * N_ + n0 + tx];
    }
    __syncthreads();
    #pragma unroll
    for (int k = 0; k < 4; k++) {
        int nn = ty + k * 8;
        float f = t[tx][nn];
        __nv_bfloat16 h, l;
        split_bf16(f, h, l);
        size_t o = ((size_t)b * N_ + n0 + nn) * C_ + c0 + tx;
        g_xThi[o] = h;
        g_xTlo[o] = l;
    }
}

// ---------------- kernel 1b: weight splits -----------------------------------
__global__ __launch_bounds__(256) void wsplit(const float* __restrict__ wq,
                                              const float* __restrict__ wk,
                                              const float* __restrict__ wv)
{
    int i = blockIdx.x * 256 + threadIdx.x;
    float f; __nv_bfloat16* dh; __nv_bfloat16* dl; int o;
    if (i < 32768)       { f = wq[i];          dh = g_wqhi; dl = g_wqlo; o = i; }
    else if (i < 65536)  { f = wk[i - 32768];  dh = g_wkhi; dl = g_wklo; o = i - 32768; }
    else                 { f = wv[i - 65536];  dh = g_wvhi; dl = g_wvlo; o = i - 65536; }
    __nv_bfloat16 h, l;
    split_bf16(f, h, l);
    dh[o] = h; dl[o] = l;
}

// ---------------- kernel 2a: Q/K projection GEMM -----------------------------
__global__ __launch_bounds__(256, 2) void proj_qk_mma(
    const float* __restrict__ bq, const float* __restrict__ bk)
{
    extern __shared__ char dyn[];
    const uint32_t base = smem_u32(dyn);

    const int tid = threadIdx.x;
    const int lane = tid & 31, wid = tid >> 5;
    const int m_base = (wid & 1) * 64, n_base = (wid >> 1) * 32;
    const int g = lane >> 2, q2 = (lane & 3) * 2;

    const int i0 = blockIdx.x * 128;
    const int zy = blockIdx.y;
    const int b = zy & 3;
    const bool isK = zy >= 4;
    const __nv_bfloat16* whi = isK ? g_wkhi : g_wqhi;
    const __nv_bfloat16* wlo = isK ? g_wklo : g_wqlo;
    const float* bias = isK ? bk : bq;
    __nv_bfloat16* dhi = (isK ? g_khi : g_qhi) + ((size_t)b * N_ + i0) * CQK_;
    __nv_bfloat16* dlo = (isK ? g_klo : g_qlo) + ((size_t)b * N_ + i0) * CQK_;

    float acc[16][4] = {};
    gemm_pipe<8>(acc, base,
                 g_xThi + ((size_t)b * N_ + i0) * C_,
                 g_xTlo + ((size_t)b * N_ + i0) * C_, C_,
                 whi, wlo, C_, m_base, n_base, tid, lane);

    #pragma unroll
    for (int mi = 0; mi < 4; mi++) {
        #pragma unroll
        for (int ni = 0; ni < 4; ni++) {
            const float* c = acc[mi * 4 + ni];
            const int r = m_base + mi * 16 + g;
            const int col = n_base + ni * 8 + q2;
            float2 bb = *reinterpret_cast<const float2*>(&bias[col]);
            __nv_bfloat16 h0, l0, h1, l1;
            split_bf16(c[0] + bb.x, h0, l0);
            split_bf16(c[1] + bb.y, h1, l1);
            __nv_bfloat162 hp; hp.x = h0; hp.y = h1;
            __nv_bfloat162 lp; lp.x = l0; lp.y = l1;
            *reinterpret_cast<__nv_bfloat162*>(&dhi[(size_t)r * CQK_ + col]) = hp;
            *reinterpret_cast<__nv_bfloat162*>(&dlo[(size_t)r * CQK_ + col]) = lp;
            split_bf16(c[2] + bb.x, h0, l0);
            split_bf16(c[3] + bb.y, h1, l1);
            hp.x = h0; hp.y = h1; lp.x = l0; lp.y = l1;
            *reinterpret_cast<__nv_bfloat162*>(&dhi[(size_t)(r + 8) * CQK_ + col]) = hp;
            *reinterpret_cast<__nv_bfloat162*>(&dlo[(size_t)(r + 8) * CQK_ + col]) = lp;
        }
    }
}

// ---------------- kernel 2b: V projection GEMM -------------------------------
__global__ __launch_bounds__(256, 2) void proj_v_mma(const float* __restrict__ bv)
{
    extern __shared__ char dyn[];
    const uint32_t base = smem_u32(dyn);

    const int tid = threadIdx.x;
    const int lane = tid & 31, wid = tid >> 5;
    const int m_base = (wid & 1) * 64, n_base = (wid >> 1) * 32;
    const int g = lane >> 2, q2 = (lane & 3) * 2;

    const int j0 = blockIdx.x * 128;
    const int c0 = blockIdx.y * 128;
    const int b  = blockIdx.z;

    float acc[16][4] = {};
    gemm_pipe<8>(acc, base,
                 g_wvhi + (size_t)c0 * C_, g_wvlo + (size_t)c0 * C_, C_,
                 g_xThi + ((size_t)b * N_ + j0) * C_,
                 g_xTlo + ((size_t)b * N_ + j0) * C_, C_,
                 m_base, n_base, tid, lane);

    #pragma unroll
    for (int mi = 0; mi < 4; mi++) {
        const int cc = c0 + m_base + mi * 16 + g;
        const float bv0 = bv[cc], bv1 = bv[cc + 8];
        #pragma unroll
        for (int ni = 0; ni < 4; ni++) {
            const float* c = acc[mi * 4 + ni];
            const int col = j0 + n_base + ni * 8 + q2;
            __nv_bfloat16 h0, l0, h1, l1;
            split_bf16(c[0] + bv0, h0, l0);
            split_bf16(c[1] + bv0, h1, l1);
            __nv_bfloat162 hp; hp.x = h0; hp.y = h1;
            __nv_bfloat162 lp; lp.x = l0; lp.y = l1;
            size_t o0 = ((size_t)b * C_ + cc) * N_ + col;
            *reinterpret_cast<__nv_bfloat162*>(&g_vhi[o0]) = hp;
            *reinterpret_cast<__nv_bfloat162*>(&g_vlo[o0]) = lp;
            split_bf16(c[2] + bv1, h0, l0);
            split_bf16(c[3] + bv1, h1, l1);
            hp.x = h0; hp.y = h1; lp.x = l0; lp.y = l1;
            size_t o1 = ((size_t)b * C_ + cc + 8) * N_ + col;
            *reinterpret_cast<__nv_bfloat162*>(&g_vhi[o1]) = hp;
            *reinterpret_cast<__nv_bfloat162*>(&g_vlo[o1]) = lp;
        }
    }
}

// ---------------- kernel 3: scores S = Q K^T + fused row partials ------------
__global__ __launch_bounds__(256, 2) void scores_mma()
{
    extern __shared__ char dyn[];
    const uint32_t base = smem_u32(dyn);

    const int tid = threadIdx.x;
    const int lane = tid & 31, wid = tid >> 5;
    const int m_base = (wid & 1) * 64, n_base = (wid >> 1) * 32;
    const int g = lane >> 2, q2 = (lane & 3) * 2;
    const int wn = wid >> 1;

    const int j0 = blockIdx.x * 128, i0 = blockIdx.y * 128, b = blockIdx.z;

    float acc[16][4] = {};
    gemm_pipe<4>(acc, base,
                 g_qhi + ((size_t)b * N_ + i0) * CQK_,
                 g_qlo + ((size_t)b * N_ + i0) * CQK_, CQK_,
                 g_khi + ((size_t)b * N_ + j0) * CQK_,
                 g_klo + ((size_t)b * N_ + j0) * CQK_, CQK_,
                 m_base, n_base, tid, lane);

    // write S tile
    float* Sb = g_S + (size_t)b * N_ * N_;
    #pragma unroll
    for (int mi = 0; mi < 4; mi++) {
        #pragma unroll
        for (int ni = 0; ni < 4; ni++) {
            const float* c = acc[mi * 4 + ni];
            const int r = i0 + m_base + mi * 16 + g;
            const int col = j0 + n_base + ni * 8 + q2;
            *reinterpret_cast<float2*>(&Sb[(size_t)r * N_ + col])       = make_float2(c[0], c[1]);
            *reinterpret_cast<float2*>(&Sb[(size_t)(r + 8) * N_ + col]) = make_float2(c[2], c[3]);
        }
    }

    // fused per-row (max, sumexp) over this tile's 128 columns
    __syncthreads();                       // smem reuse safe
    float* red  = reinterpret_cast<float*>(dyn);   // [128][4] maxes
    float* redM = red + 512;                       // [128]
    float* red2 = redM + 128;                      // [128][4] sums

    #pragma unroll
    for (int mi = 0; mi < 4; mi++) {
        #pragma unroll
        for (int h = 0; h < 2; h++) {
            float m = -3.0e38f;
            #pragma unroll
            for (int ni = 0; ni < 4; ni++) {
                m = fmaxf(m, acc[mi * 4 + ni][2 * h]);
                m = fmaxf(m, acc[mi * 4 + ni][2 * h + 1]);
            }
            m = fmaxf(m, __shfl_xor_sync(0xffffffffu, m, 1));
            m = fmaxf(m, __shfl_xor_sync(0xffffffffu, m, 2));
            if ((lane & 3) == 0)
                red[(m_base + mi * 16 + h * 8 + g) * 4 + wn] = m;
        }
    }
    __syncthreads();
    if (tid < 128) {
        float m = fmaxf(fmaxf(red[tid * 4], red[tid * 4 + 1]),
                        fmaxf(red[tid * 4 + 2], red[tid * 4 + 3]));
        redM[tid] = m;
    }
    __syncthreads();
    #pragma unroll
    for (int mi = 0; mi < 4; mi++) {
        #pragma unroll
        for (int h = 0; h < 2; h++) {
            const int row = m_base + mi * 16 + h * 8 + g;
            const float M = redM[row];
            float s = 0.f;
            #pragma unroll
            for (int ni = 0; ni < 4; ni++) {
                s += __expf(acc[mi * 4 + ni][2 * h] - M);
                s += __expf(acc[mi * 4 + ni][2 * h + 1] - M);
            }
            s += __shfl_xor_sync(0xffffffffu, s, 1);
            s += __shfl_xor_sync(0xffffffffu, s, 2);
            if ((lane & 3) == 0)
                red2[row * 4 + wn] = s;
        }
    }
    __syncthreads();
    if (tid < 128) {
        float S = red2[tid * 4] + red2[tid * 4 + 1] + red2[tid * 4 + 2] + red2[tid * 4 + 3];
        size_t o = ((size_t)b * 32 + blockIdx.x) * N_ + i0 + tid;
        g_pm[o] = redM[tid];
        g_ps[o] = S;
    }
}

// ---------------- kernel 4: combine partials into logsumexp ------------------
__global__ __launch_bounds__(256) void lse_combine()
{
    const int idx = blockIdx.x * 256 + threadIdx.x;   // b*N + i
    const int b = idx >> 12, i = idx & 4095;
    const float* pm = g_pm + (size_t)b * 32 * N_ + i;
    const float* ps = g_ps + (size_t)b * 32 * N_ + i;
    float mv[32];
    float M = -3.0e38f;
    #pragma unroll
    for (int t = 0; t < 32; t++) {
        mv[t] = pm[(size_t)t * N_];
        M = fmaxf(M, mv[t]);
    }
    float S = 0.f;
    #pragma unroll
    for (int t = 0; t < 32; t++)
        S += ps[(size_t)t * N_] * __expf(mv[t] - M);
    g_L[idx] = M + __logf(S);
}

// ---------------- kernel 5: P = exp(S - l), transposed bf16 (hi only) --------
__global__ __launch_bounds__(256) void pexp_kernel()
{
    __shared__ float t[64][65];
    const int j0 = blockIdx.x * 64, i0 = blockIdx.y * 64, b = blockIdx.z;
    const float* Sb = g_S + (size_t)b * N_ * N_;
    const float* Lb = g_L + (size_t)b * N_;
    const int tid = threadIdx.x;

    #pragma unroll
    for (int r = 0; r < 16; r++) {
        int idx = r * 256 + tid;
        int ii = idx >> 6, jj = idx & 63;
        float l = Lb[i0 + ii];
        t[ii][jj] = __expf(Sb[(size_t)(i0 + ii) * N_ + j0 + jj] - l);
    }
    __syncthreads();

    const int j = tid >> 2, ic = tid & 3;
    __align__(16) __nv_bfloat16 hi[16];
    #pragma unroll
    for (int q = 0; q < 16; q++)
        hi[q] = __float2bfloat16(t[ic * 16 + q][j]);
    size_t obase = ((size_t)b * N_ + j0 + j) * N_ + i0 + ic * 16;
    *reinterpret_cast<uint4*>(g_phi + obase)     = *reinterpret_cast<uint4*>(hi);
    *reinterpret_cast<uint4*>(g_phi + obase + 8) = *reinterpret_cast<uint4*>(hi + 8);
}

// ---------------- kernel 6: AV GEMM (2-term) + epilogue ----------------------
__global__ __launch_bounds__(256, 2) void av_mma(
    const float* __restrict__ x, const float* __restrict__ gamma,
    float* __restrict__ out)
{
    extern __shared__ char dyn[];
    const uint32_t base = smem_u32(dyn);

    const int tid = threadIdx.x;
    const int lane = tid & 31, wid = tid >> 5;
    const int m_base = (wid & 1) * 64, n_base = (wid >> 1) * 32;
    const int g = lane >> 2, q2 = (lane & 3) * 2;

    const int j0 = blockIdx.x * 128, c0 = blockIdx.y * 128, b = blockIdx.z;

    const __nv_bfloat16* vhi = g_vhi + ((size_t)b * C_ + c0) * N_;
    const __nv_bfloat16* vlo = g_vlo + ((size_t)b * C_ + c0) * N_;
    const __nv_bfloat16* ph  = g_phi + ((size_t)b * N_ + j0) * N_;

    // 3-stage x 24KB (A 16KB hi|lo + B 8KB hi)
    {
        stage2(base, vhi, vlo, N_, 0, tid);
        stage1h(base + 16384, ph, N_, 0, tid);
        CP_COMMIT();
        stage2(base + 24576, vhi, vlo, N_, 32, tid);
        stage1h(base + 24576 + 16384, ph, N_, 32, tid);
        CP_COMMIT();
    }
    float acc[16][4] = {};
    for (int ch = 0; ch < 128; ch++) {
        if (ch == 127) { CP_WAIT0(); } else { CP_WAIT1(); }
        __syncthreads();
        if (ch + 2 < 128) {
            uint32_t o = (uint32_t)(((ch + 2) % 3) * 24576);
            stage2(base + o, vhi, vlo, N_, (ch + 2) * 32, tid);
            stage1h(base + o + 16384, ph, N_, (ch + 2) * 32, tid);
            CP_COMMIT();
        }
        uint32_t o = (uint32_t)((ch % 3) * 24576);
        mma_chunk_av(acc, base + o, base + o + 16384, m_base, n_base, lane);
    }

    const float gm = gamma[0];
    #pragma unroll
    for (int mi = 0; mi < 4; mi++) {
        #pragma unroll
        for (int ni = 0; ni < 4; ni++) {
            const float* c = acc[mi * 4 + ni];
            const int cc = c0 + m_base + mi * 16 + g;
            const int col = j0 + n_base + ni * 8 + q2;
            size_t o0 = ((size_t)b * C_ + cc) * N_ + col;
            size_t o1 = ((size_t)b * C_ + cc + 8) * N_ + col;
            float2 x0 = *reinterpret_cast<const float2*>(&x[o0]);
            float2 x1 = *reinterpret_cast<const float2*>(&x[o1]);
            *reinterpret_cast<float2*>(&out[o0]) =
                make_float2(gm * c[0] + x0.x, gm * c[1] + x0.y);
            *reinterpret_cast<float2*>(&out[o1]) =
                make_float2(gm * c[2] + x1.x, gm * c[3] + x1.y);
        }
    }
}

// ---------------- launch -----------------------------------------------------
extern "C" void kernel_launch(void* const* d_in, const int* in_sizes, int n_in,
                              void* d_out, int out_size)
{
    const float* x     = (const float*)d_in[0];
    const float* wq    = (const float*)d_in[1];
    const float* bq    = (const float*)d_in[2];
    const float* wk    = (const float*)d_in[3];
    const float* bk    = (const float*)d_in[4];
    const float* wv    = (const float*)d_in[5];
    const float* bv    = (const float*)d_in[6];
    const float* gamma = (const float*)d_in[7];
    float* out = (float*)d_out;

    const int DYN3 = 98304;   // 3 stages x 32KB (hi/lo both operands)
    const int DYNA = 73728;   // 3 stages x 24KB (av)
    cudaFuncSetAttribute(proj_qk_mma, cudaFuncAttributeMaxDynamicSharedMemorySize, DYN3);
    cudaFuncSetAttribute(proj_v_mma,  cudaFuncAttributeMaxDynamicSharedMemorySize, DYN3);
    cudaFuncSetAttribute(scores_mma,  cudaFuncAttributeMaxDynamicSharedMemorySize, DYN3);
    cudaFuncSetAttribute(av_mma,      cudaFuncAttributeMaxDynamicSharedMemorySize, DYNA);

    xsplit        <<<dim3(N_ / 32, C_ / 32, B_), dim3(32, 8)>>>(x);
    wsplit        <<<dim3(512), 256>>>(wq, wk, wv);
    proj_qk_mma   <<<dim3(N_ / 128, B_ * 2), 256, DYN3>>>(bq, bk);
    proj_v_mma    <<<dim3(N_ / 128, C_ / 128, B_), 256, DYN3>>>(bv);
    scores_mma    <<<dim3(N_ / 128, N_ / 128, B_), 256, DYN3>>>();
    lse_combine   <<<dim3(B_ * N_ / 256), 256>>>();
    pexp_kernel   <<<dim3(N_ / 64, N_ / 64, B_), 256>>>();
    av_mma        <<<dim3(N_ / 128, C_ / 128, B_), 256, DYNA>>>(x, gamma, out);
}

// round 11
// speedup vs baseline: 3.5838x; 1.0281x over previous
#include <cuda_runtime.h>
#include <cuda_bf16.h>
#include <math.h>
#include <stdint.h>

#define B_   4
#define C_   256
#define CQK_ 128
#define N_   4096

// ---------------- scratch (device globals; no allocations allowed) ----------
__device__ float g_ST[(size_t)B_ * N_ * N_];      // 256 MB [b][j][i]  (S transposed)
__device__ float g_L[B_ * N_];
__device__ float g_pm[B_ * 32 * N_];              // per-tile row max   [b][jblk][i]
__device__ float g_ps[B_ * 32 * N_];              // per-tile row sumexp

__device__ __nv_bfloat16 g_xThi[B_ * N_ * C_];    // [b][n][c]
__device__ __nv_bfloat16 g_xTlo[B_ * N_ * C_];
__device__ __nv_bfloat16 g_wqhi[CQK_ * C_], g_wqlo[CQK_ * C_];
__device__ __nv_bfloat16 g_wkhi[CQK_ * C_], g_wklo[CQK_ * C_];
__device__ __nv_bfloat16 g_wvhi[C_ * C_],   g_wvlo[C_ * C_];

__device__ __nv_bfloat16 g_qhi[B_ * N_ * CQK_];   // [b][n][d]
__device__ __nv_bfloat16 g_qlo[B_ * N_ * CQK_];
__device__ __nv_bfloat16 g_khi[B_ * N_ * CQK_];
__device__ __nv_bfloat16 g_klo[B_ * N_ * CQK_];
__device__ __nv_bfloat16 g_vhi[B_ * C_ * N_];     // [b][c][n]
__device__ __nv_bfloat16 g_vlo[B_ * C_ * N_];

// ---------------- PTX helpers (baseline features only) ----------------------
__device__ __forceinline__ uint32_t smem_u32(const void* p) {
    uint32_t a;
    asm("{ .reg .u64 t; cvta.to.shared.u64 t, %1; cvt.u32.u64 %0, t; }" : "=r"(a) : "l"(p));
    return a;
}
__device__ __forceinline__ void mma16816(float* c, const uint32_t* a, const uint32_t* b) {
    asm volatile(
        "mma.sync.aligned.m16n8k16.row.col.f32.bf16.bf16.f32 "
        "{%0,%1,%2,%3}, {%4,%5,%6,%7}, {%8,%9}, {%0,%1,%2,%3};"
        : "+f"(c[0]), "+f"(c[1]), "+f"(c[2]), "+f"(c[3])
        : "r"(a[0]), "r"(a[1]), "r"(a[2]), "r"(a[3]), "r"(b[0]), "r"(b[1]));
}
__device__ __forceinline__ void ldm_x4(uint32_t* r, uint32_t addr) {
    asm volatile("ldmatrix.sync.aligned.m8n8.x4.shared.b16 {%0,%1,%2,%3}, [%4];"
                 : "=r"(r[0]), "=r"(r[1]), "=r"(r[2]), "=r"(r[3]) : "r"(addr));
}
__device__ __forceinline__ void cp16(uint32_t saddr, const void* g) {
    asm volatile("cp.async.cg.shared.global [%0], [%1], 16;" :: "r"(saddr), "l"(g));
}
#define CP_COMMIT() asm volatile("cp.async.commit_group;" ::: "memory")
#define CP_WAIT0()  asm volatile("cp.async.wait_group 0;" ::: "memory")
#define CP_WAIT1()  asm volatile("cp.async.wait_group 1;" ::: "memory")

__device__ __forceinline__ void split_bf16(float v, __nv_bfloat16& h, __nv_bfloat16& l) {
    h = __float2bfloat16(v);
    l = __float2bfloat16(v - __bfloat162float(h));
}
__device__ __forceinline__ float4 lds128f(uint32_t addr) {
    float4 v;
    asm volatile("ld.shared.v4.f32 {%0,%1,%2,%3}, [%4];"
                 : "=f"(v.x), "=f"(v.y), "=f"(v.z), "=f"(v.w) : "r"(addr));
    return v;
}
__device__ __forceinline__ void sts128u(uint32_t addr, uint32_t a, uint32_t b,
                                        uint32_t c, uint32_t d) {
    asm volatile("st.shared.v4.b32 [%0], {%1,%2,%3,%4};"
                 :: "r"(addr), "r"(a), "r"(b), "r"(c), "r"(d) : "memory");
}

// ---------------- staging ----------------------------------------------------
// 128 rows x 128B; row = [hi: 32 bf16 | lo: 32 bf16], XOR-swizzled.
__device__ __forceinline__ void stage2(uint32_t sbase, const __nv_bfloat16* hi,
                                       const __nv_bfloat16* lo, size_t rs, int kt, int tid) {
    #pragma unroll
    for (int p = 0; p < 4; p++) {
        int idx = p * 256 + tid;
        int row = idx >> 3, c8 = idx & 7;
        const __nv_bfloat16* src = (c8 < 4) ? (hi + (size_t)row * rs + kt + c8 * 8)
                                            : (lo + (size_t)row * rs + kt + (c8 - 4) * 8);
        uint32_t sa = sbase + row * 128 + ((c8 ^ (row & 7)) << 4);
        cp16(sa, src);
    }
}
// raw fp32 S^T rows: 128 rows x 32 fp32, smem row stride 144B; + l chunk 128B
__device__ __forceinline__ void stage_raw(uint32_t sbase, uint32_t lsbase,
                                          const float* st, const float* l,
                                          int kt, int tid) {
    #pragma unroll
    for (int p = 0; p < 4; p++) {
        int idx = p * 256 + tid;
        int row = idx >> 3, c = idx & 7;
        cp16(sbase + row * 144 + c * 16, st + (size_t)row * N_ + kt + c * 4);
    }
    if (tid < 8) cp16(lsbase + tid * 16, l + kt + tid * 4);
}

// ---------------- 3-term K=32 chunk (both operands hi/lo) --------------------
__device__ __forceinline__ void mma_chunk(float acc[16][4], uint32_t Abase, uint32_t Bbase,
                                          int m_base, int n_base, int lane) {
    const int L7 = lane & 7;
    const int rowA = L7 + (lane & 8);
    const int rowB = L7 + ((lane >> 1) & 8);
    #pragma unroll
    for (int ks = 0; ks < 2; ks++) {
        const int cAh = 2 * ks + (lane >> 4);
        const int cBh = 2 * ks + ((lane >> 3) & 1);
        const uint32_t swAh = (uint32_t)((cAh ^ L7) << 4);
        const uint32_t swAl = (uint32_t)(((cAh + 4) ^ L7) << 4);
        const uint32_t swBh = (uint32_t)((cBh ^ L7) << 4);
        const uint32_t swBl = (uint32_t)(((cBh + 4) ^ L7) << 4);

        uint32_t bh[2][4], bl[2][4];
        #pragma unroll
        for (int nip = 0; nip < 2; nip++) {
            uint32_t rb = Bbase + (uint32_t)(n_base + nip * 16 + rowB) * 128;
            ldm_x4(bh[nip], rb + swBh);
            ldm_x4(bl[nip], rb + swBl);
        }
        #pragma unroll
        for (int mi = 0; mi < 4; mi++) {
            uint32_t ra = Abase + (uint32_t)(m_base + mi * 16 + rowA) * 128;
            uint32_t ah[4], al[4];
            ldm_x4(ah, ra + swAh);
            ldm_x4(al, ra + swAl);
            #pragma unroll
            for (int nip = 0; nip < 2; nip++) {
                #pragma unroll
                for (int h = 0; h < 2; h++) {
                    float* c = acc[mi * 4 + nip * 2 + h];
                    uint32_t bfh[2] = {bh[nip][2 * h], bh[nip][2 * h + 1]};
                    uint32_t bfl[2] = {bl[nip][2 * h], bl[nip][2 * h + 1]};
                    mma16816(c, ah, bfh);
                    mma16816(c, al, bfh);
                    mma16816(c, ah, bfl);
                }
            }
        }
    }
}

// ---------------- 2-term K=32 chunk (A hi/lo 128B rows, B bf16 64B rows) -----
__device__ __forceinline__ void mma_chunk_av(float acc[16][4], uint32_t Abase, uint32_t Bbase,
                                             int m_base, int n_base, int lane) {
    const int L7 = lane & 7;
    const int rowA = L7 + (lane & 8);
    const int rowB = L7 + ((lane >> 1) & 8);
    #pragma unroll
    for (int ks = 0; ks < 2; ks++) {
        const int cAh = 2 * ks + (lane >> 4);
        const int cB  = 2 * ks + ((lane >> 3) & 1);
        const uint32_t swAh = (uint32_t)((cAh ^ L7) << 4);
        const uint32_t swAl = (uint32_t)(((cAh + 4) ^ L7) << 4);

        uint32_t bh[2][4];
        #pragma unroll
        for (int nip = 0; nip < 2; nip++) {
            int row = n_base + nip * 16 + rowB;
            uint32_t rb = Bbase + (uint32_t)row * 64 + (uint32_t)(((cB ^ ((row >> 1) & 3))) << 4);
            ldm_x4(bh[nip], rb);
        }
        #pragma unroll
        for (int mi = 0; mi < 4; mi++) {
            uint32_t ra = Abase + (uint32_t)(m_base + mi * 16 + rowA) * 128;
            uint32_t ah[4], al[4];
            ldm_x4(ah, ra + swAh);
            ldm_x4(al, ra + swAl);
            #pragma unroll
            for (int nip = 0; nip < 2; nip++) {
                #pragma unroll
                for (int h = 0; h < 2; h++) {
                    float* c = acc[mi * 4 + nip * 2 + h];
                    uint32_t bf[2] = {bh[nip][2 * h], bh[nip][2 * h + 1]};
                    mma16816(c, ah, bf);
                    mma16816(c, al, bf);
                }
            }
        }
    }
}

// 3-stage pipeline, both operands hi/lo (32KB/stage)
template <int NCH>
__device__ __forceinline__ void gemm_pipe(float acc[16][4], uint32_t base,
    const __nv_bfloat16* ahi, const __nv_bfloat16* alo, size_t ars,
    const __nv_bfloat16* bhi, const __nv_bfloat16* blo, size_t brs,
    int m_base, int n_base, int tid, int lane)
{
    stage2(base, ahi, alo, ars, 0, tid);
    stage2(base + 16384, bhi, blo, brs, 0, tid);
    CP_COMMIT();
    stage2(base + 32768, ahi, alo, ars, 32, tid);
    stage2(base + 32768 + 16384, bhi, blo, brs, 32, tid);
    CP_COMMIT();
    for (int ch = 0; ch < NCH; ch++) {
        if (ch == NCH - 1) { CP_WAIT0(); } else { CP_WAIT1(); }
        __syncthreads();
        if (ch + 2 < NCH) {
            uint32_t o = (uint32_t)(((ch + 2) % 3) * 32768);
            stage2(base + o, ahi, alo, ars, (ch + 2) * 32, tid);
            stage2(base + o + 16384, bhi, blo, brs, (ch + 2) * 32, tid);
            CP_COMMIT();
        }
        uint32_t o = (uint32_t)((ch % 3) * 32768);
        mma_chunk(acc, base + o, base + o + 16384, m_base, n_base, lane);
    }
}

// ---------------- kernel 1a: x transpose + bf16 hi/lo split ------------------
__global__ __launch_bounds__(256) void xsplit(const float* __restrict__ x)
{
    __shared__ float t[32][33];
    const int b  = blockIdx.z;
    const int n0 = blockIdx.x * 32;
    const int c0 = blockIdx.y * 32;
    const float* src = x + (size_t)b * C_ * N_;
    const int tx = threadIdx.x, ty = threadIdx.y;

    #pragma unroll
    for (int k = 0; k < 4; k++) {
        int cc = ty + k * 8;
        t[cc][tx] = src[(size_t)(c0 + cc) * N_ + n0 + tx];
    }
    __syncthreads();
    #pragma unroll
    for (int k = 0; k < 4; k++) {
        int nn = ty + k * 8;
        float f = t[tx][nn];
        __nv_bfloat16 h, l;
        split_bf16(f, h, l);
        size_t o = ((size_t)b * N_ + n0 + nn) * C_ + c0 + tx;
        g_xThi[o] = h;
        g_xTlo[o] = l;
    }
}

// ---------------- kernel 1b: weight splits -----------------------------------
__global__ __launch_bounds__(256) void wsplit(const float* __restrict__ wq,
                                              const float* __restrict__ wk,
                                              const float* __restrict__ wv)
{
    int i = blockIdx.x * 256 + threadIdx.x;
    float f; __nv_bfloat16* dh; __nv_bfloat16* dl; int o;
    if (i < 32768)       { f = wq[i];          dh = g_wqhi; dl = g_wqlo; o = i; }
    else if (i < 65536)  { f = wk[i - 32768];  dh = g_wkhi; dl = g_wklo; o = i - 32768; }
    else                 { f = wv[i - 65536];  dh = g_wvhi; dl = g_wvlo; o = i - 65536; }
    __nv_bfloat16 h, l;
    split_bf16(f, h, l);
    dh[o] = h; dl[o] = l;
}

// ---------------- kernel 2a: Q/K projection GEMM -----------------------------
__global__ __launch_bounds__(256, 2) void proj_qk_mma(
    const float* __restrict__ bq, const float* __restrict__ bk)
{
    extern __shared__ char dyn[];
    const uint32_t base = smem_u32(dyn);

    const int tid = threadIdx.x;
    const int lane = tid & 31, wid = tid >> 5;
    const int m_base = (wid & 1) * 64, n_base = (wid >> 1) * 32;
    const int g = lane >> 2, q2 = (lane & 3) * 2;

    const int i0 = blockIdx.x * 128;
    const int zy = blockIdx.y;
    const int b = zy & 3;
    const bool isK = zy >= 4;
    const __nv_bfloat16* whi = isK ? g_wkhi : g_wqhi;
    const __nv_bfloat16* wlo = isK ? g_wklo : g_wqlo;
    const float* bias = isK ? bk : bq;
    __nv_bfloat16* dhi = (isK ? g_khi : g_qhi) + ((size_t)b * N_ + i0) * CQK_;
    __nv_bfloat16* dlo = (isK ? g_klo : g_qlo) + ((size_t)b * N_ + i0) * CQK_;

    float acc[16][4] = {};
    gemm_pipe<8>(acc, base,
                 g_xThi + ((size_t)b * N_ + i0) * C_,
                 g_xTlo + ((size_t)b * N_ + i0) * C_, C_,
                 whi, wlo, C_, m_base, n_base, tid, lane);

    #pragma unroll
    for (int mi = 0; mi < 4; mi++) {
        #pragma unroll
        for (int ni = 0; ni < 4; ni++) {
            const float* c = acc[mi * 4 + ni];
            const int r = m_base + mi * 16 + g;
            const int col = n_base + ni * 8 + q2;
            float2 bb = *reinterpret_cast<const float2*>(&bias[col]);
            __nv_bfloat16 h0, l0, h1, l1;
            split_bf16(c[0] + bb.x, h0, l0);
            split_bf16(c[1] + bb.y, h1, l1);
            __nv_bfloat162 hp; hp.x = h0; hp.y = h1;
            __nv_bfloat162 lp; lp.x = l0; lp.y = l1;
            *reinterpret_cast<__nv_bfloat162*>(&dhi[(size_t)r * CQK_ + col]) = hp;
            *reinterpret_cast<__nv_bfloat162*>(&dlo[(size_t)r * CQK_ + col]) = lp;
            split_bf16(c[2] + bb.x, h0, l0);
            split_bf16(c[3] + bb.y, h1, l1);
            hp.x = h0; hp.y = h1; lp.x = l0; lp.y = l1;
            *reinterpret_cast<__nv_bfloat162*>(&dhi[(size_t)(r + 8) * CQK_ + col]) = hp;
            *reinterpret_cast<__nv_bfloat162*>(&dlo[(size_t)(r + 8) * CQK_ + col]) = lp;
        }
    }
}

// ---------------- kernel 2b: V projection GEMM -------------------------------
__global__ __launch_bounds__(256, 2) void proj_v_mma(const float* __restrict__ bv)
{
    extern __shared__ char dyn[];
    const uint32_t base = smem_u32(dyn);

    const int tid = threadIdx.x;
    const int lane = tid & 31, wid = tid >> 5;
    const int m_base = (wid & 1) * 64, n_base = (wid >> 1) * 32;
    const int g = lane >> 2, q2 = (lane & 3) * 2;

    const int j0 = blockIdx.x * 128;
    const int c0 = blockIdx.y * 128;
    const int b  = blockIdx.z;

    float acc[16][4] = {};
    gemm_pipe<8>(acc, base,
                 g_wvhi + (size_t)c0 * C_, g_wvlo + (size_t)c0 * C_, C_,
                 g_xThi + ((size_t)b * N_ + j0) * C_,
                 g_xTlo + ((size_t)b * N_ + j0) * C_, C_,
                 m_base, n_base, tid, lane);

    #pragma unroll
    for (int mi = 0; mi < 4; mi++) {
        const int cc = c0 + m_base + mi * 16 + g;
        const float bv0 = bv[cc], bv1 = bv[cc + 8];
        #pragma unroll
        for (int ni = 0; ni < 4; ni++) {
            const float* c = acc[mi * 4 + ni];
            const int col = j0 + n_base + ni * 8 + q2;
            __nv_bfloat16 h0, l0, h1, l1;
            split_bf16(c[0] + bv0, h0, l0);
            split_bf16(c[1] + bv0, h1, l1);
            __nv_bfloat162 hp; hp.x = h0; hp.y = h1;
            __nv_bfloat162 lp; lp.x = l0; lp.y = l1;
            size_t o0 = ((size_t)b * C_ + cc) * N_ + col;
            *reinterpret_cast<__nv_bfloat162*>(&g_vhi[o0]) = hp;
            *reinterpret_cast<__nv_bfloat162*>(&g_vlo[o0]) = lp;
            split_bf16(c[2] + bv1, h0, l0);
            split_bf16(c[3] + bv1, h1, l1);
            hp.x = h0; hp.y = h1; lp.x = l0; lp.y = l1;
            size_t o1 = ((size_t)b * C_ + cc + 8) * N_ + col;
            *reinterpret_cast<__nv_bfloat162*>(&g_vhi[o1]) = hp;
            *reinterpret_cast<__nv_bfloat162*>(&g_vlo[o1]) = lp;
        }
    }
}

// ---------------- kernel 3: scores; writes S^T + fused row partials ----------
__global__ __launch_bounds__(256, 2) void scores_mma()
{
    extern __shared__ char dyn[];
    const uint32_t base = smem_u32(dyn);

    const int tid = threadIdx.x;
    const int lane = tid & 31, wid = tid >> 5;
    const int m_base = (wid & 1) * 64, n_base = (wid >> 1) * 32;
    const int g = lane >> 2, q2 = (lane & 3) * 2;
    const int wn = wid >> 1;

    const int j0 = blockIdx.x * 128, i0 = blockIdx.y * 128, b = blockIdx.z;

    float acc[16][4] = {};
    gemm_pipe<4>(acc, base,
                 g_qhi + ((size_t)b * N_ + i0) * CQK_,
                 g_qlo + ((size_t)b * N_ + i0) * CQK_, CQK_,
                 g_khi + ((size_t)b * N_ + j0) * CQK_,
                 g_klo + ((size_t)b * N_ + j0) * CQK_, CQK_,
                 m_base, n_base, tid, lane);

    // ---- fused per-row (max, sumexp) over this tile's 128 columns ----
    __syncthreads();
    float* red  = reinterpret_cast<float*>(dyn);   // [128][4]
    float* redM = red + 512;                       // [128]
    float* red2 = redM + 128;                      // [128][4]

    #pragma unroll
    for (int mi = 0; mi < 4; mi++) {
        #pragma unroll
        for (int h = 0; h < 2; h++) {
            float m = -3.0e38f;
            #pragma unroll
            for (int ni = 0; ni < 4; ni++) {
                m = fmaxf(m, acc[mi * 4 + ni][2 * h]);
                m = fmaxf(m, acc[mi * 4 + ni][2 * h + 1]);
            }
            m = fmaxf(m, __shfl_xor_sync(0xffffffffu, m, 1));
            m = fmaxf(m, __shfl_xor_sync(0xffffffffu, m, 2));
            if ((lane & 3) == 0)
                red[(m_base + mi * 16 + h * 8 + g) * 4 + wn] = m;
        }
    }
    __syncthreads();
    if (tid < 128) {
        float m = fmaxf(fmaxf(red[tid * 4], red[tid * 4 + 1]),
                        fmaxf(red[tid * 4 + 2], red[tid * 4 + 3]));
        redM[tid] = m;
    }
    __syncthreads();
    #pragma unroll
    for (int mi = 0; mi < 4; mi++) {
        #pragma unroll
        for (int h = 0; h < 2; h++) {
            const int row = m_base + mi * 16 + h * 8 + g;
            const float M = redM[row];
            float s = 0.f;
            #pragma unroll
            for (int ni = 0; ni < 4; ni++) {
                s += __expf(acc[mi * 4 + ni][2 * h] - M);
                s += __expf(acc[mi * 4 + ni][2 * h + 1] - M);
            }
            s += __shfl_xor_sync(0xffffffffu, s, 1);
            s += __shfl_xor_sync(0xffffffffu, s, 2);
            if ((lane & 3) == 0)
                red2[row * 4 + wn] = s;
        }
    }
    __syncthreads();
    if (tid < 128) {
        float S = red2[tid * 4] + red2[tid * 4 + 1] + red2[tid * 4 + 2] + red2[tid * 4 + 3];
        size_t o = ((size_t)b * 32 + blockIdx.x) * N_ + i0 + tid;
        g_pm[o] = redM[tid];
        g_ps[o] = S;
    }
    __syncthreads();

    // ---- transpose acc -> smem ts[j][i] (pad 132), then coalesced S^T write --
    float* ts = reinterpret_cast<float*>(dyn);     // [128][132]
    #pragma unroll
    for (int mi = 0; mi < 4; mi++) {
        #pragma unroll
        for (int ni = 0; ni < 4; ni++) {
            const float* c = acc[mi * 4 + ni];
            const int r = m_base + mi * 16 + g;        // i local
            const int col = n_base + ni * 8 + q2;      // j local
            ts[col * 132 + r]           = c[0];
            ts[(col + 1) * 132 + r]     = c[1];
            ts[col * 132 + r + 8]       = c[2];
            ts[(col + 1) * 132 + r + 8] = c[3];
        }
    }
    __syncthreads();
    {
        const int jl = tid >> 5;                 // warp id -> base row (8 rows/pass? no: 8 warps)
        const int l4 = (lane) * 4;               // i quad
        float* dstb = g_ST + ((size_t)b * N_ + j0) * N_ + i0;
        #pragma unroll
        for (int it = 0; it < 16; it++) {
            const int j = jl + it * 8;
            float4 v = *reinterpret_cast<const float4*>(&ts[j * 132 + l4]);
            *reinterpret_cast<float4*>(&dstb[(size_t)j * N_ + l4]) = v;
        }
    }
}

// ---------------- kernel 4: combine partials into logsumexp ------------------
__global__ __launch_bounds__(256) void lse_combine()
{
    const int idx = blockIdx.x * 256 + threadIdx.x;   // b*N + i
    const int b = idx >> 12, i = idx & 4095;
    const float* pm = g_pm + (size_t)b * 32 * N_ + i;
    const float* ps = g_ps + (size_t)b * 32 * N_ + i;
    float mv[32];
    float M = -3.0e38f;
    #pragma unroll
    for (int t = 0; t < 32; t++) {
        mv[t] = pm[(size_t)t * N_];
        M = fmaxf(M, mv[t]);
    }
    float S = 0.f;
    #pragma unroll
    for (int t = 0; t < 32; t++)
        S += ps[(size_t)t * N_] * __expf(mv[t] - M);
    g_L[idx] = M + __logf(S);
}

// ---------------- kernel 5: AV GEMM (2-term, exp fused in staging) -----------
// smem layout (offsets from base):
//   A stages:    3 x 16384                     [0, 49152)
//   Braw stages: 3 x 18432 (128 rows x 144B)   [49152, 104448)
//   ls stages:   3 x 128                       [104448, 104832)
//   Bbf:         8192 (128 rows x 64B, swizz)  [104832, 113024)
#define AV_A(s)    (uint32_t)((s) * 16384)
#define AV_RAW(s)  (uint32_t)(49152 + (s) * 18432)
#define AV_LS(s)   (uint32_t)(104448 + (s) * 128)
#define AV_BBF     104832u
#define AV_DYN     113024

__global__ __launch_bounds__(256, 2) void av_mma(
    const float* __restrict__ x, const float* __restrict__ gamma,
    float* __restrict__ out)
{
    extern __shared__ char dyn[];
    const uint32_t base = smem_u32(dyn);

    const int tid = threadIdx.x;
    const int lane = tid & 31, wid = tid >> 5;
    const int m_base = (wid & 1) * 64, n_base = (wid >> 1) * 32;
    const int g = lane >> 2, q2 = (lane & 3) * 2;

    const int j0 = blockIdx.x * 128, c0 = blockIdx.y * 128, b = blockIdx.z;

    const __nv_bfloat16* vhi = g_vhi + ((size_t)b * C_ + c0) * N_;
    const __nv_bfloat16* vlo = g_vlo + ((size_t)b * C_ + c0) * N_;
    const float* stb = g_ST + ((size_t)b * N_ + j0) * N_;
    const float* lb  = g_L + (size_t)b * N_;

    stage2(base + AV_A(0), vhi, vlo, N_, 0, tid);
    stage_raw(base + AV_RAW(0), base + AV_LS(0), stb, lb, 0, tid);
    CP_COMMIT();
    stage2(base + AV_A(1), vhi, vlo, N_, 32, tid);
    stage_raw(base + AV_RAW(1), base + AV_LS(1), stb, lb, 32, tid);
    CP_COMMIT();

    const int cj = tid >> 1, chalf = tid & 1, ci0 = chalf * 16;
    float acc[16][4] = {};

    for (int ch = 0; ch < 128; ch++) {
        if (ch == 127) { CP_WAIT0(); } else { CP_WAIT1(); }
        __syncthreads();                  // raw[ch] visible; mma[ch-1] done -> Bbf free

        // convert raw S^T chunk -> Bbf (exp + bf16), this thread: row cj, i half ci0
        {
            const int s = ch % 3;
            const uint32_t rawb = base + AV_RAW(s) + cj * 144;
            const uint32_t lsb  = base + AV_LS(s);
            uint32_t o[8];
            #pragma unroll
            for (int u = 0; u < 4; u++) {
                float4 sv = lds128f(rawb + (ci0 + u * 4) * 4);
                float4 lv = lds128f(lsb + (ci0 + u * 4) * 4);
                float2 p0 = make_float2(__expf(sv.x - lv.x), __expf(sv.y - lv.y));
                float2 p1 = make_float2(__expf(sv.z - lv.z), __expf(sv.w - lv.w));
                __nv_bfloat162 b0 = __floats2bfloat162_rn(p0.x, p0.y);
                __nv_bfloat162 b1 = __floats2bfloat162_rn(p1.x, p1.y);
                o[u * 2]     = *reinterpret_cast<uint32_t*>(&b0);
                o[u * 2 + 1] = *reinterpret_cast<uint32_t*>(&b1);
            }
            const uint32_t sw = (uint32_t)((cj >> 1) & 3);
            const uint32_t r0 = base + AV_BBF + cj * 64 + (((chalf * 2)     ^ sw) << 4);
            const uint32_t r1 = base + AV_BBF + cj * 64 + (((chalf * 2 + 1) ^ sw) << 4);
            sts128u(r0, o[0], o[1], o[2], o[3]);
            sts128u(r1, o[4], o[5], o[6], o[7]);
        }

        if (ch + 2 < 128) {
            const int s2 = (ch + 2) % 3;
            stage2(base + AV_A(s2), vhi, vlo, N_, (ch + 2) * 32, tid);
            stage_raw(base + AV_RAW(s2), base + AV_LS(s2), stb, lb, (ch + 2) * 32, tid);
            CP_COMMIT();
        }
        __syncthreads();                  // Bbf visible

        mma_chunk_av(acc, base + AV_A(ch % 3), base + AV_BBF, m_base, n_base, lane);
    }

    const float gm = gamma[0];
    #pragma unroll
    for (int mi = 0; mi < 4; mi++) {
        #pragma unroll
        for (int ni = 0; ni < 4; ni++) {
            const float* c = acc[mi * 4 + ni];
            const int cc = c0 + m_base + mi * 16 + g;
            const int col = j0 + n_base + ni * 8 + q2;
            size_t o0 = ((size_t)b * C_ + cc) * N_ + col;
            size_t o1 = ((size_t)b * C_ + cc + 8) * N_ + col;
            float2 x0 = *reinterpret_cast<const float2*>(&x[o0]);
            float2 x1 = *reinterpret_cast<const float2*>(&x[o1]);
            *reinterpret_cast<float2*>(&out[o0]) =
                make_float2(gm * c[0] + x0.x, gm * c[1] + x0.y);
            *reinterpret_cast<float2*>(&out[o1]) =
                make_float2(gm * c[2] + x1.x, gm * c[3] + x1.y);
        }
    }
}

// ---------------- launch -----------------------------------------------------
extern "C" void kernel_launch(void* const* d_in, const int* in_sizes, int n_in,
                              void* d_out, int out_size)
{
    const float* x     = (const float*)d_in[0];
    const float* wq    = (const float*)d_in[1];
    const float* bq    = (const float*)d_in[2];
    const float* wk    = (const float*)d_in[3];
    const float* bk    = (const float*)d_in[4];
    const float* wv    = (const float*)d_in[5];
    const float* bv    = (const float*)d_in[6];
    const float* gamma = (const float*)d_in[7];
    float* out = (float*)d_out;

    const int DYN3 = 98304;   // 3 stages x 32KB
    cudaFuncSetAttribute(proj_qk_mma, cudaFuncAttributeMaxDynamicSharedMemorySize, DYN3);
    cudaFuncSetAttribute(proj_v_mma,  cudaFuncAttributeMaxDynamicSharedMemorySize, DYN3);
    cudaFuncSetAttribute(scores_mma,  cudaFuncAttributeMaxDynamicSharedMemorySize, DYN3);
    cudaFuncSetAttribute(av_mma,      cudaFuncAttributeMaxDynamicSharedMemorySize, AV_DYN);

    xsplit        <<<dim3(N_ / 32, C_ / 32, B_), dim3(32, 8)>>>(x);
    wsplit        <<<dim3(512), 256>>>(wq, wk, wv);
    proj_qk_mma   <<<dim3(N_ / 128, B_ * 2), 256, DYN3>>>(bq, bk);
    proj_v_mma    <<<dim3(N_ / 128, C_ / 128, B_), 256, DYN3>>>(bv);
    scores_mma    <<<dim3(N_ / 128, N_ / 128, B_), 256, DYN3>>>();
    lse_combine   <<<dim3(B_ * N_ / 256), 256>>>();
    av_mma        <<<dim3(N_ / 128, C_ / 128, B_), 256, AV_DYN>>>(x, gamma, out);
}

// round 12
// speedup vs baseline: 3.6979x; 1.0318x over previous
#include <cuda_runtime.h>
#include <cuda_bf16.h>
#include <cuda_fp16.h>
#include <math.h>
#include <stdint.h>

#define B_   4
#define C_   256
#define CQK_ 128
#define N_   4096

// ---------------- scratch (device globals; no allocations allowed) ----------
__device__ __half g_ST[(size_t)B_ * N_ * N_];     // 128 MB [b][j][i]  (S^T, fp16)
__device__ float g_L[B_ * N_];
__device__ float g_ps[B_ * 32 * N_];              // per-tile row sumexp [b][jblk][i]

__device__ __nv_bfloat16 g_xThi[B_ * N_ * C_];    // [b][n][c]
__device__ __nv_bfloat16 g_xTlo[B_ * N_ * C_];
__device__ __nv_bfloat16 g_wqhi[CQK_ * C_], g_wqlo[CQK_ * C_];
__device__ __nv_bfloat16 g_wkhi[CQK_ * C_], g_wklo[CQK_ * C_];
__device__ __nv_bfloat16 g_wvhi[C_ * C_],   g_wvlo[C_ * C_];

__device__ __nv_bfloat16 g_qhi[B_ * N_ * CQK_];   // [b][n][d]
__device__ __nv_bfloat16 g_qlo[B_ * N_ * CQK_];
__device__ __nv_bfloat16 g_khi[B_ * N_ * CQK_];
__device__ __nv_bfloat16 g_klo[B_ * N_ * CQK_];
__device__ __nv_bfloat16 g_vhi[B_ * C_ * N_];     // [b][c][n]
__device__ __nv_bfloat16 g_vlo[B_ * C_ * N_];

// ---------------- PTX helpers (baseline features only) ----------------------
__device__ __forceinline__ uint32_t smem_u32(const void* p) {
    uint32_t a;
    asm("{ .reg .u64 t; cvta.to.shared.u64 t, %1; cvt.u32.u64 %0, t; }" : "=r"(a) : "l"(p));
    return a;
}
__device__ __forceinline__ void mma16816(float* c, const uint32_t* a, const uint32_t* b) {
    asm volatile(
        "mma.sync.aligned.m16n8k16.row.col.f32.bf16.bf16.f32 "
        "{%0,%1,%2,%3}, {%4,%5,%6,%7}, {%8,%9}, {%0,%1,%2,%3};"
        : "+f"(c[0]), "+f"(c[1]), "+f"(c[2]), "+f"(c[3])
        : "r"(a[0]), "r"(a[1]), "r"(a[2]), "r"(a[3]), "r"(b[0]), "r"(b[1]));
}
__device__ __forceinline__ void ldm_x4(uint32_t* r, uint32_t addr) {
    asm volatile("ldmatrix.sync.aligned.m8n8.x4.shared.b16 {%0,%1,%2,%3}, [%4];"
                 : "=r"(r[0]), "=r"(r[1]), "=r"(r[2]), "=r"(r[3]) : "r"(addr));
}
__device__ __forceinline__ void cp16(uint32_t saddr, const void* g) {
    asm volatile("cp.async.cg.shared.global [%0], [%1], 16;" :: "r"(saddr), "l"(g));
}
#define CP_COMMIT() asm volatile("cp.async.commit_group;" ::: "memory")
#define CP_WAIT0()  asm volatile("cp.async.wait_group 0;" ::: "memory")
#define CP_WAIT1()  asm volatile("cp.async.wait_group 1;" ::: "memory")

__device__ __forceinline__ void split_bf16(float v, __nv_bfloat16& h, __nv_bfloat16& l) {
    h = __float2bfloat16(v);
    l = __float2bfloat16(v - __bfloat162float(h));
}
__device__ __forceinline__ float4 lds128f(uint32_t addr) {
    float4 v;
    asm volatile("ld.shared.v4.f32 {%0,%1,%2,%3}, [%4];"
                 : "=f"(v.x), "=f"(v.y), "=f"(v.z), "=f"(v.w) : "r"(addr));
    return v;
}
__device__ __forceinline__ void lds128u(uint32_t* r, uint32_t addr) {
    asm volatile("ld.shared.v4.b32 {%0,%1,%2,%3}, [%4];"
                 : "=r"(r[0]), "=r"(r[1]), "=r"(r[2]), "=r"(r[3]) : "r"(addr));
}
__device__ __forceinline__ void sts128u(uint32_t addr, uint32_t a, uint32_t b,
                                        uint32_t c, uint32_t d) {
    asm volatile("st.shared.v4.b32 [%0], {%1,%2,%3,%4};"
                 :: "r"(addr), "r"(a), "r"(b), "r"(c), "r"(d) : "memory");
}

// ---------------- staging ----------------------------------------------------
// 128 rows x 128B; row = [hi: 32 bf16 | lo: 32 bf16], XOR-swizzled.
__device__ __forceinline__ void stage2(uint32_t sbase, const __nv_bfloat16* hi,
                                       const __nv_bfloat16* lo, size_t rs, int kt, int tid) {
    #pragma unroll
    for (int p = 0; p < 4; p++) {
        int idx = p * 256 + tid;
        int row = idx >> 3, c8 = idx & 7;
        const __nv_bfloat16* src = (c8 < 4) ? (hi + (size_t)row * rs + kt + c8 * 8)
                                            : (lo + (size_t)row * rs + kt + (c8 - 4) * 8);
        uint32_t sa = sbase + row * 128 + ((c8 ^ (row & 7)) << 4);
        cp16(sa, src);
    }
}
// raw fp16 S^T rows: 128 rows x 32 halfs (64B), smem row stride 80B; + l chunk 128B
__device__ __forceinline__ void stage_raw(uint32_t sbase, uint32_t lsbase,
                                          const __half* st, const float* l,
                                          int kt, int tid) {
    #pragma unroll
    for (int p = 0; p < 2; p++) {
        int idx = p * 256 + tid;
        int row = idx >> 2, c = idx & 3;
        cp16(sbase + row * 80 + c * 16, st + (size_t)row * N_ + kt + c * 8);
    }
    if (tid < 8) cp16(lsbase + tid * 16, l + kt + tid * 4);
}

// ---------------- 3-term K=32 chunk (both operands hi/lo) --------------------
__device__ __forceinline__ void mma_chunk(float acc[16][4], uint32_t Abase, uint32_t Bbase,
                                          int m_base, int n_base, int lane) {
    const int L7 = lane & 7;
    const int rowA = L7 + (lane & 8);
    const int rowB = L7 + ((lane >> 1) & 8);
    #pragma unroll
    for (int ks = 0; ks < 2; ks++) {
        const int cAh = 2 * ks + (lane >> 4);
        const int cBh = 2 * ks + ((lane >> 3) & 1);
        const uint32_t swAh = (uint32_t)((cAh ^ L7) << 4);
        const uint32_t swAl = (uint32_t)(((cAh + 4) ^ L7) << 4);
        const uint32_t swBh = (uint32_t)((cBh ^ L7) << 4);
        const uint32_t swBl = (uint32_t)(((cBh + 4) ^ L7) << 4);

        uint32_t bh[2][4], bl[2][4];
        #pragma unroll
        for (int nip = 0; nip < 2; nip++) {
            uint32_t rb = Bbase + (uint32_t)(n_base + nip * 16 + rowB) * 128;
            ldm_x4(bh[nip], rb + swBh);
            ldm_x4(bl[nip], rb + swBl);
        }
        #pragma unroll
        for (int mi = 0; mi < 4; mi++) {
            uint32_t ra = Abase + (uint32_t)(m_base + mi * 16 + rowA) * 128;
            uint32_t ah[4], al[4];
            ldm_x4(ah, ra + swAh);
            ldm_x4(al, ra + swAl);
            #pragma unroll
            for (int nip = 0; nip < 2; nip++) {
                #pragma unroll
                for (int h = 0; h < 2; h++) {
                    float* c = acc[mi * 4 + nip * 2 + h];
                    uint32_t bfh[2] = {bh[nip][2 * h], bh[nip][2 * h + 1]};
                    uint32_t bfl[2] = {bl[nip][2 * h], bl[nip][2 * h + 1]};
                    mma16816(c, ah, bfh);
                    mma16816(c, al, bfh);
                    mma16816(c, ah, bfl);
                }
            }
        }
    }
}

// ---------------- 2-term K=32 chunk (A hi/lo 128B rows, B bf16 64B rows) -----
__device__ __forceinline__ void mma_chunk_av(float acc[16][4], uint32_t Abase, uint32_t Bbase,
                                             int m_base, int n_base, int lane) {
    const int L7 = lane & 7;
    const int rowA = L7 + (lane & 8);
    const int rowB = L7 + ((lane >> 1) & 8);
    #pragma unroll
    for (int ks = 0; ks < 2; ks++) {
        const int cAh = 2 * ks + (lane >> 4);
        const int cB  = 2 * ks + ((lane >> 3) & 1);
        const uint32_t swAh = (uint32_t)((cAh ^ L7) << 4);
        const uint32_t swAl = (uint32_t)(((cAh + 4) ^ L7) << 4);

        uint32_t bh[2][4];
        #pragma unroll
        for (int nip = 0; nip < 2; nip++) {
            int row = n_base + nip * 16 + rowB;
            uint32_t rb = Bbase + (uint32_t)row * 64 + (uint32_t)(((cB ^ ((row >> 1) & 3))) << 4);
            ldm_x4(bh[nip], rb);
        }
        #pragma unroll
        for (int mi = 0; mi < 4; mi++) {
            uint32_t ra = Abase + (uint32_t)(m_base + mi * 16 + rowA) * 128;
            uint32_t ah[4], al[4];
            ldm_x4(ah, ra + swAh);
            ldm_x4(al, ra + swAl);
            #pragma unroll
            for (int nip = 0; nip < 2; nip++) {
                #pragma unroll
                for (int h = 0; h < 2; h++) {
                    float* c = acc[mi * 4 + nip * 2 + h];
                    uint32_t bf[2] = {bh[nip][2 * h], bh[nip][2 * h + 1]};
                    mma16816(c, ah, bf);
                    mma16816(c, al, bf);
                }
            }
        }
    }
}

// 3-stage pipeline, both operands hi/lo (32KB/stage)
template <int NCH>
__device__ __forceinline__ void gemm_pipe(float acc[16][4], uint32_t base,
    const __nv_bfloat16* ahi, const __nv_bfloat16* alo, size_t ars,
    const __nv_bfloat16* bhi, const __nv_bfloat16* blo, size_t brs,
    int m_base, int n_base, int tid, int lane)
{
    stage2(base, ahi, alo, ars, 0, tid);
    stage2(base + 16384, bhi, blo, brs, 0, tid);
    CP_COMMIT();
    stage2(base + 32768, ahi, alo, ars, 32, tid);
    stage2(base + 32768 + 16384, bhi, blo, brs, 32, tid);
    CP_COMMIT();
    for (int ch = 0; ch < NCH; ch++) {
        if (ch == NCH - 1) { CP_WAIT0(); } else { CP_WAIT1(); }
        __syncthreads();
        if (ch + 2 < NCH) {
            uint32_t o = (uint32_t)(((ch + 2) % 3) * 32768);
            stage2(base + o, ahi, alo, ars, (ch + 2) * 32, tid);
            stage2(base + o + 16384, bhi, blo, brs, (ch + 2) * 32, tid);
            CP_COMMIT();
        }
        uint32_t o = (uint32_t)((ch % 3) * 32768);
        mma_chunk(acc, base + o, base + o + 16384, m_base, n_base, lane);
    }
}

// ---------------- kernel 1a: x transpose + bf16 hi/lo split ------------------
// tile: 32 c x 64 n per CTA
__global__ __launch_bounds__(256) void xsplit(const float* __restrict__ x)
{
    __shared__ float t[32][69];
    const int b  = blockIdx.z;
    const int n0 = blockIdx.x * 64;
    const int c0 = blockIdx.y * 32;
    const float* src = x + (size_t)b * C_ * N_;
    const int tid = threadIdx.x;

    #pragma unroll
    for (int p = 0; p < 2; p++) {
        int idx = p * 256 + tid;
        int row = idx >> 4, col4 = (idx & 15) * 4;
        float4 v = *reinterpret_cast<const float4*>(&src[(size_t)(c0 + row) * N_ + n0 + col4]);
        t[row][col4] = v.x; t[row][col4 + 1] = v.y;
        t[row][col4 + 2] = v.z; t[row][col4 + 3] = v.w;
    }
    __syncthreads();

    const int nn = tid >> 2, cseg = (tid & 3) * 8;
    __align__(16) __nv_bfloat16 hi[8];
    __align__(16) __nv_bfloat16 lo[8];
    #pragma unroll
    for (int k = 0; k < 8; k++) {
        __nv_bfloat16 h, l;
        split_bf16(t[cseg + k][nn], h, l);
        hi[k] = h; lo[k] = l;
    }
    size_t o = ((size_t)b * N_ + n0 + nn) * C_ + c0 + cseg;
    *reinterpret_cast<uint4*>(&g_xThi[o]) = *reinterpret_cast<uint4*>(hi);
    *reinterpret_cast<uint4*>(&g_xTlo[o]) = *reinterpret_cast<uint4*>(lo);
}

// ---------------- kernel 1b: weight splits -----------------------------------
__global__ __launch_bounds__(256) void wsplit(const float* __restrict__ wq,
                                              const float* __restrict__ wk,
                                              const float* __restrict__ wv)
{
    int i = blockIdx.x * 256 + threadIdx.x;
    float f; __nv_bfloat16* dh; __nv_bfloat16* dl; int o;
    if (i < 32768)       { f = wq[i];          dh = g_wqhi; dl = g_wqlo; o = i; }
    else if (i < 65536)  { f = wk[i - 32768];  dh = g_wkhi; dl = g_wklo; o = i - 32768; }
    else                 { f = wv[i - 65536];  dh = g_wvhi; dl = g_wvlo; o = i - 65536; }
    __nv_bfloat16 h, l;
    split_bf16(f, h, l);
    dh[o] = h; dl[o] = l;
}

// ---------------- kernel 2a: Q/K projection GEMM -----------------------------
__global__ __launch_bounds__(256, 2) void proj_qk_mma(
    const float* __restrict__ bq, const float* __restrict__ bk)
{
    extern __shared__ char dyn[];
    const uint32_t base = smem_u32(dyn);

    const int tid = threadIdx.x;
    const int lane = tid & 31, wid = tid >> 5;
    const int m_base = (wid & 1) * 64, n_base = (wid >> 1) * 32;
    const int g = lane >> 2, q2 = (lane & 3) * 2;

    const int i0 = blockIdx.x * 128;
    const int zy = blockIdx.y;
    const int b = zy & 3;
    const bool isK = zy >= 4;
    const __nv_bfloat16* whi = isK ? g_wkhi : g_wqhi;
    const __nv_bfloat16* wlo = isK ? g_wklo : g_wqlo;
    const float* bias = isK ? bk : bq;
    __nv_bfloat16* dhi = (isK ? g_khi : g_qhi) + ((size_t)b * N_ + i0) * CQK_;
    __nv_bfloat16* dlo = (isK ? g_klo : g_qlo) + ((size_t)b * N_ + i0) * CQK_;

    float acc[16][4] = {};
    gemm_pipe<8>(acc, base,
                 g_xThi + ((size_t)b * N_ + i0) * C_,
                 g_xTlo + ((size_t)b * N_ + i0) * C_, C_,
                 whi, wlo, C_, m_base, n_base, tid, lane);

    #pragma unroll
    for (int mi = 0; mi < 4; mi++) {
        #pragma unroll
        for (int ni = 0; ni < 4; ni++) {
            const float* c = acc[mi * 4 + ni];
            const int r = m_base + mi * 16 + g;
            const int col = n_base + ni * 8 + q2;
            float2 bb = *reinterpret_cast<const float2*>(&bias[col]);
            __nv_bfloat16 h0, l0, h1, l1;
            split_bf16(c[0] + bb.x, h0, l0);
            split_bf16(c[1] + bb.y, h1, l1);
            __nv_bfloat162 hp; hp.x = h0; hp.y = h1;
            __nv_bfloat162 lp; lp.x = l0; lp.y = l1;
            *reinterpret_cast<__nv_bfloat162*>(&dhi[(size_t)r * CQK_ + col]) = hp;
            *reinterpret_cast<__nv_bfloat162*>(&dlo[(size_t)r * CQK_ + col]) = lp;
            split_bf16(c[2] + bb.x, h0, l0);
            split_bf16(c[3] + bb.y, h1, l1);
            hp.x = h0; hp.y = h1; lp.x = l0; lp.y = l1;
            *reinterpret_cast<__nv_bfloat162*>(&dhi[(size_t)(r + 8) * CQK_ + col]) = hp;
            *reinterpret_cast<__nv_bfloat162*>(&dlo[(size_t)(r + 8) * CQK_ + col]) = lp;
        }
    }
}

// ---------------- kernel 2b: V projection GEMM -------------------------------
__global__ __launch_bounds__(256, 2) void proj_v_mma(const float* __restrict__ bv)
{
    extern __shared__ char dyn[];
    const uint32_t base = smem_u32(dyn);

    const int tid = threadIdx.x;
    const int lane = tid & 31, wid = tid >> 5;
    const int m_base = (wid & 1) * 64, n_base = (wid >> 1) * 32;
    const int g = lane >> 2, q2 = (lane & 3) * 2;

    const int j0 = blockIdx.x * 128;
    const int c0 = blockIdx.y * 128;
    const int b  = blockIdx.z;

    float acc[16][4] = {};
    gemm_pipe<8>(acc, base,
                 g_wvhi + (size_t)c0 * C_, g_wvlo + (size_t)c0 * C_, C_,
                 g_xThi + ((size_t)b * N_ + j0) * C_,
                 g_xTlo + ((size_t)b * N_ + j0) * C_, C_,
                 m_base, n_base, tid, lane);

    #pragma unroll
    for (int mi = 0; mi < 4; mi++) {
        const int cc = c0 + m_base + mi * 16 + g;
        const float bv0 = bv[cc], bv1 = bv[cc + 8];
        #pragma unroll
        for (int ni = 0; ni < 4; ni++) {
            const float* c = acc[mi * 4 + ni];
            const int col = j0 + n_base + ni * 8 + q2;
            __nv_bfloat16 h0, l0, h1, l1;
            split_bf16(c[0] + bv0, h0, l0);
            split_bf16(c[1] + bv0, h1, l1);
            __nv_bfloat162 hp; hp.x = h0; hp.y = h1;
            __nv_bfloat162 lp; lp.x = l0; lp.y = l1;
            size_t o0 = ((size_t)b * C_ + cc) * N_ + col;
            *reinterpret_cast<__nv_bfloat162*>(&g_vhi[o0]) = hp;
            *reinterpret_cast<__nv_bfloat162*>(&g_vlo[o0]) = lp;
            split_bf16(c[2] + bv1, h0, l0);
            split_bf16(c[3] + bv1, h1, l1);
            hp.x = h0; hp.y = h1; lp.x = l0; lp.y = l1;
            size_t o1 = ((size_t)b * C_ + cc + 8) * N_ + col;
            *reinterpret_cast<__nv_bfloat162*>(&g_vhi[o1]) = hp;
            *reinterpret_cast<__nv_bfloat162*>(&g_vlo[o1]) = lp;
        }
    }
}

// ---------------- kernel 3: scores; writes S^T (fp16) + row sumexp partials --
__global__ __launch_bounds__(256, 2) void scores_mma()
{
    extern __shared__ char dyn[];
    const uint32_t base = smem_u32(dyn);

    const int tid = threadIdx.x;
    const int lane = tid & 31, wid = tid >> 5;
    const int m_base = (wid & 1) * 64, n_base = (wid >> 1) * 32;
    const int g = lane >> 2, q2 = (lane & 3) * 2;
    const int wn = wid >> 1;

    const int j0 = blockIdx.x * 128, i0 = blockIdx.y * 128, b = blockIdx.z;

    float acc[16][4] = {};
    gemm_pipe<4>(acc, base,
                 g_qhi + ((size_t)b * N_ + i0) * CQK_,
                 g_qlo + ((size_t)b * N_ + i0) * CQK_, CQK_,
                 g_khi + ((size_t)b * N_ + j0) * CQK_,
                 g_klo + ((size_t)b * N_ + j0) * CQK_, CQK_,
                 m_base, n_base, tid, lane);

    // ---- per-row sumexp over this tile (no max subtraction; S bounded) ------
    __syncthreads();
    float* red2 = reinterpret_cast<float*>(dyn);   // [128][4]
    #pragma unroll
    for (int mi = 0; mi < 4; mi++) {
        #pragma unroll
        for (int h = 0; h < 2; h++) {
            const int row = m_base + mi * 16 + h * 8 + g;
            float s = 0.f;
            #pragma unroll
            for (int ni = 0; ni < 4; ni++) {
                s += __expf(acc[mi * 4 + ni][2 * h]);
                s += __expf(acc[mi * 4 + ni][2 * h + 1]);
            }
            s += __shfl_xor_sync(0xffffffffu, s, 1);
            s += __shfl_xor_sync(0xffffffffu, s, 2);
            if ((lane & 3) == 0)
                red2[row * 4 + wn] = s;
        }
    }
    __syncthreads();
    if (tid < 128) {
        float S = red2[tid * 4] + red2[tid * 4 + 1] + red2[tid * 4 + 2] + red2[tid * 4 + 3];
        g_ps[((size_t)b * 32 + blockIdx.x) * N_ + i0 + tid] = S;
    }
    __syncthreads();

    // ---- transpose acc -> smem ts[j][i] (pad 132), then coalesced fp16 write -
    float* ts = reinterpret_cast<float*>(dyn);     // [128][132]
    #pragma unroll
    for (int mi = 0; mi < 4; mi++) {
        #pragma unroll
        for (int ni = 0; ni < 4; ni++) {
            const float* c = acc[mi * 4 + ni];
            const int r = m_base + mi * 16 + g;
            const int col = n_base + ni * 8 + q2;
            ts[col * 132 + r]           = c[0];
            ts[(col + 1) * 132 + r]     = c[1];
            ts[col * 132 + r + 8]       = c[2];
            ts[(col + 1) * 132 + r + 8] = c[3];
        }
    }
    __syncthreads();
    {
        const int jl = tid >> 5;
        const int l4 = lane * 4;
        __half* dstb = g_ST + ((size_t)b * N_ + j0) * N_ + i0;
        #pragma unroll
        for (int it = 0; it < 16; it++) {
            const int j = jl + it * 8;
            float4 v = *reinterpret_cast<const float4*>(&ts[j * 132 + l4]);
            __half2 h01 = __floats2half2_rn(v.x, v.y);
            __half2 h23 = __floats2half2_rn(v.z, v.w);
            uint2 pk;
            pk.x = *reinterpret_cast<uint32_t*>(&h01);
            pk.y = *reinterpret_cast<uint32_t*>(&h23);
            *reinterpret_cast<uint2*>(&dstb[(size_t)j * N_ + l4]) = pk;
        }
    }
}

// ---------------- kernel 4: combine partials into logsumexp ------------------
__global__ __launch_bounds__(256) void lse_combine()
{
    const int idx = blockIdx.x * 256 + threadIdx.x;   // b*N + i
    const int b = idx >> 12, i = idx & 4095;
    const float* ps = g_ps + (size_t)b * 32 * N_ + i;
    float S = 0.f;
    #pragma unroll
    for (int t = 0; t < 32; t++)
        S += ps[(size_t)t * N_];
    g_L[idx] = __logf(S);
}

// ---------------- kernel 5: AV GEMM (2-term, exp fused in staging) -----------
// smem: A 3x16384 [0,49152) | raw 3x10240 [49152,79872) | ls 3x128 [79872,80256)
//       | Bbf 8192 [80256,88448)
#define AV_A(s)    (uint32_t)((s) * 16384)
#define AV_RAW(s)  (uint32_t)(49152 + (s) * 10240)
#define AV_LS(s)   (uint32_t)(79872 + (s) * 128)
#define AV_BBF     80256u
#define AV_DYN     88448

__global__ __launch_bounds__(256, 2) void av_mma(
    const float* __restrict__ x, const float* __restrict__ gamma,
    float* __restrict__ out)
{
    extern __shared__ char dyn[];
    const uint32_t base = smem_u32(dyn);

    const int tid = threadIdx.x;
    const int lane = tid & 31, wid = tid >> 5;
    const int m_base = (wid & 1) * 64, n_base = (wid >> 1) * 32;
    const int g = lane >> 2, q2 = (lane & 3) * 2;

    const int j0 = blockIdx.x * 128, c0 = blockIdx.y * 128, b = blockIdx.z;

    const __nv_bfloat16* vhi = g_vhi + ((size_t)b * C_ + c0) * N_;
    const __nv_bfloat16* vlo = g_vlo + ((size_t)b * C_ + c0) * N_;
    const __half* stb = g_ST + ((size_t)b * N_ + j0) * N_;
    const float* lb  = g_L + (size_t)b * N_;

    stage2(base + AV_A(0), vhi, vlo, N_, 0, tid);
    stage_raw(base + AV_RAW(0), base + AV_LS(0), stb, lb, 0, tid);
    CP_COMMIT();
    stage2(base + AV_A(1), vhi, vlo, N_, 32, tid);
    stage_raw(base + AV_RAW(1), base + AV_LS(1), stb, lb, 32, tid);
    CP_COMMIT();

    const int cj = tid >> 1, chalf = tid & 1, ci0 = chalf * 16;
    float acc[16][4] = {};

    for (int ch = 0; ch < 128; ch++) {
        if (ch == 127) { CP_WAIT0(); } else { CP_WAIT1(); }
        __syncthreads();                  // raw[ch] visible; mma[ch-1] done

        // convert raw fp16 S^T chunk -> Bbf (exp + bf16); thread: row cj, half ci0
        {
            const int s = ch % 3;
            const uint32_t rawb = base + AV_RAW(s) + cj * 80 + chalf * 32;
            const uint32_t lsb  = base + AV_LS(s);
            uint32_t hraw[8];
            lds128u(hraw, rawb);
            lds128u(hraw + 4, rawb + 16);
            uint32_t o[8];
            #pragma unroll
            for (int u = 0; u < 4; u++) {
                float2 sa = __half22float2(*reinterpret_cast<__half2*>(&hraw[u * 2]));
                float2 sb = __half22float2(*reinterpret_cast<__half2*>(&hraw[u * 2 + 1]));
                float4 lv = lds128f(lsb + (ci0 + u * 4) * 4);
                __nv_bfloat162 b0 = __floats2bfloat162_rn(__expf(sa.x - lv.x), __expf(sa.y - lv.y));
                __nv_bfloat162 b1 = __floats2bfloat162_rn(__expf(sb.x - lv.z), __expf(sb.y - lv.w));
                o[u * 2]     = *reinterpret_cast<uint32_t*>(&b0);
                o[u * 2 + 1] = *reinterpret_cast<uint32_t*>(&b1);
            }
            const uint32_t sw = (uint32_t)((cj >> 1) & 3);
            const uint32_t r0 = base + AV_BBF + cj * 64 + (((chalf * 2)     ^ sw) << 4);
            const uint32_t r1 = base + AV_BBF + cj * 64 + (((chalf * 2 + 1) ^ sw) << 4);
            sts128u(r0, o[0], o[1], o[2], o[3]);
            sts128u(r1, o[4], o[5], o[6], o[7]);
        }

        if (ch + 2 < 128) {
            const int s2 = (ch + 2) % 3;
            stage2(base + AV_A(s2), vhi, vlo, N_, (ch + 2) * 32, tid);
            stage_raw(base + AV_RAW(s2), base + AV_LS(s2), stb, lb, (ch + 2) * 32, tid);
            CP_COMMIT();
        }
        __syncthreads();                  // Bbf visible

        mma_chunk_av(acc, base + AV_A(ch % 3), base + AV_BBF, m_base, n_base, lane);
    }

    const float gm = gamma[0];
    #pragma unroll
    for (int mi = 0; mi < 4; mi++) {
        #pragma unroll
        for (int ni = 0; ni < 4; ni++) {
            const float* c = acc[mi * 4 + ni];
            const int cc = c0 + m_base + mi * 16 + g;
            const int col = j0 + n_base + ni * 8 + q2;
            size_t o0 = ((size_t)b * C_ + cc) * N_ + col;
            size_t o1 = ((size_t)b * C_ + cc + 8) * N_ + col;
            float2 x0 = *reinterpret_cast<const float2*>(&x[o0]);
            float2 x1 = *reinterpret_cast<const float2*>(&x[o1]);
            *reinterpret_cast<float2*>(&out[o0]) =
                make_float2(gm * c[0] + x0.x, gm * c[1] + x0.y);
            *reinterpret_cast<float2*>(&out[o1]) =
                make_float2(gm * c[2] + x1.x, gm * c[3] + x1.y);
        }
    }
}

// ---------------- launch -----------------------------------------------------
extern "C" void kernel_launch(void* const* d_in, const int* in_sizes, int n_in,
                              void* d_out, int out_size)
{
    const float* x     = (const float*)d_in[0];
    const float* wq    = (const float*)d_in[1];
    const float* bq    = (const float*)d_in[2];
    const float* wk    = (const float*)d_in[3];
    const float* bk    = (const float*)d_in[4];
    const float* wv    = (const float*)d_in[5];
    const float* bv    = (const float*)d_in[6];
    const float* gamma = (const float*)d_in[7];
    float* out = (float*)d_out;

    const int DYN3 = 98304;   // 3 stages x 32KB
    cudaFuncSetAttribute(proj_qk_mma, cudaFuncAttributeMaxDynamicSharedMemorySize, DYN3);
    cudaFuncSetAttribute(proj_v_mma,  cudaFuncAttributeMaxDynamicSharedMemorySize, DYN3);
    cudaFuncSetAttribute(scores_mma,  cudaFuncAttributeMaxDynamicSharedMemorySize, DYN3);
    cudaFuncSetAttribute(av_mma,      cudaFuncAttributeMaxDynamicSharedMemorySize, AV_DYN);

    xsplit        <<<dim3(N_ / 64, C_ / 32, B_), 256>>>(x);
    wsplit        <<<dim3(512), 256>>>(wq, wk, wv);
    proj_qk_mma   <<<dim3(N_ / 128, B_ * 2), 256, DYN3>>>(bq, bk);
    proj_v_mma    <<<dim3(N_ / 128, C_ / 128, B_), 256, DYN3>>>(bv);
    scores_mma    <<<dim3(N_ / 128, N_ / 128, B_), 256, DYN3>>>();
    lse_combine   <<<dim3(B_ * N_ / 256), 256>>>();
    av_mma        <<<dim3(N_ / 128, C_ / 128, B_), 256, AV_DYN>>>(x, gamma, out);
}

// round 13
// speedup vs baseline: 4.2173x; 1.1405x over previous
#include <cuda_runtime.h>
#include <cuda_bf16.h>
#include <math.h>
#include <stdint.h>

#define B_   4
#define C_   256
#define CQK_ 128
#define N_   4096

// ---------------- scratch (device globals; no allocations allowed) ----------
__device__ __nv_bfloat16 g_PT[(size_t)B_ * N_ * N_];  // 128 MB [b][j][i] = exp(S^T)
__device__ float g_Linv[B_ * N_];                     // 1 / sum_j exp(S[i][j])
__device__ float g_ps[B_ * 32 * N_];                  // per-tile row sumexp

__device__ __nv_bfloat16 g_xThi[B_ * N_ * C_];    // [b][n][c]
__device__ __nv_bfloat16 g_xTlo[B_ * N_ * C_];
__device__ __nv_bfloat16 g_wqhi[CQK_ * C_], g_wqlo[CQK_ * C_];
__device__ __nv_bfloat16 g_wkhi[CQK_ * C_], g_wklo[CQK_ * C_];
__device__ __nv_bfloat16 g_wvhi[C_ * C_],   g_wvlo[C_ * C_];

__device__ __nv_bfloat16 g_qhi[B_ * N_ * CQK_];   // [b][n][d]
__device__ __nv_bfloat16 g_qlo[B_ * N_ * CQK_];
__device__ __nv_bfloat16 g_khi[B_ * N_ * CQK_];
__device__ __nv_bfloat16 g_klo[B_ * N_ * CQK_];
__device__ __nv_bfloat16 g_vhi[B_ * C_ * N_];     // [b][c][n]; rescaled in place
__device__ __nv_bfloat16 g_vlo[B_ * C_ * N_];

// ---------------- PTX helpers (baseline features only) ----------------------
__device__ __forceinline__ uint32_t smem_u32(const void* p) {
    uint32_t a;
    asm("{ .reg .u64 t; cvta.to.shared.u64 t, %1; cvt.u32.u64 %0, t; }" : "=r"(a) : "l"(p));
    return a;
}
__device__ __forceinline__ void mma16816(float* c, const uint32_t* a, const uint32_t* b) {
    asm volatile(
        "mma.sync.aligned.m16n8k16.row.col.f32.bf16.bf16.f32 "
        "{%0,%1,%2,%3}, {%4,%5,%6,%7}, {%8,%9}, {%0,%1,%2,%3};"
        : "+f"(c[0]), "+f"(c[1]), "+f"(c[2]), "+f"(c[3])
        : "r"(a[0]), "r"(a[1]), "r"(a[2]), "r"(a[3]), "r"(b[0]), "r"(b[1]));
}
__device__ __forceinline__ void ldm_x4(uint32_t* r, uint32_t addr) {
    asm volatile("ldmatrix.sync.aligned.m8n8.x4.shared.b16 {%0,%1,%2,%3}, [%4];"
                 : "=r"(r[0]), "=r"(r[1]), "=r"(r[2]), "=r"(r[3]) : "r"(addr));
}
__device__ __forceinline__ void cp16(uint32_t saddr, const void* g) {
    asm volatile("cp.async.cg.shared.global [%0], [%1], 16;" :: "r"(saddr), "l"(g));
}
#define CP_COMMIT() asm volatile("cp.async.commit_group;" ::: "memory")
#define CP_WAIT0()  asm volatile("cp.async.wait_group 0;" ::: "memory")
#define CP_WAIT1()  asm volatile("cp.async.wait_group 1;" ::: "memory")

__device__ __forceinline__ void split_bf16(float v, __nv_bfloat16& h, __nv_bfloat16& l) {
    h = __float2bfloat16(v);
    l = __float2bfloat16(v - __bfloat162float(h));
}

// ---------------- staging ----------------------------------------------------
// 128 rows x 128B; row = [hi: 32 bf16 | lo: 32 bf16], XOR-swizzled.
__device__ __forceinline__ void stage2(uint32_t sbase, const __nv_bfloat16* hi,
                                       const __nv_bfloat16* lo, size_t rs, int kt, int tid) {
    #pragma unroll
    for (int p = 0; p < 4; p++) {
        int idx = p * 256 + tid;
        int row = idx >> 3, c8 = idx & 7;
        const __nv_bfloat16* src = (c8 < 4) ? (hi + (size_t)row * rs + kt + c8 * 8)
                                            : (lo + (size_t)row * rs + kt + (c8 - 4) * 8);
        uint32_t sa = sbase + row * 128 + ((c8 ^ (row & 7)) << 4);
        cp16(sa, src);
    }
}
// 128 rows x 64B (bf16, K=32), row-pair swizzle; conflict-free for ldmatrix.
__device__ __forceinline__ void stage1h(uint32_t sbase, const __nv_bfloat16* src,
                                        size_t rs, int kt, int tid) {
    #pragma unroll
    for (int p = 0; p < 2; p++) {
        int idx = p * 256 + tid;
        int row = idx >> 2, c4 = idx & 3;
        uint32_t sa = sbase + row * 64 + ((c4 ^ ((row >> 1) & 3)) << 4);
        cp16(sa, src + (size_t)row * rs + kt + c4 * 8);
    }
}

// ---------------- 3-term K=32 chunk (both operands hi/lo) --------------------
__device__ __forceinline__ void mma_chunk(float acc[16][4], uint32_t Abase, uint32_t Bbase,
                                          int m_base, int n_base, int lane) {
    const int L7 = lane & 7;
    const int rowA = L7 + (lane & 8);
    const int rowB = L7 + ((lane >> 1) & 8);
    #pragma unroll
    for (int ks = 0; ks < 2; ks++) {
        const int cAh = 2 * ks + (lane >> 4);
        const int cBh = 2 * ks + ((lane >> 3) & 1);
        const uint32_t swAh = (uint32_t)((cAh ^ L7) << 4);
        const uint32_t swAl = (uint32_t)(((cAh + 4) ^ L7) << 4);
        const uint32_t swBh = (uint32_t)((cBh ^ L7) << 4);
        const uint32_t swBl = (uint32_t)(((cBh + 4) ^ L7) << 4);

        uint32_t bh[2][4], bl[2][4];
        #pragma unroll
        for (int nip = 0; nip < 2; nip++) {
            uint32_t rb = Bbase + (uint32_t)(n_base + nip * 16 + rowB) * 128;
            ldm_x4(bh[nip], rb + swBh);
            ldm_x4(bl[nip], rb + swBl);
        }
        #pragma unroll
        for (int mi = 0; mi < 4; mi++) {
            uint32_t ra = Abase + (uint32_t)(m_base + mi * 16 + rowA) * 128;
            uint32_t ah[4], al[4];
            ldm_x4(ah, ra + swAh);
            ldm_x4(al, ra + swAl);
            #pragma unroll
            for (int nip = 0; nip < 2; nip++) {
                #pragma unroll
                for (int h = 0; h < 2; h++) {
                    float* c = acc[mi * 4 + nip * 2 + h];
                    uint32_t bfh[2] = {bh[nip][2 * h], bh[nip][2 * h + 1]};
                    uint32_t bfl[2] = {bl[nip][2 * h], bl[nip][2 * h + 1]};
                    mma16816(c, ah, bfh);
                    mma16816(c, al, bfh);
                    mma16816(c, ah, bfl);
                }
            }
        }
    }
}

// ---------------- 2-term K=32 chunk (A hi/lo 128B rows, B bf16 64B rows) -----
__device__ __forceinline__ void mma_chunk_av(float acc[16][4], uint32_t Abase, uint32_t Bbase,
                                             int m_base, int n_base, int lane) {
    const int L7 = lane & 7;
    const int rowA = L7 + (lane & 8);
    const int rowB = L7 + ((lane >> 1) & 8);
    #pragma unroll
    for (int ks = 0; ks < 2; ks++) {
        const int cAh = 2 * ks + (lane >> 4);
        const int cB  = 2 * ks + ((lane >> 3) & 1);
        const uint32_t swAh = (uint32_t)((cAh ^ L7) << 4);
        const uint32_t swAl = (uint32_t)(((cAh + 4) ^ L7) << 4);

        uint32_t bh[2][4];
        #pragma unroll
        for (int nip = 0; nip < 2; nip++) {
            int row = n_base + nip * 16 + rowB;
            uint32_t rb = Bbase + (uint32_t)row * 64 + (uint32_t)(((cB ^ ((row >> 1) & 3))) << 4);
            ldm_x4(bh[nip], rb);
        }
        #pragma unroll
        for (int mi = 0; mi < 4; mi++) {
            uint32_t ra = Abase + (uint32_t)(m_base + mi * 16 + rowA) * 128;
            uint32_t ah[4], al[4];
            ldm_x4(ah, ra + swAh);
            ldm_x4(al, ra + swAl);
            #pragma unroll
            for (int nip = 0; nip < 2; nip++) {
                #pragma unroll
                for (int h = 0; h < 2; h++) {
                    float* c = acc[mi * 4 + nip * 2 + h];
                    uint32_t bf[2] = {bh[nip][2 * h], bh[nip][2 * h + 1]};
                    mma16816(c, ah, bf);
                    mma16816(c, al, bf);
                }
            }
        }
    }
}

// 3-stage pipeline, both operands hi/lo (32KB/stage)
template <int NCH>
__device__ __forceinline__ void gemm_pipe(float acc[16][4], uint32_t base,
    const __nv_bfloat16* ahi, const __nv_bfloat16* alo, size_t ars,
    const __nv_bfloat16* bhi, const __nv_bfloat16* blo, size_t brs,
    int m_base, int n_base, int tid, int lane)
{
    stage2(base, ahi, alo, ars, 0, tid);
    stage2(base + 16384, bhi, blo, brs, 0, tid);
    CP_COMMIT();
    stage2(base + 32768, ahi, alo, ars, 32, tid);
    stage2(base + 32768 + 16384, bhi, blo, brs, 32, tid);
    CP_COMMIT();
    for (int ch = 0; ch < NCH; ch++) {
        if (ch == NCH - 1) { CP_WAIT0(); } else { CP_WAIT1(); }
        __syncthreads();
        if (ch + 2 < NCH) {
            uint32_t o = (uint32_t)(((ch + 2) % 3) * 32768);
            stage2(base + o, ahi, alo, ars, (ch + 2) * 32, tid);
            stage2(base + o + 16384, bhi, blo, brs, (ch + 2) * 32, tid);
            CP_COMMIT();
        }
        uint32_t o = (uint32_t)((ch % 3) * 32768);
        mma_chunk(acc, base + o, base + o + 16384, m_base, n_base, lane);
    }
}

// ---------------- kernel 1a: x transpose + bf16 hi/lo split ------------------
__global__ __launch_bounds__(256) void xsplit(const float* __restrict__ x)
{
    __shared__ float t[32][69];
    const int b  = blockIdx.z;
    const int n0 = blockIdx.x * 64;
    const int c0 = blockIdx.y * 32;
    const float* src = x + (size_t)b * C_ * N_;
    const int tid = threadIdx.x;

    #pragma unroll
    for (int p = 0; p < 2; p++) {
        int idx = p * 256 + tid;
        int row = idx >> 4, col4 = (idx & 15) * 4;
        float4 v = *reinterpret_cast<const float4*>(&src[(size_t)(c0 + row) * N_ + n0 + col4]);
        t[row][col4] = v.x; t[row][col4 + 1] = v.y;
        t[row][col4 + 2] = v.z; t[row][col4 + 3] = v.w;
    }
    __syncthreads();

    const int nn = tid >> 2, cseg = (tid & 3) * 8;
    __align__(16) __nv_bfloat16 hi[8];
    __align__(16) __nv_bfloat16 lo[8];
    #pragma unroll
    for (int k = 0; k < 8; k++) {
        __nv_bfloat16 h, l;
        split_bf16(t[cseg + k][nn], h, l);
        hi[k] = h; lo[k] = l;
    }
    size_t o = ((size_t)b * N_ + n0 + nn) * C_ + c0 + cseg;
    *reinterpret_cast<uint4*>(&g_xThi[o]) = *reinterpret_cast<uint4*>(hi);
    *reinterpret_cast<uint4*>(&g_xTlo[o]) = *reinterpret_cast<uint4*>(lo);
}

// ---------------- kernel 1b: weight splits -----------------------------------
__global__ __launch_bounds__(256) void wsplit(const float* __restrict__ wq,
                                              const float* __restrict__ wk,
                                              const float* __restrict__ wv)
{
    int i = blockIdx.x * 256 + threadIdx.x;
    float f; __nv_bfloat16* dh; __nv_bfloat16* dl; int o;
    if (i < 32768)       { f = wq[i];          dh = g_wqhi; dl = g_wqlo; o = i; }
    else if (i < 65536)  { f = wk[i - 32768];  dh = g_wkhi; dl = g_wklo; o = i - 32768; }
    else                 { f = wv[i - 65536];  dh = g_wvhi; dl = g_wvlo; o = i - 65536; }
    __nv_bfloat16 h, l;
    split_bf16(f, h, l);
    dh[o] = h; dl[o] = l;
}

// ---------------- kernel 2a: Q/K projection GEMM -----------------------------
__global__ __launch_bounds__(256, 2) void proj_qk_mma(
    const float* __restrict__ bq, const float* __restrict__ bk)
{
    extern __shared__ char dyn[];
    const uint32_t base = smem_u32(dyn);

    const int tid = threadIdx.x;
    const int lane = tid & 31, wid = tid >> 5;
    const int m_base = (wid & 1) * 64, n_base = (wid >> 1) * 32;
    const int g = lane >> 2, q2 = (lane & 3) * 2;

    const int i0 = blockIdx.x * 128;
    const int zy = blockIdx.y;
    const int b = zy & 3;
    const bool isK = zy >= 4;
    const __nv_bfloat16* whi = isK ? g_wkhi : g_wqhi;
    const __nv_bfloat16* wlo = isK ? g_wklo : g_wqlo;
    const float* bias = isK ? bk : bq;
    __nv_bfloat16* dhi = (isK ? g_khi : g_qhi) + ((size_t)b * N_ + i0) * CQK_;
    __nv_bfloat16* dlo = (isK ? g_klo : g_qlo) + ((size_t)b * N_ + i0) * CQK_;

    float acc[16][4] = {};
    gemm_pipe<8>(acc, base,
                 g_xThi + ((size_t)b * N_ + i0) * C_,
                 g_xTlo + ((size_t)b * N_ + i0) * C_, C_,
                 whi, wlo, C_, m_base, n_base, tid, lane);

    #pragma unroll
    for (int mi = 0; mi < 4; mi++) {
        #pragma unroll
        for (int ni = 0; ni < 4; ni++) {
            const float* c = acc[mi * 4 + ni];
            const int r = m_base + mi * 16 + g;
            const int col = n_base + ni * 8 + q2;
            float2 bb = *reinterpret_cast<const float2*>(&bias[col]);
            __nv_bfloat16 h0, l0, h1, l1;
            split_bf16(c[0] + bb.x, h0, l0);
            split_bf16(c[1] + bb.y, h1, l1);
            __nv_bfloat162 hp; hp.x = h0; hp.y = h1;
            __nv_bfloat162 lp; lp.x = l0; lp.y = l1;
            *reinterpret_cast<__nv_bfloat162*>(&dhi[(size_t)r * CQK_ + col]) = hp;
            *reinterpret_cast<__nv_bfloat162*>(&dlo[(size_t)r * CQK_ + col]) = lp;
            split_bf16(c[2] + bb.x, h0, l0);
            split_bf16(c[3] + bb.y, h1, l1);
            hp.x = h0; hp.y = h1; lp.x = l0; lp.y = l1;
            *reinterpret_cast<__nv_bfloat162*>(&dhi[(size_t)(r + 8) * CQK_ + col]) = hp;
            *reinterpret_cast<__nv_bfloat162*>(&dlo[(size_t)(r + 8) * CQK_ + col]) = lp;
        }
    }
}

// ---------------- kernel 2b: V projection GEMM -------------------------------
__global__ __launch_bounds__(256, 2) void proj_v_mma(const float* __restrict__ bv)
{
    extern __shared__ char dyn[];
    const uint32_t base = smem_u32(dyn);

    const int tid = threadIdx.x;
    const int lane = tid & 31, wid = tid >> 5;
    const int m_base = (wid & 1) * 64, n_base = (wid >> 1) * 32;
    const int g = lane >> 2, q2 = (lane & 3) * 2;

    const int j0 = blockIdx.x * 128;
    const int c0 = blockIdx.y * 128;
    const int b  = blockIdx.z;

    float acc[16][4] = {};
    gemm_pipe<8>(acc, base,
                 g_wvhi + (size_t)c0 * C_, g_wvlo + (size_t)c0 * C_, C_,
                 g_xThi + ((size_t)b * N_ + j0) * C_,
                 g_xTlo + ((size_t)b * N_ + j0) * C_, C_,
                 m_base, n_base, tid, lane);

    #pragma unroll
    for (int mi = 0; mi < 4; mi++) {
        const int cc = c0 + m_base + mi * 16 + g;
        const float bv0 = bv[cc], bv1 = bv[cc + 8];
        #pragma unroll
        for (int ni = 0; ni < 4; ni++) {
            const float* c = acc[mi * 4 + ni];
            const int col = j0 + n_base + ni * 8 + q2;
            __nv_bfloat16 h0, l0, h1, l1;
            split_bf16(c[0] + bv0, h0, l0);
            split_bf16(c[1] + bv0, h1, l1);
            __nv_bfloat162 hp; hp.x = h0; hp.y = h1;
            __nv_bfloat162 lp; lp.x = l0; lp.y = l1;
            size_t o0 = ((size_t)b * C_ + cc) * N_ + col;
            *reinterpret_cast<__nv_bfloat162*>(&g_vhi[o0]) = hp;
            *reinterpret_cast<__nv_bfloat162*>(&g_vlo[o0]) = lp;
            split_bf16(c[2] + bv1, h0, l0);
            split_bf16(c[3] + bv1, h1, l1);
            hp.x = h0; hp.y = h1; lp.x = l0; lp.y = l1;
            size_t o1 = ((size_t)b * C_ + cc + 8) * N_ + col;
            *reinterpret_cast<__nv_bfloat162*>(&g_vhi[o1]) = hp;
            *reinterpret_cast<__nv_bfloat162*>(&g_vlo[o1]) = lp;
        }
    }
}

// ---------------- kernel 3: scores; writes exp(S^T) bf16 + row sumexp --------
__global__ __launch_bounds__(256, 2) void scores_mma()
{
    extern __shared__ char dyn[];
    const uint32_t base = smem_u32(dyn);

    const int tid = threadIdx.x;
    const int lane = tid & 31, wid = tid >> 5;
    const int m_base = (wid & 1) * 64, n_base = (wid >> 1) * 32;
    const int g = lane >> 2, q2 = (lane & 3) * 2;
    const int wn = wid >> 1;

    const int j0 = blockIdx.x * 128, i0 = blockIdx.y * 128, b = blockIdx.z;

    float acc[16][4] = {};
    gemm_pipe<4>(acc, base,
                 g_qhi + ((size_t)b * N_ + i0) * CQK_,
                 g_qlo + ((size_t)b * N_ + i0) * CQK_, CQK_,
                 g_khi + ((size_t)b * N_ + j0) * CQK_,
                 g_klo + ((size_t)b * N_ + j0) * CQK_, CQK_,
                 m_base, n_base, tid, lane);

    // exp in place (S bounded; no max subtraction needed)
    #pragma unroll
    for (int u = 0; u < 16; u++)
        #pragma unroll
        for (int v = 0; v < 4; v++)
            acc[u][v] = __expf(acc[u][v]);

    // ---- per-row sumexp over this tile ----
    __syncthreads();
    float* red2 = reinterpret_cast<float*>(dyn);   // [128][4]
    #pragma unroll
    for (int mi = 0; mi < 4; mi++) {
        #pragma unroll
        for (int h = 0; h < 2; h++) {
            const int row = m_base + mi * 16 + h * 8 + g;
            float s = 0.f;
            #pragma unroll
            for (int ni = 0; ni < 4; ni++)
                s += acc[mi * 4 + ni][2 * h] + acc[mi * 4 + ni][2 * h + 1];
            s += __shfl_xor_sync(0xffffffffu, s, 1);
            s += __shfl_xor_sync(0xffffffffu, s, 2);
            if ((lane & 3) == 0)
                red2[row * 4 + wn] = s;
        }
    }
    __syncthreads();
    if (tid < 128) {
        float S = red2[tid * 4] + red2[tid * 4 + 1] + red2[tid * 4 + 2] + red2[tid * 4 + 3];
        g_ps[((size_t)b * 32 + blockIdx.x) * N_ + i0 + tid] = S;
    }
    __syncthreads();

    // ---- transpose exp(acc) -> ts[j][i] (pad 132), coalesced bf16 write -----
    float* ts = reinterpret_cast<float*>(dyn);     // [128][132]
    #pragma unroll
    for (int mi = 0; mi < 4; mi++) {
        #pragma unroll
        for (int ni = 0; ni < 4; ni++) {
            const float* c = acc[mi * 4 + ni];
            const int r = m_base + mi * 16 + g;
            const int col = n_base + ni * 8 + q2;
            ts[col * 132 + r]           = c[0];
            ts[(col + 1) * 132 + r]     = c[1];
            ts[col * 132 + r + 8]       = c[2];
            ts[(col + 1) * 132 + r + 8] = c[3];
        }
    }
    __syncthreads();
    {
        const int jl = tid >> 5;
        const int l4 = lane * 4;
        __nv_bfloat16* dstb = g_PT + ((size_t)b * N_ + j0) * N_ + i0;
        #pragma unroll
        for (int it = 0; it < 16; it++) {
            const int j = jl + it * 8;
            float4 v = *reinterpret_cast<const float4*>(&ts[j * 132 + l4]);
            __nv_bfloat162 p0 = __floats2bfloat162_rn(v.x, v.y);
            __nv_bfloat162 p1 = __floats2bfloat162_rn(v.z, v.w);
            uint2 pk;
            pk.x = *reinterpret_cast<uint32_t*>(&p0);
            pk.y = *reinterpret_cast<uint32_t*>(&p1);
            *reinterpret_cast<uint2*>(&dstb[(size_t)j * N_ + l4]) = pk;
        }
    }
}

// ---------------- kernel 4: combine partials -> inverse row sums -------------
__global__ __launch_bounds__(256) void inv_combine()
{
    const int idx = blockIdx.x * 256 + threadIdx.x;   // b*N + i
    const int b = idx >> 12, i = idx & 4095;
    const float* ps = g_ps + (size_t)b * 32 * N_ + i;
    float S = 0.f;
    #pragma unroll
    for (int t = 0; t < 32; t++)
        S += ps[(size_t)t * N_];
    g_Linv[idx] = 1.0f / S;
}

// ---------------- kernel 5: rescale V by inv row-sum (in place) --------------
__global__ __launch_bounds__(256) void vscale()
{
    const size_t e8 = ((size_t)blockIdx.x * 256 + threadIdx.x) * 8;  // elem idx
    const int b = (int)(e8 >> 20);              // C_*N_ = 1<<20 per batch
    const int n = (int)(e8 & (N_ - 1));
    uint4 hv = *reinterpret_cast<const uint4*>(&g_vhi[e8]);
    uint4 lv = *reinterpret_cast<const uint4*>(&g_vlo[e8]);
    const float* inv = g_Linv + b * N_ + n;
    __nv_bfloat16* hp = reinterpret_cast<__nv_bfloat16*>(&hv);
    __nv_bfloat16* lp = reinterpret_cast<__nv_bfloat16*>(&lv);
    #pragma unroll
    for (int k = 0; k < 8; k++) {
        float v = (__bfloat162float(hp[k]) + __bfloat162float(lp[k])) * inv[k];
        __nv_bfloat16 h, l;
        split_bf16(v, h, l);
        hp[k] = h; lp[k] = l;
    }
    *reinterpret_cast<uint4*>(&g_vhi[e8]) = hv;
    *reinterpret_cast<uint4*>(&g_vlo[e8]) = lv;
}

// ---------------- kernel 6: AV pure GEMM (2-term) + epilogue -----------------
// smem: A 3x16384 [0,49152) | B 3x8192 [49152,73728)
#define AV_A(s)  (uint32_t)((s) * 16384)
#define AV_B(s)  (uint32_t)(49152 + (s) * 8192)
#define AV_DYN   73728

__global__ __launch_bounds__(256, 2) void av_mma(
    const float* __restrict__ x, const float* __restrict__ gamma,
    float* __restrict__ out)
{
    extern __shared__ char dyn[];
    const uint32_t base = smem_u32(dyn);

    const int tid = threadIdx.x;
    const int lane = tid & 31, wid = tid >> 5;
    const int m_base = (wid & 1) * 64, n_base = (wid >> 1) * 32;
    const int g = lane >> 2, q2 = (lane & 3) * 2;

    const int j0 = blockIdx.x * 128, c0 = blockIdx.y * 128, b = blockIdx.z;

    const __nv_bfloat16* vhi = g_vhi + ((size_t)b * C_ + c0) * N_;
    const __nv_bfloat16* vlo = g_vlo + ((size_t)b * C_ + c0) * N_;
    const __nv_bfloat16* pt  = g_PT + ((size_t)b * N_ + j0) * N_;

    stage2(base + AV_A(0), vhi, vlo, N_, 0, tid);
    stage1h(base + AV_B(0), pt, N_, 0, tid);
    CP_COMMIT();
    stage2(base + AV_A(1), vhi, vlo, N_, 32, tid);
    stage1h(base + AV_B(1), pt, N_, 32, tid);
    CP_COMMIT();

    float acc[16][4] = {};
    for (int ch = 0; ch < 128; ch++) {
        if (ch == 127) { CP_WAIT0(); } else { CP_WAIT1(); }
        __syncthreads();
        if (ch + 2 < 128) {
            const int s2 = (ch + 2) % 3;
            stage2(base + AV_A(s2), vhi, vlo, N_, (ch + 2) * 32, tid);
            stage1h(base + AV_B(s2), pt, N_, (ch + 2) * 32, tid);
            CP_COMMIT();
        }
        const int s = ch % 3;
        mma_chunk_av(acc, base + AV_A(s), base + AV_B(s), m_base, n_base, lane);
    }

    const float gm = gamma[0];
    #pragma unroll
    for (int mi = 0; mi < 4; mi++) {
        #pragma unroll
        for (int ni = 0; ni < 4; ni++) {
            const float* c = acc[mi * 4 + ni];
            const int cc = c0 + m_base + mi * 16 + g;
            const int col = j0 + n_base + ni * 8 + q2;
            size_t o0 = ((size_t)b * C_ + cc) * N_ + col;
            size_t o1 = ((size_t)b * C_ + cc + 8) * N_ + col;
            float2 x0 = *reinterpret_cast<const float2*>(&x[o0]);
            float2 x1 = *reinterpret_cast<const float2*>(&x[o1]);
            *reinterpret_cast<float2*>(&out[o0]) =
                make_float2(gm * c[0] + x0.x, gm * c[1] + x0.y);
            *reinterpret_cast<float2*>(&out[o1]) =
                make_float2(gm * c[2] + x1.x, gm * c[3] + x1.y);
        }
    }
}

// ---------------- launch -----------------------------------------------------
extern "C" void kernel_launch(void* const* d_in, const int* in_sizes, int n_in,
                              void* d_out, int out_size)
{
    const float* x     = (const float*)d_in[0];
    const float* wq    = (const float*)d_in[1];
    const float* bq    = (const float*)d_in[2];
    const float* wk    = (const float*)d_in[3];
    const float* bk    = (const float*)d_in[4];
    const float* wv    = (const float*)d_in[5];
    const float* bv    = (const float*)d_in[6];
    const float* gamma = (const float*)d_in[7];
    float* out = (float*)d_out;

    const int DYN3 = 98304;   // 3 stages x 32KB
    cudaFuncSetAttribute(proj_qk_mma, cudaFuncAttributeMaxDynamicSharedMemorySize, DYN3);
    cudaFuncSetAttribute(proj_v_mma,  cudaFuncAttributeMaxDynamicSharedMemorySize, DYN3);
    cudaFuncSetAttribute(scores_mma,  cudaFuncAttributeMaxDynamicSharedMemorySize, DYN3);
    cudaFuncSetAttribute(av_mma,      cudaFuncAttributeMaxDynamicSharedMemorySize, AV_DYN);

    xsplit        <<<dim3(N_ / 64, C_ / 32, B_), 256>>>(x);
    wsplit        <<<dim3(512), 256>>>(wq, wk, wv);
    proj_qk_mma   <<<dim3(N_ / 128, B_ * 2), 256, DYN3>>>(bq, bk);
    proj_v_mma    <<<dim3(N_ / 128, C_ / 128, B_), 256, DYN3>>>(bv);
    scores_mma    <<<dim3(N_ / 128, N_ / 128, B_), 256, DYN3>>>();
    inv_combine   <<<dim3(B_ * N_ / 256), 256>>>();
    vscale        <<<dim3((B_ * C_ * N_ / 8) / 256), 256>>>();
    av_mma        <<<dim3(N_ / 128, C_ / 128, B_), 256, AV_DYN>>>(x, gamma, out);
}

// round 14
// speedup vs baseline: 7.9749x; 1.8910x over previous
#include <cuda_runtime.h>
#include <cuda_bf16.h>
#include <cuda_fp16.h>
#include <math.h>
#include <stdint.h>

#define B_   4
#define C_   256
#define CQK_ 128
#define N_   4096

// ---------------- scratch (device globals; no allocations allowed) ----------
__device__ __nv_bfloat16 g_PT[(size_t)B_ * N_ * N_];  // 128 MB [b][j][i] = exp(S^T)
__device__ float g_Linv[B_ * N_];                     // 1 / sum_j exp(S[i][j])
__device__ float g_ps[B_ * 32 * N_];                  // per-tile row sumexp

__device__ __half g_xT[B_ * N_ * C_];     // [b][n][c] fp16
__device__ __half g_wq[CQK_ * C_];
__device__ __half g_wk[CQK_ * C_];
__device__ __half g_wv[C_ * C_];
__device__ __half g_q[B_ * N_ * CQK_];    // [b][n][d] fp16
__device__ __half g_k[B_ * N_ * CQK_];
__device__ __nv_bfloat16 g_v[B_ * C_ * N_];  // [b][c][n] bf16, pre-scaled by Linv

// ---------------- PTX helpers (baseline features only) ----------------------
__device__ __forceinline__ uint32_t smem_u32(const void* p) {
    uint32_t a;
    asm("{ .reg .u64 t; cvta.to.shared.u64 t, %1; cvt.u32.u64 %0, t; }" : "=r"(a) : "l"(p));
    return a;
}
__device__ __forceinline__ void mma_bf16(float* c, const uint32_t* a, const uint32_t* b) {
    asm volatile(
        "mma.sync.aligned.m16n8k16.row.col.f32.bf16.bf16.f32 "
        "{%0,%1,%2,%3}, {%4,%5,%6,%7}, {%8,%9}, {%0,%1,%2,%3};"
        : "+f"(c[0]), "+f"(c[1]), "+f"(c[2]), "+f"(c[3])
        : "r"(a[0]), "r"(a[1]), "r"(a[2]), "r"(a[3]), "r"(b[0]), "r"(b[1]));
}
__device__ __forceinline__ void mma_f16(float* c, const uint32_t* a, const uint32_t* b) {
    asm volatile(
        "mma.sync.aligned.m16n8k16.row.col.f32.f16.f16.f32 "
        "{%0,%1,%2,%3}, {%4,%5,%6,%7}, {%8,%9}, {%0,%1,%2,%3};"
        : "+f"(c[0]), "+f"(c[1]), "+f"(c[2]), "+f"(c[3])
        : "r"(a[0]), "r"(a[1]), "r"(a[2]), "r"(a[3]), "r"(b[0]), "r"(b[1]));
}
__device__ __forceinline__ void ldm_x4(uint32_t* r, uint32_t addr) {
    asm volatile("ldmatrix.sync.aligned.m8n8.x4.shared.b16 {%0,%1,%2,%3}, [%4];"
                 : "=r"(r[0]), "=r"(r[1]), "=r"(r[2]), "=r"(r[3]) : "r"(addr));
}
__device__ __forceinline__ void cp16(uint32_t saddr, const void* g) {
    asm volatile("cp.async.cg.shared.global [%0], [%1], 16;" :: "r"(saddr), "l"(g));
}
#define CP_COMMIT() asm volatile("cp.async.commit_group;" ::: "memory")
#define CP_WAIT0()  asm volatile("cp.async.wait_group 0;" ::: "memory")
#define CP_WAIT1()  asm volatile("cp.async.wait_group 1;" ::: "memory")

// ---------------- staging: 128 rows x 64B (K=32 of 2-byte elems) -------------
// row-pair swizzle; conflict-free for cp.async stores and ldmatrix reads
template <typename T>
__device__ __forceinline__ void stage1(uint32_t sbase, const T* src, size_t rs,
                                       int kt, int tid) {
    #pragma unroll
    for (int p = 0; p < 2; p++) {
        int idx = p * 256 + tid;
        int row = idx >> 2, c4 = idx & 3;
        uint32_t sa = sbase + row * 64 + ((c4 ^ ((row >> 1) & 3)) << 4);
        cp16(sa, src + (size_t)row * rs + kt + c4 * 8);
    }
}

// ---------------- single-term K=32 chunk (A,B both 64B rows) -----------------
template <bool HALF>
__device__ __forceinline__ void mma_chunk1(float acc[16][4], uint32_t Abase, uint32_t Bbase,
                                           int m_base, int n_base, int lane) {
    const int L7 = lane & 7;
    const int rowA = L7 + (lane & 8);
    const int rowB = L7 + ((lane >> 1) & 8);
    #pragma unroll
    for (int ks = 0; ks < 2; ks++) {
        const int segA = 2 * ks + (lane >> 4);
        const int segB = 2 * ks + ((lane >> 3) & 1);

        uint32_t bh[2][4];
        #pragma unroll
        for (int nip = 0; nip < 2; nip++) {
            int row = n_base + nip * 16 + rowB;
            uint32_t rb = Bbase + (uint32_t)row * 64 + (uint32_t)((segB ^ ((row >> 1) & 3)) << 4);
            ldm_x4(bh[nip], rb);
        }
        #pragma unroll
        for (int mi = 0; mi < 4; mi++) {
            int rowa = m_base + mi * 16 + rowA;
            uint32_t ra = Abase + (uint32_t)rowa * 64 + (uint32_t)((segA ^ ((rowa >> 1) & 3)) << 4);
            uint32_t a[4];
            ldm_x4(a, ra);
            #pragma unroll
            for (int nip = 0; nip < 2; nip++) {
                #pragma unroll
                for (int h = 0; h < 2; h++) {
                    float* c = acc[mi * 4 + nip * 2 + h];
                    uint32_t bf[2] = {bh[nip][2 * h], bh[nip][2 * h + 1]};
                    if (HALF) mma_f16(c, a, bf);
                    else      mma_bf16(c, a, bf);
                }
            }
        }
    }
}

// 3-stage single-term pipeline (16KB/stage: A 8KB + B 8KB)
template <int NCH, bool HALF, typename T>
__device__ __forceinline__ void gemm_pipe1(float acc[16][4], uint32_t base,
    const T* A, size_t ars, const T* Bp, size_t brs,
    int m_base, int n_base, int tid, int lane)
{
    stage1(base, A, ars, 0, tid);
    stage1(base + 8192, Bp, brs, 0, tid);
    CP_COMMIT();
    stage1(base + 16384, A, ars, 32, tid);
    stage1(base + 16384 + 8192, Bp, brs, 32, tid);
    CP_COMMIT();
    for (int ch = 0; ch < NCH; ch++) {
        if (ch == NCH - 1) { CP_WAIT0(); } else { CP_WAIT1(); }
        __syncthreads();
        if (ch + 2 < NCH) {
            uint32_t o = (uint32_t)(((ch + 2) % 3) * 16384);
            stage1(base + o, A, ars, (ch + 2) * 32, tid);
            stage1(base + o + 8192, Bp, brs, (ch + 2) * 32, tid);
            CP_COMMIT();
        }
        uint32_t o = (uint32_t)((ch % 3) * 16384);
        mma_chunk1<HALF>(acc, base + o, base + o + 8192, m_base, n_base, lane);
    }
}

// ---------------- kernel 1a: x transpose -> fp16 xT --------------------------
__global__ __launch_bounds__(256) void xsplit(const float* __restrict__ x)
{
    __shared__ float t[32][69];
    const int b  = blockIdx.z;
    const int n0 = blockIdx.x * 64;
    const int c0 = blockIdx.y * 32;
    const float* src = x + (size_t)b * C_ * N_;
    const int tid = threadIdx.x;

    #pragma unroll
    for (int p = 0; p < 2; p++) {
        int idx = p * 256 + tid;
        int row = idx >> 4, col4 = (idx & 15) * 4;
        float4 v = *reinterpret_cast<const float4*>(&src[(size_t)(c0 + row) * N_ + n0 + col4]);
        t[row][col4] = v.x; t[row][col4 + 1] = v.y;
        t[row][col4 + 2] = v.z; t[row][col4 + 3] = v.w;
    }
    __syncthreads();

    const int nn = tid >> 2, cseg = (tid & 3) * 8;
    __align__(16) __half h[8];
    #pragma unroll
    for (int k = 0; k < 8; k++)
        h[k] = __float2half(t[cseg + k][nn]);
    size_t o = ((size_t)b * N_ + n0 + nn) * C_ + c0 + cseg;
    *reinterpret_cast<uint4*>(&g_xT[o]) = *reinterpret_cast<uint4*>(h);
}

// ---------------- kernel 1b: weight -> fp16 ----------------------------------
__global__ __launch_bounds__(256) void wsplit(const float* __restrict__ wq,
                                              const float* __restrict__ wk,
                                              const float* __restrict__ wv)
{
    int i = blockIdx.x * 256 + threadIdx.x;
    if (i < 32768)       g_wq[i]         = __float2half(wq[i]);
    else if (i < 65536)  g_wk[i - 32768] = __float2half(wk[i - 32768]);
    else                 g_wv[i - 65536] = __float2half(wv[i - 65536]);
}

// ---------------- kernel 2a: Q/K projection (single fp16 GEMM) ---------------
__global__ __launch_bounds__(256, 2) void proj_qk_mma(
    const float* __restrict__ bq, const float* __restrict__ bk)
{
    extern __shared__ char dyn[];
    const uint32_t base = smem_u32(dyn);

    const int tid = threadIdx.x;
    const int lane = tid & 31, wid = tid >> 5;
    const int m_base = (wid & 1) * 64, n_base = (wid >> 1) * 32;
    const int g = lane >> 2, q2 = (lane & 3) * 2;

    const int i0 = blockIdx.x * 128;
    const int zy = blockIdx.y;
    const int b = zy & 3;
    const bool isK = zy >= 4;
    const __half* W = isK ? g_wk : g_wq;
    const float* bias = isK ? bk : bq;
    __half* dst = (isK ? g_k : g_q) + ((size_t)b * N_ + i0) * CQK_;

    float acc[16][4] = {};
    gemm_pipe1<8, true>(acc, base,
                        g_xT + ((size_t)b * N_ + i0) * C_, (size_t)C_,
                        W, (size_t)C_, m_base, n_base, tid, lane);

    #pragma unroll
    for (int mi = 0; mi < 4; mi++) {
        #pragma unroll
        for (int ni = 0; ni < 4; ni++) {
            const float* c = acc[mi * 4 + ni];
            const int r = m_base + mi * 16 + g;
            const int col = n_base + ni * 8 + q2;
            float2 bb = *reinterpret_cast<const float2*>(&bias[col]);
            __half2 p0 = __floats2half2_rn(c[0] + bb.x, c[1] + bb.y);
            __half2 p1 = __floats2half2_rn(c[2] + bb.x, c[3] + bb.y);
            *reinterpret_cast<__half2*>(&dst[(size_t)r * CQK_ + col])       = p0;
            *reinterpret_cast<__half2*>(&dst[(size_t)(r + 8) * CQK_ + col]) = p1;
        }
    }
}

// ---------------- kernel 3: scores (single fp16 GEMM) -> exp(S^T) bf16 -------
__global__ __launch_bounds__(256, 2) void scores_mma()
{
    extern __shared__ char dyn[];
    const uint32_t base = smem_u32(dyn);

    const int tid = threadIdx.x;
    const int lane = tid & 31, wid = tid >> 5;
    const int m_base = (wid & 1) * 64, n_base = (wid >> 1) * 32;
    const int g = lane >> 2, q2 = (lane & 3) * 2;
    const int wn = wid >> 1;

    const int j0 = blockIdx.x * 128, i0 = blockIdx.y * 128, b = blockIdx.z;

    float acc[16][4] = {};
    gemm_pipe1<4, true>(acc, base,
                        g_q + ((size_t)b * N_ + i0) * CQK_, (size_t)CQK_,
                        g_k + ((size_t)b * N_ + j0) * CQK_, (size_t)CQK_,
                        m_base, n_base, tid, lane);

    // exp in place (S bounded; no max subtraction needed)
    #pragma unroll
    for (int u = 0; u < 16; u++)
        #pragma unroll
        for (int v = 0; v < 4; v++)
            acc[u][v] = __expf(acc[u][v]);

    // ---- per-row sumexp partials ----
    __syncthreads();
    float* red2 = reinterpret_cast<float*>(dyn);   // [128][4]
    #pragma unroll
    for (int mi = 0; mi < 4; mi++) {
        #pragma unroll
        for (int h = 0; h < 2; h++) {
            const int row = m_base + mi * 16 + h * 8 + g;
            float s = 0.f;
            #pragma unroll
            for (int ni = 0; ni < 4; ni++)
                s += acc[mi * 4 + ni][2 * h] + acc[mi * 4 + ni][2 * h + 1];
            s += __shfl_xor_sync(0xffffffffu, s, 1);
            s += __shfl_xor_sync(0xffffffffu, s, 2);
            if ((lane & 3) == 0)
                red2[row * 4 + wn] = s;
        }
    }
    __syncthreads();
    if (tid < 128) {
        float S = red2[tid * 4] + red2[tid * 4 + 1] + red2[tid * 4 + 2] + red2[tid * 4 + 3];
        g_ps[((size_t)b * 32 + blockIdx.x) * N_ + i0 + tid] = S;
    }
    __syncthreads();

    // ---- transpose exp(acc) -> ts[j][i] (pad 132), coalesced bf16 write -----
    float* ts = reinterpret_cast<float*>(dyn);     // [128][132]
    #pragma unroll
    for (int mi = 0; mi < 4; mi++) {
        #pragma unroll
        for (int ni = 0; ni < 4; ni++) {
            const float* c = acc[mi * 4 + ni];
            const int r = m_base + mi * 16 + g;
            const int col = n_base + ni * 8 + q2;
            ts[col * 132 + r]           = c[0];
            ts[(col + 1) * 132 + r]     = c[1];
            ts[col * 132 + r + 8]       = c[2];
            ts[(col + 1) * 132 + r + 8] = c[3];
        }
    }
    __syncthreads();
    {
        const int jl = tid >> 5;
        const int l4 = lane * 4;
        __nv_bfloat16* dstb = g_PT + ((size_t)b * N_ + j0) * N_ + i0;
        #pragma unroll
        for (int it = 0; it < 16; it++) {
            const int j = jl + it * 8;
            float4 v = *reinterpret_cast<const float4*>(&ts[j * 132 + l4]);
            __nv_bfloat162 p0 = __floats2bfloat162_rn(v.x, v.y);
            __nv_bfloat162 p1 = __floats2bfloat162_rn(v.z, v.w);
            uint2 pk;
            pk.x = *reinterpret_cast<uint32_t*>(&p0);
            pk.y = *reinterpret_cast<uint32_t*>(&p1);
            *reinterpret_cast<uint2*>(&dstb[(size_t)j * N_ + l4]) = pk;
        }
    }
}

// ---------------- kernel 4: combine partials -> inverse row sums -------------
__global__ __launch_bounds__(256) void inv_combine()
{
    const int idx = blockIdx.x * 256 + threadIdx.x;   // b*N + i
    const int b = idx >> 12, i = idx & 4095;
    const float* ps = g_ps + (size_t)b * 32 * N_ + i;
    float S = 0.f;
    #pragma unroll
    for (int t = 0; t < 32; t++)
        S += ps[(size_t)t * N_];
    g_Linv[idx] = 1.0f / S;
}

// ---------------- kernel 5: V projection (single fp16 GEMM), Linv folded -----
// V[c][n] = (Wv.xT + bv) * Linv[n], stored bf16 (range: Linv can be ~1e-19)
__global__ __launch_bounds__(256, 2) void proj_v_mma(const float* __restrict__ bv)
{
    extern __shared__ char dyn[];
    const uint32_t base = smem_u32(dyn);

    const int tid = threadIdx.x;
    const int lane = tid & 31, wid = tid >> 5;
    const int m_base = (wid & 1) * 64, n_base = (wid >> 1) * 32;
    const int g = lane >> 2, q2 = (lane & 3) * 2;

    const int j0 = blockIdx.x * 128;
    const int c0 = blockIdx.y * 128;
    const int b  = blockIdx.z;

    float acc[16][4] = {};
    gemm_pipe1<8, true>(acc, base,
                        g_wv + (size_t)c0 * C_, (size_t)C_,
                        g_xT + ((size_t)b * N_ + j0) * C_, (size_t)C_,
                        m_base, n_base, tid, lane);

    const float* invb = g_Linv + b * N_ + j0;
    #pragma unroll
    for (int mi = 0; mi < 4; mi++) {
        const int cc = c0 + m_base + mi * 16 + g;
        const float bv0 = bv[cc], bv1 = bv[cc + 8];
        #pragma unroll
        for (int ni = 0; ni < 4; ni++) {
            const float* c = acc[mi * 4 + ni];
            const int col = n_base + ni * 8 + q2;
            float2 iv = *reinterpret_cast<const float2*>(&invb[col]);
            __nv_bfloat162 p0 = __floats2bfloat162_rn((c[0] + bv0) * iv.x, (c[1] + bv0) * iv.y);
            __nv_bfloat162 p1 = __floats2bfloat162_rn((c[2] + bv1) * iv.x, (c[3] + bv1) * iv.y);
            size_t o0 = ((size_t)b * C_ + cc) * N_ + j0 + col;
            size_t o1 = ((size_t)b * C_ + cc + 8) * N_ + j0 + col;
            *reinterpret_cast<__nv_bfloat162*>(&g_v[o0]) = p0;
            *reinterpret_cast<__nv_bfloat162*>(&g_v[o1]) = p1;
        }
    }
}

// ---------------- kernel 6: AV (single bf16 GEMM) + epilogue -----------------
__global__ __launch_bounds__(256, 2) void av_mma(
    const float* __restrict__ x, const float* __restrict__ gamma,
    float* __restrict__ out)
{
    extern __shared__ char dyn[];
    const uint32_t base = smem_u32(dyn);

    const int tid = threadIdx.x;
    const int lane = tid & 31, wid = tid >> 5;
    const int m_base = (wid & 1) * 64, n_base = (wid >> 1) * 32;
    const int g = lane >> 2, q2 = (lane & 3) * 2;

    const int j0 = blockIdx.x * 128, c0 = blockIdx.y * 128, b = blockIdx.z;

    float acc[16][4] = {};
    gemm_pipe1<128, false>(acc, base,
                           g_v + ((size_t)b * C_ + c0) * N_, (size_t)N_,
                           g_PT + ((size_t)b * N_ + j0) * N_, (size_t)N_,
                           m_base, n_base, tid, lane);

    const float gm = gamma[0];
    #pragma unroll
    for (int mi = 0; mi < 4; mi++) {
        #pragma unroll
        for (int ni = 0; ni < 4; ni++) {
            const float* c = acc[mi * 4 + ni];
            const int cc = c0 + m_base + mi * 16 + g;
            const int col = j0 + n_base + ni * 8 + q2;
            size_t o0 = ((size_t)b * C_ + cc) * N_ + col;
            size_t o1 = ((size_t)b * C_ + cc + 8) * N_ + col;
            float2 x0 = *reinterpret_cast<const float2*>(&x[o0]);
            float2 x1 = *reinterpret_cast<const float2*>(&x[o1]);
            *reinterpret_cast<float2*>(&out[o0]) =
                make_float2(gm * c[0] + x0.x, gm * c[1] + x0.y);
            *reinterpret_cast<float2*>(&out[o1]) =
                make_float2(gm * c[2] + x1.x, gm * c[3] + x1.y);
        }
    }
}

// ---------------- launch -----------------------------------------------------
extern "C" void kernel_launch(void* const* d_in, const int* in_sizes, int n_in,
                              void* d_out, int out_size)
{
    const float* x     = (const float*)d_in[0];
    const float* wq    = (const float*)d_in[1];
    const float* bq    = (const float*)d_in[2];
    const float* wk    = (const float*)d_in[3];
    const float* bk    = (const float*)d_in[4];
    const float* wv    = (const float*)d_in[5];
    const float* bv    = (const float*)d_in[6];
    const float* gamma = (const float*)d_in[7];
    float* out = (float*)d_out;

    const int DYN1 = 49152;   // 3 stages x 16KB (single-term)
    const int DYNS = 67584;   // scores: max(pipeline 49152, ts transpose 128*132*4)
    cudaFuncSetAttribute(proj_qk_mma, cudaFuncAttributeMaxDynamicSharedMemorySize, DYN1);
    cudaFuncSetAttribute(proj_v_mma,  cudaFuncAttributeMaxDynamicSharedMemorySize, DYN1);
    cudaFuncSetAttribute(scores_mma,  cudaFuncAttributeMaxDynamicSharedMemorySize, DYNS);
    cudaFuncSetAttribute(av_mma,      cudaFuncAttributeMaxDynamicSharedMemorySize, DYN1);

    xsplit        <<<dim3(N_ / 64, C_ / 32, B_), 256>>>(x);
    wsplit        <<<dim3(512), 256>>>(wq, wk, wv);
    proj_qk_mma   <<<dim3(N_ / 128, B_ * 2), 256, DYN1>>>(bq, bk);
    scores_mma    <<<dim3(N_ / 128, N_ / 128, B_), 256, DYNS>>>();
    inv_combine   <<<dim3(B_ * N_ / 256), 256>>>();
    proj_v_mma    <<<dim3(N_ / 128, C_ / 128, B_), 256, DYN1>>>(bv);
    av_mma        <<<dim3(N_ / 128, C_ / 128, B_), 256, DYN1>>>(x, gamma, out);
}

// round 16
// speedup vs baseline: 8.7382x; 1.0957x over previous
#include <cuda_runtime.h>
#include <cuda_bf16.h>
#include <cuda_fp16.h>
#include <math.h>
#include <stdint.h>

#define B_   4
#define C_   256
#define CQK_ 128
#define N_   4096

// ---------------- scratch (device globals; no allocations allowed) ----------
__device__ __nv_bfloat16 g_PT[(size_t)B_ * N_ * N_];  // 128 MB [b][j][i] = exp(S^T)
__device__ float g_Linv[B_ * N_];                     // 1 / sum_j exp(S[i][j])
__device__ float g_ps[B_ * 32 * N_];                  // per-tile row sumexp

__device__ __half g_xT[B_ * N_ * C_];     // [b][n][c] fp16
__device__ __half g_wq[CQK_ * C_];
__device__ __half g_wk[CQK_ * C_];
__device__ __half g_wv[C_ * C_];
__device__ __half g_q[B_ * N_ * CQK_];    // [b][n][d] fp16
__device__ __half g_k[B_ * N_ * CQK_];
__device__ __nv_bfloat16 g_v[B_ * C_ * N_];  // [b][c][n] bf16, pre-scaled by Linv

// ---------------- PTX helpers (baseline features only) ----------------------
__device__ __forceinline__ uint32_t smem_u32(const void* p) {
    uint32_t a;
    asm("{ .reg .u64 t; cvta.to.shared.u64 t, %1; cvt.u32.u64 %0, t; }" : "=r"(a) : "l"(p));
    return a;
}
__device__ __forceinline__ void mma_bf16(float* c, const uint32_t* a, const uint32_t* b) {
    asm volatile(
        "mma.sync.aligned.m16n8k16.row.col.f32.bf16.bf16.f32 "
        "{%0,%1,%2,%3}, {%4,%5,%6,%7}, {%8,%9}, {%0,%1,%2,%3};"
        : "+f"(c[0]), "+f"(c[1]), "+f"(c[2]), "+f"(c[3])
        : "r"(a[0]), "r"(a[1]), "r"(a[2]), "r"(a[3]), "r"(b[0]), "r"(b[1]));
}
__device__ __forceinline__ void mma_f16(float* c, const uint32_t* a, const uint32_t* b) {
    asm volatile(
        "mma.sync.aligned.m16n8k16.row.col.f32.f16.f16.f32 "
        "{%0,%1,%2,%3}, {%4,%5,%6,%7}, {%8,%9}, {%0,%1,%2,%3};"
        : "+f"(c[0]), "+f"(c[1]), "+f"(c[2]), "+f"(c[3])
        : "r"(a[0]), "r"(a[1]), "r"(a[2]), "r"(a[3]), "r"(b[0]), "r"(b[1]));
}
__device__ __forceinline__ void ldm_x4(uint32_t* r, uint32_t addr) {
    asm volatile("ldmatrix.sync.aligned.m8n8.x4.shared.b16 {%0,%1,%2,%3}, [%4];"
                 : "=r"(r[0]), "=r"(r[1]), "=r"(r[2]), "=r"(r[3]) : "r"(addr));
}
__device__ __forceinline__ void cp16(uint32_t saddr, const void* g) {
    asm volatile("cp.async.cg.shared.global [%0], [%1], 16;" :: "r"(saddr), "l"(g));
}
#define CP_COMMIT() asm volatile("cp.async.commit_group;" ::: "memory")
#define CP_WAIT0()  asm volatile("cp.async.wait_group 0;" ::: "memory")
#define CP_WAIT1()  asm volatile("cp.async.wait_group 1;" ::: "memory")

// ---------------- staging: 128 rows x 128B (K=64 of 2-byte elems) ------------
// XOR swizzle (seg ^ (row&7)); conflict-free cp.async stores + ldmatrix reads
template <typename T>
__device__ __forceinline__ void stage64(uint32_t sbase, const T* src, size_t rs,
                                        int kt, int tid) {
    #pragma unroll
    for (int p = 0; p < 4; p++) {
        int idx = p * 256 + tid;
        int row = idx >> 3, c8 = idx & 7;
        uint32_t sa = sbase + row * 128 + ((c8 ^ (row & 7)) << 4);
        cp16(sa, src + (size_t)row * rs + kt + c8 * 8);
    }
}

// ---------------- single-term K=64 chunk (A,B both 128B rows) ----------------
template <bool HALF>
__device__ __forceinline__ void mma_chunk64(float acc[16][4], uint32_t Abase, uint32_t Bbase,
                                            int m_base, int n_base, int lane) {
    const int L7 = lane & 7;
    const int rowA = L7 + (lane & 8);
    const int rowB = L7 + ((lane >> 1) & 8);
    #pragma unroll
    for (int ks = 0; ks < 4; ks++) {
        const int cA = 2 * ks + (lane >> 4);
        const int cB = 2 * ks + ((lane >> 3) & 1);
        const uint32_t swA = (uint32_t)((cA ^ L7) << 4);
        const uint32_t swB = (uint32_t)((cB ^ L7) << 4);

        uint32_t bh[2][4];
        #pragma unroll
        for (int nip = 0; nip < 2; nip++) {
            uint32_t rb = Bbase + (uint32_t)(n_base + nip * 16 + rowB) * 128 + swB;
            ldm_x4(bh[nip], rb);
        }
        #pragma unroll
        for (int mi = 0; mi < 4; mi++) {
            uint32_t ra = Abase + (uint32_t)(m_base + mi * 16 + rowA) * 128 + swA;
            uint32_t a[4];
            ldm_x4(a, ra);
            #pragma unroll
            for (int nip = 0; nip < 2; nip++) {
                #pragma unroll
                for (int h = 0; h < 2; h++) {
                    float* c = acc[mi * 4 + nip * 2 + h];
                    uint32_t bf[2] = {bh[nip][2 * h], bh[nip][2 * h + 1]};
                    if (HALF) mma_f16(c, a, bf);
                    else      mma_bf16(c, a, bf);
                }
            }
        }
    }
}

// 3-stage K=64 pipeline (32KB/stage: A 16KB + B 16KB)
template <int NCH, bool HALF, typename T>
__device__ __forceinline__ void gemm_pipe64(float acc[16][4], uint32_t base,
    const T* A, size_t ars, const T* Bp, size_t brs,
    int m_base, int n_base, int tid, int lane)
{
    stage64(base, A, ars, 0, tid);
    stage64(base + 16384, Bp, brs, 0, tid);
    CP_COMMIT();
    if (NCH > 1) {
        stage64(base + 32768, A, ars, 64, tid);
        stage64(base + 32768 + 16384, Bp, brs, 64, tid);
        CP_COMMIT();
    }
    for (int ch = 0; ch < NCH; ch++) {
        if (ch == NCH - 1) { CP_WAIT0(); } else { CP_WAIT1(); }
        __syncthreads();
        if (ch + 2 < NCH) {
            uint32_t o = (uint32_t)(((ch + 2) % 3) * 32768);
            stage64(base + o, A, ars, (ch + 2) * 64, tid);
            stage64(base + o + 16384, Bp, brs, (ch + 2) * 64, tid);
            CP_COMMIT();
        }
        uint32_t o = (uint32_t)((ch % 3) * 32768);
        mma_chunk64<HALF>(acc, base + o, base + o + 16384, m_base, n_base, lane);
    }
}

// ---------------- kernel 1a: x transpose -> fp16 xT --------------------------
__global__ __launch_bounds__(256) void xsplit(const float* __restrict__ x)
{
    __shared__ float t[32][69];
    const int b  = blockIdx.z;
    const int n0 = blockIdx.x * 64;
    const int c0 = blockIdx.y * 32;
    const float* src = x + (size_t)b * C_ * N_;
    const int tid = threadIdx.x;

    #pragma unroll
    for (int p = 0; p < 2; p++) {
        int idx = p * 256 + tid;
        int row = idx >> 4, col4 = (idx & 15) * 4;
        float4 v = *reinterpret_cast<const float4*>(&src[(size_t)(c0 + row) * N_ + n0 + col4]);
        t[row][col4] = v.x; t[row][col4 + 1] = v.y;
        t[row][col4 + 2] = v.z; t[row][col4 + 3] = v.w;
    }
    __syncthreads();

    const int nn = tid >> 2, cseg = (tid & 3) * 8;
    __align__(16) __half h[8];
    #pragma unroll
    for (int k = 0; k < 8; k++)
        h[k] = __float2half(t[cseg + k][nn]);
    size_t o = ((size_t)b * N_ + n0 + nn) * C_ + c0 + cseg;
    *reinterpret_cast<uint4*>(&g_xT[o]) = *reinterpret_cast<uint4*>(h);
}

// ---------------- kernel 1b: weight -> fp16 ----------------------------------
__global__ __launch_bounds__(256) void wsplit(const float* __restrict__ wq,
                                              const float* __restrict__ wk,
                                              const float* __restrict__ wv)
{
    int i = blockIdx.x * 256 + threadIdx.x;
    if (i < 32768)       g_wq[i]         = __float2half(wq[i]);
    else if (i < 65536)  g_wk[i - 32768] = __float2half(wk[i - 32768]);
    else                 g_wv[i - 65536] = __float2half(wv[i - 65536]);
}

// ---------------- kernel 2a: Q/K projection (single fp16 GEMM) ---------------
__global__ __launch_bounds__(256, 2) void proj_qk_mma(
    const float* __restrict__ bq, const float* __restrict__ bk)
{
    extern __shared__ char dyn[];
    const uint32_t base = smem_u32(dyn);

    const int tid = threadIdx.x;
    const int lane = tid & 31, wid = tid >> 5;
    const int m_base = (wid & 1) * 64, n_base = (wid >> 1) * 32;
    const int g = lane >> 2, q2 = (lane & 3) * 2;

    const int i0 = blockIdx.x * 128;
    const int zy = blockIdx.y;
    const int b = zy & 3;
    const bool isK = zy >= 4;
    const __half* W = isK ? g_wk : g_wq;
    const float* bias = isK ? bk : bq;
    __half* dst = (isK ? g_k : g_q) + ((size_t)b * N_ + i0) * CQK_;

    float acc[16][4] = {};
    gemm_pipe64<4, true>(acc, base,
                         g_xT + ((size_t)b * N_ + i0) * C_, (size_t)C_,
                         W, (size_t)C_, m_base, n_base, tid, lane);

    #pragma unroll
    for (int mi = 0; mi < 4; mi++) {
        #pragma unroll
        for (int ni = 0; ni < 4; ni++) {
            const float* c = acc[mi * 4 + ni];
            const int r = m_base + mi * 16 + g;
            const int col = n_base + ni * 8 + q2;
            float2 bb = *reinterpret_cast<const float2*>(&bias[col]);
            __half2 p0 = __floats2half2_rn(c[0] + bb.x, c[1] + bb.y);
            __half2 p1 = __floats2half2_rn(c[2] + bb.x, c[3] + bb.y);
            *reinterpret_cast<__half2*>(&dst[(size_t)r * CQK_ + col])       = p0;
            *reinterpret_cast<__half2*>(&dst[(size_t)(r + 8) * CQK_ + col]) = p1;
        }
    }
}

// ---------------- kernel 3: scores (fp16 GEMM) -> exp(S^T) bf16 + sumexp -----
__global__ __launch_bounds__(256, 2) void scores_mma()
{
    extern __shared__ char dyn[];
    const uint32_t base = smem_u32(dyn);

    const int tid = threadIdx.x;
    const int lane = tid & 31, wid = tid >> 5;
    const int m_base = (wid & 1) * 64, n_base = (wid >> 1) * 32;
    const int g = lane >> 2, q2 = (lane & 3) * 2;
    const int wn = wid >> 1;

    const int j0 = blockIdx.x * 128, i0 = blockIdx.y * 128, b = blockIdx.z;

    float acc[16][4] = {};
    gemm_pipe64<2, true>(acc, base,
                         g_q + ((size_t)b * N_ + i0) * CQK_, (size_t)CQK_,
                         g_k + ((size_t)b * N_ + j0) * CQK_, (size_t)CQK_,
                         m_base, n_base, tid, lane);

    // exp in place (S bounded; no max subtraction needed)
    #pragma unroll
    for (int u = 0; u < 16; u++)
        #pragma unroll
        for (int v = 0; v < 4; v++)
            acc[u][v] = __expf(acc[u][v]);

    // ---- per-row sumexp partials ----
    __syncthreads();
    float* red2 = reinterpret_cast<float*>(dyn);   // [128][4]
    #pragma unroll
    for (int mi = 0; mi < 4; mi++) {
        #pragma unroll
        for (int h = 0; h < 2; h++) {
            const int row = m_base + mi * 16 + h * 8 + g;
            float s = 0.f;
            #pragma unroll
            for (int ni = 0; ni < 4; ni++)
                s += acc[mi * 4 + ni][2 * h] + acc[mi * 4 + ni][2 * h + 1];
            s += __shfl_xor_sync(0xffffffffu, s, 1);
            s += __shfl_xor_sync(0xffffffffu, s, 2);
            if ((lane & 3) == 0)
                red2[row * 4 + wn] = s;
        }
    }
    __syncthreads();
    if (tid < 128) {
        float S = red2[tid * 4] + red2[tid * 4 + 1] + red2[tid * 4 + 2] + red2[tid * 4 + 3];
        g_ps[((size_t)b * 32 + blockIdx.x) * N_ + i0 + tid] = S;
    }
    __syncthreads();

    // ---- transpose (bf16) -> ts[j][i] pad 136, coalesced uint2 writes -------
    __nv_bfloat16* ts = reinterpret_cast<__nv_bfloat16*>(dyn);  // [128][136]
    #pragma unroll
    for (int mi = 0; mi < 4; mi++) {
        #pragma unroll
        for (int ni = 0; ni < 4; ni++) {
            const float* c = acc[mi * 4 + ni];
            const int r = m_base + mi * 16 + g;
            const int col = n_base + ni * 8 + q2;
            ts[col * 136 + r]           = __float2bfloat16(c[0]);
            ts[(col + 1) * 136 + r]     = __float2bfloat16(c[1]);
            ts[col * 136 + r + 8]       = __float2bfloat16(c[2]);
            ts[(col + 1) * 136 + r + 8] = __float2bfloat16(c[3]);
        }
    }
    __syncthreads();
    {
        const int jl = tid >> 5;
        __nv_bfloat16* dstb = g_PT + ((size_t)b * N_ + j0) * N_ + i0;
        #pragma unroll
        for (int it = 0; it < 16; it++) {
            const int j = jl + it * 8;
            uint2 v = *reinterpret_cast<const uint2*>(&ts[j * 136 + lane * 4]);
            *reinterpret_cast<uint2*>(&dstb[(size_t)j * N_ + lane * 4]) = v;
        }
    }
}

// ---------------- kernel 4: combine partials -> inverse row sums -------------
__global__ __launch_bounds__(256) void inv_combine()
{
    const int idx = blockIdx.x * 256 + threadIdx.x;   // b*N + i
    const int b = idx >> 12, i = idx & 4095;
    const float* ps = g_ps + (size_t)b * 32 * N_ + i;
    float S = 0.f;
    #pragma unroll
    for (int t = 0; t < 32; t++)
        S += ps[(size_t)t * N_];
    g_Linv[idx] = 1.0f / S;
}

// ---------------- kernel 5: V projection (fp16 GEMM), Linv folded ------------
__global__ __launch_bounds__(256, 2) void proj_v_mma(const float* __restrict__ bv)
{
    extern __shared__ char dyn[];
    const uint32_t base = smem_u32(dyn);

    const int tid = threadIdx.x;
    const int lane = tid & 31, wid = tid >> 5;
    const int m_base = (wid & 1) * 64, n_base = (wid >> 1) * 32;
    const int g = lane >> 2, q2 = (lane & 3) * 2;

    const int j0 = blockIdx.x * 128;
    const int c0 = blockIdx.y * 128;
    const int b  = blockIdx.z;

    float acc[16][4] = {};
    gemm_pipe64<4, true>(acc, base,
                         g_wv + (size_t)c0 * C_, (size_t)C_,
                         g_xT + ((size_t)b * N_ + j0) * C_, (size_t)C_,
                         m_base, n_base, tid, lane);

    const float* invb = g_Linv + b * N_ + j0;
    #pragma unroll
    for (int mi = 0; mi < 4; mi++) {
        const int cc = c0 + m_base + mi * 16 + g;
        const float bv0 = bv[cc], bv1 = bv[cc + 8];
        #pragma unroll
        for (int ni = 0; ni < 4; ni++) {
            const float* c = acc[mi * 4 + ni];
            const int col = n_base + ni * 8 + q2;
            float2 iv = *reinterpret_cast<const float2*>(&invb[col]);
            __nv_bfloat162 p0 = __floats2bfloat162_rn((c[0] + bv0) * iv.x, (c[1] + bv0) * iv.y);
            __nv_bfloat162 p1 = __floats2bfloat162_rn((c[2] + bv1) * iv.x, (c[3] + bv1) * iv.y);
            size_t o0 = ((size_t)b * C_ + cc) * N_ + j0 + col;
            size_t o1 = ((size_t)b * C_ + cc + 8) * N_ + j0 + col;
            *reinterpret_cast<__nv_bfloat162*>(&g_v[o0]) = p0;
            *reinterpret_cast<__nv_bfloat162*>(&g_v[o1]) = p1;
        }
    }
}

// ---------------- kernel 6: AV (single bf16 GEMM) + epilogue -----------------
// grid (2 c-blocks fastest, 32 j, 4 b): paired c-blocks launch adjacently so
// the shared PT j-tile hits L2 on the second read.
__global__ __launch_bounds__(256, 2) void av_mma(
    const float* __restrict__ x, const float* __restrict__ gamma,
    float* __restrict__ out)
{
    extern __shared__ char dyn[];
    const uint32_t base = smem_u32(dyn);

    const int tid = threadIdx.x;
    const int lane = tid & 31, wid = tid >> 5;
    const int m_base = (wid & 1) * 64, n_base = (wid >> 1) * 32;
    const int g = lane >> 2, q2 = (lane & 3) * 2;

    const int c0 = blockIdx.x * 128, j0 = blockIdx.y * 128, b = blockIdx.z;

    float acc[16][4] = {};
    gemm_pipe64<64, false>(acc, base,
                           g_v + ((size_t)b * C_ + c0) * N_, (size_t)N_,
                           g_PT + ((size_t)b * N_ + j0) * N_, (size_t)N_,
                           m_base, n_base, tid, lane);

    const float gm = gamma[0];
    #pragma unroll
    for (int mi = 0; mi < 4; mi++) {
        #pragma unroll
        for (int ni = 0; ni < 4; ni++) {
            const float* c = acc[mi * 4 + ni];
            const int cc = c0 + m_base + mi * 16 + g;
            const int col = j0 + n_base + ni * 8 + q2;
            size_t o0 = ((size_t)b * C_ + cc) * N_ + col;
            size_t o1 = ((size_t)b * C_ + cc + 8) * N_ + col;
            float2 x0 = *reinterpret_cast<const float2*>(&x[o0]);
            float2 x1 = *reinterpret_cast<const float2*>(&x[o1]);
            *reinterpret_cast<float2*>(&out[o0]) =
                make_float2(gm * c[0] + x0.x, gm * c[1] + x0.y);
            *reinterpret_cast<float2*>(&out[o1]) =
                make_float2(gm * c[2] + x1.x, gm * c[3] + x1.y);
        }
    }
}

// ---------------- launch -----------------------------------------------------
extern "C" void kernel_launch(void* const* d_in, const int* in_sizes, int n_in,
                              void* d_out, int out_size)
{
    const float* x     = (const float*)d_in[0];
    const float* wq    = (const float*)d_in[1];
    const float* bq    = (const float*)d_in[2];
    const float* wk    = (const float*)d_in[3];
    const float* bk    = (const float*)d_in[4];
    const float* wv    = (const float*)d_in[5];
    const float* bv    = (const float*)d_in[6];
    const float* gamma = (const float*)d_in[7];
    float* out = (float*)d_out;

    const int DYN = 98304;   // 3 stages x 32KB
    cudaFuncSetAttribute(proj_qk_mma, cudaFuncAttributeMaxDynamicSharedMemorySize, DYN);
    cudaFuncSetAttribute(proj_v_mma,  cudaFuncAttributeMaxDynamicSharedMemorySize, DYN);
    cudaFuncSetAttribute(scores_mma,  cudaFuncAttributeMaxDynamicSharedMemorySize, DYN);
    cudaFuncSetAttribute(av_mma,      cudaFuncAttributeMaxDynamicSharedMemorySize, DYN);

    xsplit        <<<dim3(N_ / 64, C_ / 32, B_), 256>>>(x);
    wsplit        <<<dim3(512), 256>>>(wq, wk, wv);
    proj_qk_mma   <<<dim3(N_ / 128, B_ * 2), 256, DYN>>>(bq, bk);
    scores_mma    <<<dim3(N_ / 128, N_ / 128, B_), 256, DYN>>>();
    inv_combine   <<<dim3(B_ * N_ / 256), 256>>>();
    proj_v_mma    <<<dim3(N_ / 128, C_ / 128, B_), 256, DYN>>>(bv);
    av_mma        <<<dim3(C_ / 128, N_ / 128, B_), 256, DYN>>>(x, gamma, out);
}